// round 1
// baseline (speedup 1.0000x reference)
#include <cuda_runtime.h>
#include <math.h>

#define NTOK 4096      // B*T
#define DM   1024
#define NH   16
#define HD   64
#define NE   8
#define DFF  4096
#define NSLOT 8192     // NTOK * TOP_K
#define TT   1024
#define NBH  64        // B * NH

// ---------------- scratch (static device memory; no allocs allowed) -----------
__device__ float g_xn1 [NTOK * DM];
__device__ float g_qkv [NTOK * 3 * DM];
__device__ float g_q   [NTOK * DM];   // [B,H,T,HD]
__device__ float g_k   [NTOK * DM];
__device__ float g_v   [NTOK * DM];
__device__ float g_attn[NTOK * DM];   // [B,T,D]
__device__ float g_x2  [NTOK * DM];
__device__ float g_xn2 [NTOK * DM];
__device__ float g_h   [(size_t)NSLOT * DFF];
__device__ float g_y   [NSLOT * DM];

__device__ int   g_cnt[NE];
__device__ int   g_off[NE];
__device__ int   g_cur[NE];
__device__ float g_probsum[NE];
__device__ int   g_top_i[NSLOT];
__device__ float g_top_w[NSLOT];
__device__ int   g_perm_tok[NSLOT];
__device__ float g_slot_gate[NSLOT];
__device__ int   g_slot_of[NSLOT];
__device__ float g_aux;

// ---------------- small helpers ----------------
__global__ void zero_small_kernel() {
    int i = threadIdx.x;
    if (i < NE) { g_cnt[i] = 0; g_cur[i] = 0; g_probsum[i] = 0.f; }
}

// ---------------- layernorm: one block (256 thr) per row ----------------
__global__ void __launch_bounds__(256) ln_kernel(
    const float* __restrict__ x, const float* __restrict__ g,
    const float* __restrict__ b, float* __restrict__ o)
{
    int row = blockIdx.x;
    const float* xr = x + (size_t)row * DM;
    float v[4]; float s = 0.f, ss = 0.f;
    #pragma unroll
    for (int i = 0; i < 4; i++) {
        float u = xr[threadIdx.x + i * 256];
        v[i] = u; s += u; ss += u * u;
    }
    #pragma unroll
    for (int ofs = 16; ofs > 0; ofs >>= 1) {
        s  += __shfl_xor_sync(0xffffffffu, s,  ofs);
        ss += __shfl_xor_sync(0xffffffffu, ss, ofs);
    }
    __shared__ float sh[2][8];
    int warp = threadIdx.x >> 5, lane = threadIdx.x & 31;
    if (lane == 0) { sh[0][warp] = s; sh[1][warp] = ss; }
    __syncthreads();
    float S = 0.f, SS = 0.f;
    #pragma unroll
    for (int w = 0; w < 8; w++) { S += sh[0][w]; SS += sh[1][w]; }
    float mu  = S * (1.0f / DM);
    float var = SS * (1.0f / DM) - mu * mu;
    float inv = rsqrtf(var + 1e-5f);
    float* orow = o + (size_t)row * DM;
    #pragma unroll
    for (int i = 0; i < 4; i++) {
        int idx = threadIdx.x + i * 256;
        orow[idx] = (v[i] - mu) * inv * g[idx] + b[idx];
    }
}

// ---------------- generic 128x128x16 SGEMM (bias/residual epilogue) ----------
__global__ void __launch_bounds__(256) sgemm128(
    const float* __restrict__ A, const float* __restrict__ B,
    const float* __restrict__ bias, const float* __restrict__ resid,
    float* __restrict__ C, int M, int N, int K)
{
    __shared__ __align__(16) float As[16][128];
    __shared__ __align__(16) float Bs[16][128];
    int tid = threadIdx.x;
    int tx = tid & 15, ty = tid >> 4;
    int n0 = blockIdx.x * 128, m0 = blockIdx.y * 128;
    float acc[8][8];
    #pragma unroll
    for (int i = 0; i < 8; i++)
        #pragma unroll
        for (int j = 0; j < 8; j++) acc[i][j] = 0.f;

    for (int k0 = 0; k0 < K; k0 += 16) {
        #pragma unroll
        for (int l = 0; l < 2; l++) {
            int idx  = tid + l * 256;
            int arow = idx >> 2, kc = (idx & 3) * 4;
            float4 va = *(const float4*)(A + (size_t)(m0 + arow) * K + k0 + kc);
            As[kc + 0][arow] = va.x; As[kc + 1][arow] = va.y;
            As[kc + 2][arow] = va.z; As[kc + 3][arow] = va.w;
            int brow = idx >> 5, bcol = (idx & 31) * 4;
            *(float4*)(&Bs[brow][bcol]) =
                *(const float4*)(B + (size_t)(k0 + brow) * N + n0 + bcol);
        }
        __syncthreads();
        #pragma unroll
        for (int kk = 0; kk < 16; kk++) {
            float4 a0 = *(const float4*)(&As[kk][ty * 4]);
            float4 a1 = *(const float4*)(&As[kk][64 + ty * 4]);
            float4 b0 = *(const float4*)(&Bs[kk][tx * 4]);
            float4 b1 = *(const float4*)(&Bs[kk][64 + tx * 4]);
            float a[8] = {a0.x,a0.y,a0.z,a0.w,a1.x,a1.y,a1.z,a1.w};
            float bb[8]= {b0.x,b0.y,b0.z,b0.w,b1.x,b1.y,b1.z,b1.w};
            #pragma unroll
            for (int i = 0; i < 8; i++)
                #pragma unroll
                for (int j = 0; j < 8; j++)
                    acc[i][j] = fmaf(a[i], bb[j], acc[i][j]);
        }
        __syncthreads();
    }
    #pragma unroll
    for (int i = 0; i < 8; i++) {
        int m = m0 + ((i < 4) ? ty * 4 + i : 64 + ty * 4 + i - 4);
        #pragma unroll
        for (int j = 0; j < 8; j++) {
            int n = n0 + ((j < 4) ? tx * 4 + j : 64 + tx * 4 + j - 4);
            float vv = acc[i][j];
            if (bias)  vv += bias[n];
            if (resid) vv += resid[(size_t)m * N + n];
            C[(size_t)m * N + n] = vv;
        }
    }
}

// ---------------- RoPE + layout transform [B,T,3D] -> q,k,v [B,H,T,HD] -------
__global__ void __launch_bounds__(256) rope_kernel(
    const float* __restrict__ qkv, float* __restrict__ q,
    float* __restrict__ k, float* __restrict__ v)
{
    int tok = blockIdx.x;
    int b = tok >> 10, t = tok & 1023;
    const float* row = qkv + (size_t)tok * (3 * DM);
    for (int i = threadIdx.x; i < DM; i += 256) {
        int h = i >> 6, d = i & 63;
        int f = d & 31;
        float freq = powf(10000.0f, -(float)f / 32.0f);
        float ang = (float)t * freq;
        float sv, cv;
        sincosf(ang, &sv, &cv);
        float qa = row[i], ka = row[DM + i];
        float qo, ko;
        if (d < 32) {
            qo = qa * cv - row[i + 32] * sv;
            ko = ka * cv - row[DM + i + 32] * sv;
        } else {
            qo = qa * cv + row[i - 32] * sv;
            ko = ka * cv + row[DM + i - 32] * sv;
        }
        int dst = ((b * NH + h) * TT + t) * HD + d;
        q[dst] = qo;
        k[dst] = ko;
        v[dst] = row[2 * DM + i];
    }
}

// ---------------- causal attention: one warp per query row -------------------
__global__ void __launch_bounds__(256) attn_kernel(
    const float* __restrict__ q, const float* __restrict__ k,
    const float* __restrict__ v, float* __restrict__ o)
{
    int warp = threadIdx.x >> 5, lane = threadIdx.x & 31;
    int gr = blockIdx.x * 8 + warp;          // [0, 65536)
    int bh = gr >> 10;
    int t  = gr & 1023;
    const float* qp = q + (size_t)gr * HD;
    float q0 = qp[lane], q1 = qp[lane + 32];
    const float* kb = k + (size_t)bh * TT * HD;
    const float* vb = v + (size_t)bh * TT * HD;
    float m = -1e30f, l = 0.f, a0 = 0.f, a1 = 0.f;
    for (int j = 0; j <= t; j++) {
        const float* kj = kb + j * HD;
        float s = q0 * kj[lane] + q1 * kj[lane + 32];
        #pragma unroll
        for (int ofs = 16; ofs > 0; ofs >>= 1)
            s += __shfl_xor_sync(0xffffffffu, s, ofs);
        s *= 0.125f;   // HD^-0.5
        const float* vj = vb + j * HD;
        float v0 = vj[lane], v1 = vj[lane + 32];
        if (s <= m) {
            float p = __expf(s - m);
            l += p; a0 += p * v0; a1 += p * v1;
        } else {
            float c = __expf(m - s);
            l = l * c + 1.f; a0 = a0 * c + v0; a1 = a1 * c + v1;
            m = s;
        }
    }
    int b = bh >> 4, h = bh & 15;
    float* op = o + ((size_t)(b * TT + t)) * DM + h * HD;
    float inv = 1.0f / l;
    op[lane]      = a0 * inv;
    op[lane + 32] = a1 * inv;
}

// ---------------- router: block (128 thr) per token --------------------------
__global__ void __launch_bounds__(128) router_kernel(
    const float* __restrict__ xn2, const float* __restrict__ wr)
{
    int tok = blockIdx.x, tid = threadIdx.x;
    const float* xr = xn2 + (size_t)tok * DM;
    float p[NE];
    #pragma unroll
    for (int e = 0; e < NE; e++) p[e] = 0.f;
    for (int i = tid; i < DM; i += 128) {
        float xv = xr[i];
        const float* w = wr + i * NE;
        #pragma unroll
        for (int e = 0; e < NE; e++) p[e] += xv * w[e];
    }
    __shared__ float red[NE][128];
    #pragma unroll
    for (int e = 0; e < NE; e++) red[e][tid] = p[e];
    __syncthreads();
    for (int st = 64; st > 0; st >>= 1) {
        if (tid < st) {
            #pragma unroll
            for (int e = 0; e < NE; e++) red[e][tid] += red[e][tid + st];
        }
        __syncthreads();
    }
    if (tid == 0) {
        float lg[NE], mx = -1e30f;
        #pragma unroll
        for (int e = 0; e < NE; e++) { lg[e] = red[e][0]; mx = fmaxf(mx, lg[e]); }
        float se = 0.f, pr[NE];
        #pragma unroll
        for (int e = 0; e < NE; e++) { pr[e] = __expf(lg[e] - mx); se += pr[e]; }
        float inv = 1.0f / se;
        #pragma unroll
        for (int e = 0; e < NE; e++) {
            pr[e] *= inv;
            atomicAdd(&g_probsum[e], pr[e]);
        }
        int i0 = 0;
        #pragma unroll
        for (int e = 1; e < NE; e++) if (pr[e] > pr[i0]) i0 = e;
        int i1 = (i0 == 0) ? 1 : 0;
        #pragma unroll
        for (int e = 0; e < NE; e++) if (e != i0 && pr[e] > pr[i1]) i1 = e;
        float w0 = pr[i0], w1 = pr[i1], sw = 1.0f / (w0 + w1);
        g_top_i[tok * 2] = i0; g_top_i[tok * 2 + 1] = i1;
        g_top_w[tok * 2] = w0 * sw; g_top_w[tok * 2 + 1] = w1 * sw;
        atomicAdd(&g_cnt[i0], 1);
        atomicAdd(&g_cnt[i1], 1);
    }
}

__global__ void scan_kernel() {
    if (threadIdx.x == 0 && blockIdx.x == 0) {
        int o = 0;
        float aux = 0.f;
        for (int e = 0; e < NE; e++) { g_off[e] = o; o += g_cnt[e]; }
        for (int e = 0; e < NE; e++)
            aux += ((float)g_cnt[e] / (float)(NTOK * 2)) * (g_probsum[e] / (float)NTOK);
        g_aux = (float)NE * aux;
    }
}

__global__ void place_kernel() {
    int s = blockIdx.x * 256 + threadIdx.x;
    if (s >= NSLOT) return;
    int tok = s >> 1;
    int e = g_top_i[s];
    float w = g_top_w[s];
    int pos = atomicAdd(&g_cur[e], 1);
    int slot = g_off[e] + pos;
    g_perm_tok[slot] = tok;
    g_slot_gate[slot] = w;
    g_slot_of[s] = slot;
}

// ---------------- grouped FFN1: h = gelu(gather(xn2) @ w1[e] + b1[e]) --------
__global__ void __launch_bounds__(256) moe_ffn1(
    const float* __restrict__ X, const float* __restrict__ W1,
    const float* __restrict__ B1)
{
    int e = blockIdx.z;
    int cnt = g_cnt[e];
    int r0 = blockIdx.y * 128;
    if (r0 >= cnt) return;
    int off = g_off[e];
    const float* B = W1 + (size_t)e * DM * DFF;
    const float* bias = B1 + e * DFF;
    int n0 = blockIdx.x * 128;

    __shared__ __align__(16) float As[16][128];
    __shared__ __align__(16) float Bs[16][128];
    int tid = threadIdx.x;
    int tx = tid & 15, ty = tid >> 4;
    float acc[8][8];
    #pragma unroll
    for (int i = 0; i < 8; i++)
        #pragma unroll
        for (int j = 0; j < 8; j++) acc[i][j] = 0.f;

    for (int k0 = 0; k0 < DM; k0 += 16) {
        #pragma unroll
        for (int l = 0; l < 2; l++) {
            int idx = tid + l * 256;
            int arow = idx >> 2, kc = (idx & 3) * 4;
            int rr = r0 + arow;
            float4 va = make_float4(0.f, 0.f, 0.f, 0.f);
            if (rr < cnt) {
                int tok = g_perm_tok[off + rr];
                va = *(const float4*)(X + (size_t)tok * DM + k0 + kc);
            }
            As[kc + 0][arow] = va.x; As[kc + 1][arow] = va.y;
            As[kc + 2][arow] = va.z; As[kc + 3][arow] = va.w;
            int brow = idx >> 5, bcol = (idx & 31) * 4;
            *(float4*)(&Bs[brow][bcol]) =
                *(const float4*)(B + (size_t)(k0 + brow) * DFF + n0 + bcol);
        }
        __syncthreads();
        #pragma unroll
        for (int kk = 0; kk < 16; kk++) {
            float4 a0 = *(const float4*)(&As[kk][ty * 4]);
            float4 a1 = *(const float4*)(&As[kk][64 + ty * 4]);
            float4 b0 = *(const float4*)(&Bs[kk][tx * 4]);
            float4 b1 = *(const float4*)(&Bs[kk][64 + tx * 4]);
            float a[8] = {a0.x,a0.y,a0.z,a0.w,a1.x,a1.y,a1.z,a1.w};
            float bb[8]= {b0.x,b0.y,b0.z,b0.w,b1.x,b1.y,b1.z,b1.w};
            #pragma unroll
            for (int i = 0; i < 8; i++)
                #pragma unroll
                for (int j = 0; j < 8; j++)
                    acc[i][j] = fmaf(a[i], bb[j], acc[i][j]);
        }
        __syncthreads();
    }
    #pragma unroll
    for (int i = 0; i < 8; i++) {
        int rl = (i < 4) ? ty * 4 + i : 64 + ty * 4 + i - 4;
        if (r0 + rl >= cnt) continue;
        size_t crow = (size_t)(off + r0 + rl) * DFF;
        #pragma unroll
        for (int j = 0; j < 8; j++) {
            int n = n0 + ((j < 4) ? tx * 4 + j : 64 + tx * 4 + j - 4);
            float vv = acc[i][j] + bias[n];
            vv = 0.5f * vv * (1.0f + erff(vv * 0.70710678118654752f));  // exact gelu
            g_h[crow + n] = vv;
        }
    }
}

// ---------------- grouped FFN2: y = h @ w2[e] + b2[e] ------------------------
__global__ void __launch_bounds__(256) moe_ffn2(
    const float* __restrict__ W2, const float* __restrict__ B2)
{
    int e = blockIdx.z;
    int cnt = g_cnt[e];
    int r0 = blockIdx.y * 128;
    if (r0 >= cnt) return;
    int off = g_off[e];
    const float* B = W2 + (size_t)e * DFF * DM;
    const float* bias = B2 + e * DM;
    int n0 = blockIdx.x * 128;

    __shared__ __align__(16) float As[16][128];
    __shared__ __align__(16) float Bs[16][128];
    int tid = threadIdx.x;
    int tx = tid & 15, ty = tid >> 4;
    float acc[8][8];
    #pragma unroll
    for (int i = 0; i < 8; i++)
        #pragma unroll
        for (int j = 0; j < 8; j++) acc[i][j] = 0.f;

    for (int k0 = 0; k0 < DFF; k0 += 16) {
        #pragma unroll
        for (int l = 0; l < 2; l++) {
            int idx = tid + l * 256;
            int arow = idx >> 2, kc = (idx & 3) * 4;
            int rr = r0 + arow;
            float4 va = make_float4(0.f, 0.f, 0.f, 0.f);
            if (rr < cnt)
                va = *(const float4*)(g_h + (size_t)(off + rr) * DFF + k0 + kc);
            As[kc + 0][arow] = va.x; As[kc + 1][arow] = va.y;
            As[kc + 2][arow] = va.z; As[kc + 3][arow] = va.w;
            int brow = idx >> 5, bcol = (idx & 31) * 4;
            *(float4*)(&Bs[brow][bcol]) =
                *(const float4*)(B + (size_t)(k0 + brow) * DM + n0 + bcol);
        }
        __syncthreads();
        #pragma unroll
        for (int kk = 0; kk < 16; kk++) {
            float4 a0 = *(const float4*)(&As[kk][ty * 4]);
            float4 a1 = *(const float4*)(&As[kk][64 + ty * 4]);
            float4 b0 = *(const float4*)(&Bs[kk][tx * 4]);
            float4 b1 = *(const float4*)(&Bs[kk][64 + tx * 4]);
            float a[8] = {a0.x,a0.y,a0.z,a0.w,a1.x,a1.y,a1.z,a1.w};
            float bb[8]= {b0.x,b0.y,b0.z,b0.w,b1.x,b1.y,b1.z,b1.w};
            #pragma unroll
            for (int i = 0; i < 8; i++)
                #pragma unroll
                for (int j = 0; j < 8; j++)
                    acc[i][j] = fmaf(a[i], bb[j], acc[i][j]);
        }
        __syncthreads();
    }
    #pragma unroll
    for (int i = 0; i < 8; i++) {
        int rl = (i < 4) ? ty * 4 + i : 64 + ty * 4 + i - 4;
        if (r0 + rl >= cnt) continue;
        size_t crow = (size_t)(off + r0 + rl) * DM;
        #pragma unroll
        for (int j = 0; j < 8; j++) {
            int n = n0 + ((j < 4) ? tx * 4 + j : 64 + tx * 4 + j - 4);
            g_y[crow + n] = acc[i][j] + bias[n];
        }
    }
}

// ---------------- final combine: out = x2 + g0*y[s0] + g1*y[s1]; aux ---------
__global__ void __launch_bounds__(256) combine_kernel(float* __restrict__ out, int out_size)
{
    int tok = blockIdx.x;
    int s0 = g_slot_of[tok * 2], s1 = g_slot_of[tok * 2 + 1];
    float w0 = g_slot_gate[s0], w1 = g_slot_gate[s1];
    const float* y0 = g_y + (size_t)s0 * DM;
    const float* y1 = g_y + (size_t)s1 * DM;
    const float* xr = g_x2 + (size_t)tok * DM;
    float* orow = out + (size_t)tok * DM;
    #pragma unroll
    for (int l = 0; l < 4; l++) {
        int i = threadIdx.x + l * 256;
        orow[i] = xr[i] + w0 * y0[i] + w1 * y1[i];
    }
    if (tok == 0 && threadIdx.x == 0 && out_size > NTOK * DM)
        out[NTOK * DM] = g_aux;
}

// ---------------- launch ----------------
extern "C" void kernel_launch(void* const* d_in, const int* in_sizes, int n_in,
                              void* d_out, int out_size)
{
    const float* x       = (const float*)d_in[0];
    // d_in[1] = mask (causal; handled structurally)
    const float* ln1_g   = (const float*)d_in[2];
    const float* ln1_b   = (const float*)d_in[3];
    const float* w_qkv   = (const float*)d_in[4];
    const float* w_proj  = (const float*)d_in[5];
    const float* b_proj  = (const float*)d_in[6];
    const float* ln2_g   = (const float*)d_in[7];
    const float* ln2_b   = (const float*)d_in[8];
    const float* w_router= (const float*)d_in[9];
    const float* w1      = (const float*)d_in[10];
    const float* b1      = (const float*)d_in[11];
    const float* w2      = (const float*)d_in[12];
    const float* b2      = (const float*)d_in[13];
    float* out = (float*)d_out;

    float *p_xn1, *p_qkv, *p_q, *p_k, *p_v, *p_attn, *p_x2, *p_xn2;
    cudaGetSymbolAddress((void**)&p_xn1,  g_xn1);
    cudaGetSymbolAddress((void**)&p_qkv,  g_qkv);
    cudaGetSymbolAddress((void**)&p_q,    g_q);
    cudaGetSymbolAddress((void**)&p_k,    g_k);
    cudaGetSymbolAddress((void**)&p_v,    g_v);
    cudaGetSymbolAddress((void**)&p_attn, g_attn);
    cudaGetSymbolAddress((void**)&p_x2,   g_x2);
    cudaGetSymbolAddress((void**)&p_xn2,  g_xn2);

    zero_small_kernel<<<1, 32>>>();

    // ln1
    ln_kernel<<<NTOK, 256>>>(x, ln1_g, ln1_b, p_xn1);
    // qkv = xn1 @ w_qkv   [4096,1024]x[1024,3072]
    sgemm128<<<dim3(3 * DM / 128, NTOK / 128), 256>>>(
        p_xn1, w_qkv, nullptr, nullptr, p_qkv, NTOK, 3 * DM, DM);
    // rope + [B,H,T,HD] layout
    rope_kernel<<<NTOK, 256>>>(p_qkv, p_q, p_k, p_v);
    // causal attention
    attn_kernel<<<NBH * TT / 8, 256>>>(p_q, p_k, p_v, p_attn);
    // x2 = attn @ w_proj + b_proj + x
    sgemm128<<<dim3(DM / 128, NTOK / 128), 256>>>(
        p_attn, w_proj, b_proj, x, p_x2, NTOK, DM, DM);
    // ln2
    ln_kernel<<<NTOK, 256>>>(p_x2, ln2_g, ln2_b, p_xn2);
    // router + top-2 + aux stats
    router_kernel<<<NTOK, 128>>>(p_xn2, w_router);
    scan_kernel<<<1, 1>>>();
    place_kernel<<<NSLOT / 256, 256>>>();
    // grouped expert FFN (top-2 routed; identical to gated dense sum)
    moe_ffn1<<<dim3(DFF / 128, NSLOT / 128, NE), 256>>>(p_xn2, w1, b1);
    moe_ffn2<<<dim3(DM / 128, NSLOT / 128, NE), 256>>>(w2, b2);
    // out = x2 + gated expert outputs; write aux scalar
    combine_kernel<<<NTOK, 256>>>(out, out_size);
}

// round 3
// speedup vs baseline: 1.2967x; 1.2967x over previous
#include <cuda_runtime.h>
#include <cuda_bf16.h>
#include <math.h>
#include <stdint.h>

#define NTOK 4096      // B*T
#define DM   1024
#define NH   16
#define HD   64
#define NE   8
#define DFF  4096
#define NSLOT 8192     // NTOK * TOP_K
#define TT   1024
#define NBH  64        // B * NH

typedef __nv_bfloat16 bf16;

// ===================== scratch (static device memory) ========================
__device__ bf16  g_xn1_h [NTOK * DM];
__device__ bf16  g_xn1_l [NTOK * DM];
__device__ float g_qkv   [NTOK * 3 * DM];
__device__ float g_q     [NTOK * DM];   // [B,H,T,HD]
__device__ float g_k     [NTOK * DM];
__device__ float g_v     [NTOK * DM];
__device__ bf16  g_attn_h[NTOK * DM];
__device__ bf16  g_attn_l[NTOK * DM];
__device__ float g_x2    [NTOK * DM];
__device__ float g_xn2   [NTOK * DM];
__device__ bf16  g_xn2_h [NTOK * DM];
__device__ bf16  g_xn2_l [NTOK * DM];
__device__ bf16  g_h_h   [(size_t)NSLOT * DFF];
__device__ bf16  g_h_l   [(size_t)NSLOT * DFF];
__device__ float g_y     [NSLOT * DM];

// transposed hi/lo weights ([N,K] K-major per expert)
__device__ bf16 g_wqkvt_h[3 * DM * DM];
__device__ bf16 g_wqkvt_l[3 * DM * DM];
__device__ bf16 g_wprojt_h[DM * DM];
__device__ bf16 g_wprojt_l[DM * DM];
__device__ bf16 g_w1t_h[(size_t)NE * DFF * DM];
__device__ bf16 g_w1t_l[(size_t)NE * DFF * DM];
__device__ bf16 g_w2t_h[(size_t)NE * DM * DFF];
__device__ bf16 g_w2t_l[(size_t)NE * DM * DFF];

__device__ int   g_cnt[NE];
__device__ int   g_off[NE];
__device__ int   g_cur[NE];
__device__ float g_probsum[NE];
__device__ int   g_top_i[NSLOT];
__device__ float g_top_w[NSLOT];
__device__ int   g_perm_tok[NSLOT];
__device__ float g_slot_gate[NSLOT];
__device__ int   g_slot_of[NSLOT];
__device__ float g_aux;

__device__ __forceinline__ void split_store(float v, bf16* h, bf16* l) {
    bf16 hi = __float2bfloat16(v);
    *h = hi;
    *l = __float2bfloat16(v - __bfloat162float(hi));
}

__device__ __forceinline__ uint32_t smem_u32(const void* p) {
    uint32_t a;
    asm("{ .reg .u64 t; cvta.to.shared.u64 t, %1; cvt.u32.u64 %0, t; }"
        : "=r"(a) : "l"(p));
    return a;
}
__device__ __forceinline__ void ldsm4(uint32_t* r, uint32_t addr) {
    asm volatile("ldmatrix.sync.aligned.m8n8.x4.shared.b16 {%0,%1,%2,%3}, [%4];"
                 : "=r"(r[0]), "=r"(r[1]), "=r"(r[2]), "=r"(r[3]) : "r"(addr));
}
__device__ __forceinline__ void mma_bf16(float* d, const uint32_t* a, const uint32_t* b) {
    asm volatile(
        "mma.sync.aligned.m16n8k16.row.col.f32.bf16.bf16.f32 "
        "{%0,%1,%2,%3}, {%4,%5,%6,%7}, {%8,%9}, {%0,%1,%2,%3};"
        : "+f"(d[0]), "+f"(d[1]), "+f"(d[2]), "+f"(d[3])
        : "r"(a[0]), "r"(a[1]), "r"(a[2]), "r"(a[3]), "r"(b[0]), "r"(b[1]));
}

// ===================== small helpers ====================
__global__ void zero_small_kernel() {
    int i = threadIdx.x;
    if (i < NE) { g_cnt[i] = 0; g_cur[i] = 0; g_probsum[i] = 0.f; }
}

// ---------------- transpose + hi/lo convert: w[K,N] -> t[N,K] ----------------
__global__ void __launch_bounds__(256) trans_conv(
    const float* __restrict__ w, bf16* __restrict__ th, bf16* __restrict__ tl,
    int K, int N)
{
    const size_t eoff = (size_t)blockIdx.z * K * N;
    const float* wp = w + eoff;
    bf16* thp = th + eoff;
    bf16* tlp = tl + eoff;
    __shared__ float t[32][33];
    int tx = threadIdx.x & 31, ty = threadIdx.x >> 5;
    int n0 = blockIdx.x * 32, k0 = blockIdx.y * 32;
    #pragma unroll
    for (int i = 0; i < 4; i++)
        t[ty + i * 8][tx] = wp[(size_t)(k0 + ty + i * 8) * N + n0 + tx];
    __syncthreads();
    #pragma unroll
    for (int i = 0; i < 4; i++) {
        float v = t[tx][ty + i * 8];
        int n = n0 + ty + i * 8, k = k0 + tx;
        bf16 hi = __float2bfloat16(v);
        thp[(size_t)n * K + k] = hi;
        tlp[(size_t)n * K + k] = __float2bfloat16(v - __bfloat162float(hi));
    }
}

// ---------------- layernorm (256 thr/row) ----------------
__global__ void __launch_bounds__(256) ln_kernel(
    const float* __restrict__ x, const float* __restrict__ g,
    const float* __restrict__ b, float* __restrict__ o32,
    bf16* __restrict__ oh, bf16* __restrict__ ol)
{
    int row = blockIdx.x;
    const float* xr = x + (size_t)row * DM;
    float v[4]; float s = 0.f, ss = 0.f;
    #pragma unroll
    for (int i = 0; i < 4; i++) {
        float u = xr[threadIdx.x + i * 256];
        v[i] = u; s += u; ss += u * u;
    }
    #pragma unroll
    for (int ofs = 16; ofs > 0; ofs >>= 1) {
        s  += __shfl_xor_sync(0xffffffffu, s,  ofs);
        ss += __shfl_xor_sync(0xffffffffu, ss, ofs);
    }
    __shared__ float sh[2][8];
    int warp = threadIdx.x >> 5, lane = threadIdx.x & 31;
    if (lane == 0) { sh[0][warp] = s; sh[1][warp] = ss; }
    __syncthreads();
    float S = 0.f, SS = 0.f;
    #pragma unroll
    for (int w = 0; w < 8; w++) { S += sh[0][w]; SS += sh[1][w]; }
    float mu  = S * (1.0f / DM);
    float var = SS * (1.0f / DM) - mu * mu;
    float inv = rsqrtf(var + 1e-5f);
    #pragma unroll
    for (int i = 0; i < 4; i++) {
        int idx = threadIdx.x + i * 256;
        float o = (v[i] - mu) * inv * g[idx] + b[idx];
        size_t p = (size_t)row * DM + idx;
        if (o32) o32[p] = o;
        split_store(o, oh + p, ol + p);
    }
}

// ---------------- RoPE + layout transform ----------------
__global__ void __launch_bounds__(256) rope_kernel(
    const float* __restrict__ qkv, float* __restrict__ q,
    float* __restrict__ k, float* __restrict__ v)
{
    int tok = blockIdx.x;
    int b = tok >> 10, t = tok & 1023;
    const float* row = qkv + (size_t)tok * (3 * DM);
    for (int i = threadIdx.x; i < DM; i += 256) {
        int h = i >> 6, d = i & 63;
        int f = d & 31;
        float freq = powf(10000.0f, -(float)f / 32.0f);
        float ang = (float)t * freq;
        float sv, cv;
        sincosf(ang, &sv, &cv);
        float qa = row[i], ka = row[DM + i];
        float qo, ko;
        if (d < 32) {
            qo = qa * cv - row[i + 32] * sv;
            ko = ka * cv - row[DM + i + 32] * sv;
        } else {
            qo = qa * cv + row[i - 32] * sv;
            ko = ka * cv + row[DM + i - 32] * sv;
        }
        int dst = ((b * NH + h) * TT + t) * HD + d;
        q[dst] = qo;
        k[dst] = ko;
        v[dst] = row[2 * DM + i];
    }
}

// ---------------- causal attention: one warp per query row -------------------
__global__ void __launch_bounds__(256) attn_kernel(
    const float* __restrict__ q, const float* __restrict__ k,
    const float* __restrict__ v, bf16* __restrict__ oh, bf16* __restrict__ ol)
{
    int warp = threadIdx.x >> 5, lane = threadIdx.x & 31;
    int gr = blockIdx.x * 8 + warp;
    int bh = gr >> 10;
    int t  = gr & 1023;
    const float* qp = q + (size_t)gr * HD;
    float q0 = qp[lane], q1 = qp[lane + 32];
    const float* kb = k + (size_t)bh * TT * HD;
    const float* vb = v + (size_t)bh * TT * HD;
    float m = -1e30f, l = 0.f, a0 = 0.f, a1 = 0.f;
    for (int j = 0; j <= t; j++) {
        const float* kj = kb + j * HD;
        float s = q0 * kj[lane] + q1 * kj[lane + 32];
        #pragma unroll
        for (int ofs = 16; ofs > 0; ofs >>= 1)
            s += __shfl_xor_sync(0xffffffffu, s, ofs);
        s *= 0.125f;
        const float* vj = vb + j * HD;
        float v0 = vj[lane], v1 = vj[lane + 32];
        if (s <= m) {
            float p = __expf(s - m);
            l += p; a0 += p * v0; a1 += p * v1;
        } else {
            float c = __expf(m - s);
            l = l * c + 1.f; a0 = a0 * c + v0; a1 = a1 * c + v1;
            m = s;
        }
    }
    int b = bh >> 4, h = bh & 15;
    size_t op = ((size_t)(b * TT + t)) * DM + h * HD;
    float inv = 1.0f / l;
    split_store(a0 * inv, oh + op + lane, ol + op + lane);
    split_store(a1 * inv, oh + op + lane + 32, ol + op + lane + 32);
}

// ===================== HMMA GEMM core ========================================
// C[128x128] = A[128,K](hi/lo) x B[128,K]^T(hi/lo), fp32 accum via
// mma.sync m16n8k16 bf16. 256 threads = 8 warps (2 x 4), warp tile 64x32.
// smem: 4 tiles of [128 rows][64 bf16] SW128-swizzled, K chunk = 64.

#define SA_H 0
#define SA_L 16384
#define SB_H 32768
#define SB_L 49152
#define GEMM_SMEM 65536

__device__ __forceinline__ uint32_t sw128(uint32_t o) {
    return o ^ ((o >> 3) & 0x70u);
}

__device__ __forceinline__ void gemm_mainloop(
    char* smem, uint32_t sb, float (*acc)[4],
    const bf16* __restrict__ ah, const bf16* __restrict__ al,
    const bf16* __restrict__ bh, const bf16* __restrict__ bl,
    int K, const int* __restrict__ perm, int row_base, int valid, int b_row0)
{
    const int tid = threadIdx.x;
    const int lane = tid & 31;
    const int wid = tid >> 5;
    const int wm = wid >> 2, wn = wid & 3;
    const int nkb = K >> 6;

    for (int kb = 0; kb < nkb; kb++) {
        // ---- load 4 x 16KB tiles (A hi/lo gathered rows, B hi/lo) ----
        #pragma unroll
        for (int it = 0; it < 4; it++) {
            int idx = tid + it * 256;       // [0,1024)
            int row = idx >> 3, ch = idx & 7;
            int koff = kb * 64 + ch * 8;
            uint32_t so = sw128((uint32_t)(row * 128 + ch * 16));
            uint4 vh = make_uint4(0, 0, 0, 0), vl = make_uint4(0, 0, 0, 0);
            if (row < valid) {
                int gra = perm ? perm[row_base + row] : (row_base + row);
                size_t ab = (size_t)gra * K + koff;
                vh = *(const uint4*)(ah + ab);
                vl = *(const uint4*)(al + ab);
            }
            *(uint4*)(smem + SA_H + so) = vh;
            *(uint4*)(smem + SA_L + so) = vl;
            size_t bb = (size_t)(b_row0 + row) * K + koff;
            *(uint4*)(smem + SB_H + so) = *(const uint4*)(bh + bb);
            *(uint4*)(smem + SB_L + so) = *(const uint4*)(bl + bb);
        }
        __syncthreads();
        // ---- compute 4 k-steps of 16 ----
        #pragma unroll
        for (int ks = 0; ks < 4; ks++) {
            uint32_t afh[4][4], afl[4][4];
            #pragma unroll
            for (int mt = 0; mt < 4; mt++) {
                int row = wm * 64 + mt * 16 + (lane & 15);
                uint32_t so = sw128((uint32_t)(row * 128 + ks * 32 + (lane >> 4) * 16));
                ldsm4(afh[mt], sb + SA_H + so);
                ldsm4(afl[mt], sb + SA_L + so);
            }
            uint32_t bfh[4][2], bfl[4][2];
            #pragma unroll
            for (int n2 = 0; n2 < 2; n2++) {
                int row = wn * 32 + n2 * 16 + (lane & 15);
                uint32_t so = sw128((uint32_t)(row * 128 + ks * 32 + (lane >> 4) * 16));
                uint32_t t4[4];
                ldsm4(t4, sb + SB_H + so);
                bfh[n2 * 2][0] = t4[0]; bfh[n2 * 2][1] = t4[2];
                bfh[n2 * 2 + 1][0] = t4[1]; bfh[n2 * 2 + 1][1] = t4[3];
                ldsm4(t4, sb + SB_L + so);
                bfl[n2 * 2][0] = t4[0]; bfl[n2 * 2][1] = t4[2];
                bfl[n2 * 2 + 1][0] = t4[1]; bfl[n2 * 2 + 1][1] = t4[3];
            }
            #pragma unroll
            for (int mt = 0; mt < 4; mt++)
                #pragma unroll
                for (int nt = 0; nt < 4; nt++) {
                    float* d = acc[mt * 4 + nt];
                    mma_bf16(d, afh[mt], bfh[nt]);
                    mma_bf16(d, afl[mt], bfh[nt]);
                    mma_bf16(d, afh[mt], bfl[nt]);
                }
        }
        __syncthreads();
    }
}

// element coords for acc[mt*4+nt][r]:
//   row = wm*64 + mt*16 + lane/4 + 8*(r>>1)
//   col = wn*32 + nt*8  + 2*(lane&3) + (r&1)

// ---------------- qkv = xn1 @ w_qkv ----------------
__global__ void __launch_bounds__(256) qkv_gemm() {
    extern __shared__ char smem[];
    uint32_t sb = smem_u32(smem);
    float acc[16][4];
    #pragma unroll
    for (int i = 0; i < 16; i++)
        #pragma unroll
        for (int j = 0; j < 4; j++) acc[i][j] = 0.f;
    int m0 = blockIdx.y * 128, n0 = blockIdx.x * 128;
    gemm_mainloop(smem, sb, acc, g_xn1_h, g_xn1_l, g_wqkvt_h, g_wqkvt_l,
                  DM, nullptr, m0, 128, n0);
    int lane = threadIdx.x & 31, wid = threadIdx.x >> 5;
    int wm = wid >> 2, wn = wid & 3;
    #pragma unroll
    for (int mt = 0; mt < 4; mt++)
        #pragma unroll
        for (int nt = 0; nt < 4; nt++) {
            int r = m0 + wm * 64 + mt * 16 + (lane >> 2);
            int c = n0 + wn * 32 + nt * 8 + 2 * (lane & 3);
            float* d = acc[mt * 4 + nt];
            float* p0 = g_qkv + (size_t)r * (3 * DM) + c;
            p0[0] = d[0]; p0[1] = d[1];
            float* p1 = g_qkv + (size_t)(r + 8) * (3 * DM) + c;
            p1[0] = d[2]; p1[1] = d[3];
        }
}

// ---------------- x2 = attn @ w_proj + b_proj + x ----------------
__global__ void __launch_bounds__(256) proj_gemm(
    const float* __restrict__ bias, const float* __restrict__ resid)
{
    extern __shared__ char smem[];
    uint32_t sb = smem_u32(smem);
    float acc[16][4];
    #pragma unroll
    for (int i = 0; i < 16; i++)
        #pragma unroll
        for (int j = 0; j < 4; j++) acc[i][j] = 0.f;
    int m0 = blockIdx.y * 128, n0 = blockIdx.x * 128;
    gemm_mainloop(smem, sb, acc, g_attn_h, g_attn_l, g_wprojt_h, g_wprojt_l,
                  DM, nullptr, m0, 128, n0);
    int lane = threadIdx.x & 31, wid = threadIdx.x >> 5;
    int wm = wid >> 2, wn = wid & 3;
    #pragma unroll
    for (int mt = 0; mt < 4; mt++)
        #pragma unroll
        for (int nt = 0; nt < 4; nt++) {
            int r = m0 + wm * 64 + mt * 16 + (lane >> 2);
            int c = n0 + wn * 32 + nt * 8 + 2 * (lane & 3);
            float* d = acc[mt * 4 + nt];
            size_t p0 = (size_t)r * DM + c;
            size_t p1 = (size_t)(r + 8) * DM + c;
            g_x2[p0]     = d[0] + bias[c]     + resid[p0];
            g_x2[p0 + 1] = d[1] + bias[c + 1] + resid[p0 + 1];
            g_x2[p1]     = d[2] + bias[c]     + resid[p1];
            g_x2[p1 + 1] = d[3] + bias[c + 1] + resid[p1 + 1];
        }
}

// ---------------- h = gelu(gather(xn2) @ w1[e] + b1[e]) ----------------
__global__ void __launch_bounds__(256) ffn1_gemm(const float* __restrict__ B1) {
    int e = blockIdx.z;
    int cnt = g_cnt[e];
    int r0 = blockIdx.y * 128;
    if (r0 >= cnt) return;
    extern __shared__ char smem[];
    uint32_t sb = smem_u32(smem);
    float acc[16][4];
    #pragma unroll
    for (int i = 0; i < 16; i++)
        #pragma unroll
        for (int j = 0; j < 4; j++) acc[i][j] = 0.f;
    int off = g_off[e];
    int n0 = blockIdx.x * 128;
    int valid = cnt - r0; if (valid > 128) valid = 128;
    gemm_mainloop(smem, sb, acc, g_xn2_h, g_xn2_l,
                  g_w1t_h + (size_t)e * DFF * DM, g_w1t_l + (size_t)e * DFF * DM,
                  DM, g_perm_tok, off + r0, valid, n0);
    int lane = threadIdx.x & 31, wid = threadIdx.x >> 5;
    int wm = wid >> 2, wn = wid & 3;
    const float* bias = B1 + e * DFF;
    #pragma unroll
    for (int mt = 0; mt < 4; mt++)
        #pragma unroll
        for (int nt = 0; nt < 4; nt++) {
            int rl = wm * 64 + mt * 16 + (lane >> 2);
            int c = n0 + wn * 32 + nt * 8 + 2 * (lane & 3);
            float* d = acc[mt * 4 + nt];
            #pragma unroll
            for (int half = 0; half < 2; half++) {
                int row = rl + half * 8;
                if (row >= valid) continue;
                size_t rp = (size_t)(off + r0 + row) * DFF + c;
                #pragma unroll
                for (int u = 0; u < 2; u++) {
                    float v = d[half * 2 + u] + bias[c + u];
                    v = 0.5f * v * (1.0f + erff(v * 0.70710678118654752f));
                    split_store(v, g_h_h + rp + u, g_h_l + rp + u);
                }
            }
        }
}

// ---------------- y = h @ w2[e] + b2[e] ----------------
__global__ void __launch_bounds__(256) ffn2_gemm(const float* __restrict__ B2) {
    int e = blockIdx.z;
    int cnt = g_cnt[e];
    int r0 = blockIdx.y * 128;
    if (r0 >= cnt) return;
    extern __shared__ char smem[];
    uint32_t sb = smem_u32(smem);
    float acc[16][4];
    #pragma unroll
    for (int i = 0; i < 16; i++)
        #pragma unroll
        for (int j = 0; j < 4; j++) acc[i][j] = 0.f;
    int off = g_off[e];
    int n0 = blockIdx.x * 128;
    int valid = cnt - r0; if (valid > 128) valid = 128;
    gemm_mainloop(smem, sb, acc, g_h_h, g_h_l,
                  g_w2t_h + (size_t)e * DM * DFF, g_w2t_l + (size_t)e * DM * DFF,
                  DFF, nullptr, off + r0, valid, n0);
    int lane = threadIdx.x & 31, wid = threadIdx.x >> 5;
    int wm = wid >> 2, wn = wid & 3;
    const float* bias = B2 + e * DM;
    #pragma unroll
    for (int mt = 0; mt < 4; mt++)
        #pragma unroll
        for (int nt = 0; nt < 4; nt++) {
            int rl = wm * 64 + mt * 16 + (lane >> 2);
            int c = n0 + wn * 32 + nt * 8 + 2 * (lane & 3);
            float* d = acc[mt * 4 + nt];
            #pragma unroll
            for (int half = 0; half < 2; half++) {
                int row = rl + half * 8;
                if (row >= valid) continue;
                size_t rp = (size_t)(off + r0 + row) * DM + c;
                g_y[rp]     = d[half * 2]     + bias[c];
                g_y[rp + 1] = d[half * 2 + 1] + bias[c + 1];
            }
        }
}

// ---------------- router ----------------
__global__ void __launch_bounds__(128) router_kernel(
    const float* __restrict__ xn2, const float* __restrict__ wr)
{
    int tok = blockIdx.x, tid = threadIdx.x;
    const float* xr = xn2 + (size_t)tok * DM;
    float p[NE];
    #pragma unroll
    for (int e = 0; e < NE; e++) p[e] = 0.f;
    for (int i = tid; i < DM; i += 128) {
        float xv = xr[i];
        const float* w = wr + i * NE;
        #pragma unroll
        for (int e = 0; e < NE; e++) p[e] += xv * w[e];
    }
    __shared__ float red[NE][128];
    #pragma unroll
    for (int e = 0; e < NE; e++) red[e][tid] = p[e];
    __syncthreads();
    for (int st = 64; st > 0; st >>= 1) {
        if (tid < st) {
            #pragma unroll
            for (int e = 0; e < NE; e++) red[e][tid] += red[e][tid + st];
        }
        __syncthreads();
    }
    if (tid == 0) {
        float lg[NE], mx = -1e30f;
        #pragma unroll
        for (int e = 0; e < NE; e++) { lg[e] = red[e][0]; mx = fmaxf(mx, lg[e]); }
        float se = 0.f, pr[NE];
        #pragma unroll
        for (int e = 0; e < NE; e++) { pr[e] = __expf(lg[e] - mx); se += pr[e]; }
        float inv = 1.0f / se;
        #pragma unroll
        for (int e = 0; e < NE; e++) {
            pr[e] *= inv;
            atomicAdd(&g_probsum[e], pr[e]);
        }
        int i0 = 0;
        #pragma unroll
        for (int e = 1; e < NE; e++) if (pr[e] > pr[i0]) i0 = e;
        int i1 = (i0 == 0) ? 1 : 0;
        #pragma unroll
        for (int e = 0; e < NE; e++) if (e != i0 && pr[e] > pr[i1]) i1 = e;
        float w0 = pr[i0], w1 = pr[i1], sw = 1.0f / (w0 + w1);
        g_top_i[tok * 2] = i0; g_top_i[tok * 2 + 1] = i1;
        g_top_w[tok * 2] = w0 * sw; g_top_w[tok * 2 + 1] = w1 * sw;
        atomicAdd(&g_cnt[i0], 1);
        atomicAdd(&g_cnt[i1], 1);
    }
}

__global__ void scan_kernel() {
    if (threadIdx.x == 0 && blockIdx.x == 0) {
        int o = 0;
        float aux = 0.f;
        for (int e = 0; e < NE; e++) { g_off[e] = o; o += g_cnt[e]; }
        for (int e = 0; e < NE; e++)
            aux += ((float)g_cnt[e] / (float)(NTOK * 2)) * (g_probsum[e] / (float)NTOK);
        g_aux = (float)NE * aux;
    }
}

__global__ void place_kernel() {
    int s = blockIdx.x * 256 + threadIdx.x;
    if (s >= NSLOT) return;
    int tok = s >> 1;
    int e = g_top_i[s];
    float w = g_top_w[s];
    int pos = atomicAdd(&g_cur[e], 1);
    int slot = g_off[e] + pos;
    g_perm_tok[slot] = tok;
    g_slot_gate[slot] = w;
    g_slot_of[s] = slot;
}

// ---------------- final combine ----------------
__global__ void __launch_bounds__(256) combine_kernel(float* __restrict__ out, int out_size)
{
    int tok = blockIdx.x;
    int s0 = g_slot_of[tok * 2], s1 = g_slot_of[tok * 2 + 1];
    float w0 = g_slot_gate[s0], w1 = g_slot_gate[s1];
    const float* y0 = g_y + (size_t)s0 * DM;
    const float* y1 = g_y + (size_t)s1 * DM;
    const float* xr = g_x2 + (size_t)tok * DM;
    float* orow = out + (size_t)tok * DM;
    #pragma unroll
    for (int l = 0; l < 4; l++) {
        int i = threadIdx.x + l * 256;
        orow[i] = xr[i] + w0 * y0[i] + w1 * y1[i];
    }
    if (tok == 0 && threadIdx.x == 0 && out_size > NTOK * DM)
        out[NTOK * DM] = g_aux;
}

// ===================== launch =====================
extern "C" void kernel_launch(void* const* d_in, const int* in_sizes, int n_in,
                              void* d_out, int out_size)
{
    const float* x        = (const float*)d_in[0];
    const float* ln1_g    = (const float*)d_in[2];
    const float* ln1_b    = (const float*)d_in[3];
    const float* w_qkv    = (const float*)d_in[4];
    const float* w_proj   = (const float*)d_in[5];
    const float* b_proj   = (const float*)d_in[6];
    const float* ln2_g    = (const float*)d_in[7];
    const float* ln2_b    = (const float*)d_in[8];
    const float* w_router = (const float*)d_in[9];
    const float* w1       = (const float*)d_in[10];
    const float* b1       = (const float*)d_in[11];
    const float* w2       = (const float*)d_in[12];
    const float* b2       = (const float*)d_in[13];
    float* out = (float*)d_out;

    static bool attr_done = false;
    if (!attr_done) {
        cudaFuncSetAttribute(qkv_gemm,  cudaFuncAttributeMaxDynamicSharedMemorySize, GEMM_SMEM);
        cudaFuncSetAttribute(proj_gemm, cudaFuncAttributeMaxDynamicSharedMemorySize, GEMM_SMEM);
        cudaFuncSetAttribute(ffn1_gemm, cudaFuncAttributeMaxDynamicSharedMemorySize, GEMM_SMEM);
        cudaFuncSetAttribute(ffn2_gemm, cudaFuncAttributeMaxDynamicSharedMemorySize, GEMM_SMEM);
        attr_done = true;
    }

    float *p_qkv, *p_q, *p_k, *p_v, *p_x2, *p_xn2;
    bf16 *p_xn1_h, *p_xn1_l, *p_attn_h, *p_attn_l, *p_xn2_h, *p_xn2_l;
    bf16 *p_wqkvt_h, *p_wqkvt_l, *p_wprojt_h, *p_wprojt_l;
    bf16 *p_w1t_h, *p_w1t_l, *p_w2t_h, *p_w2t_l;
    cudaGetSymbolAddress((void**)&p_qkv,  g_qkv);
    cudaGetSymbolAddress((void**)&p_q,    g_q);
    cudaGetSymbolAddress((void**)&p_k,    g_k);
    cudaGetSymbolAddress((void**)&p_v,    g_v);
    cudaGetSymbolAddress((void**)&p_x2,   g_x2);
    cudaGetSymbolAddress((void**)&p_xn2,  g_xn2);
    cudaGetSymbolAddress((void**)&p_xn1_h, g_xn1_h);
    cudaGetSymbolAddress((void**)&p_xn1_l, g_xn1_l);
    cudaGetSymbolAddress((void**)&p_attn_h, g_attn_h);
    cudaGetSymbolAddress((void**)&p_attn_l, g_attn_l);
    cudaGetSymbolAddress((void**)&p_xn2_h, g_xn2_h);
    cudaGetSymbolAddress((void**)&p_xn2_l, g_xn2_l);
    cudaGetSymbolAddress((void**)&p_wqkvt_h, g_wqkvt_h);
    cudaGetSymbolAddress((void**)&p_wqkvt_l, g_wqkvt_l);
    cudaGetSymbolAddress((void**)&p_wprojt_h, g_wprojt_h);
    cudaGetSymbolAddress((void**)&p_wprojt_l, g_wprojt_l);
    cudaGetSymbolAddress((void**)&p_w1t_h, g_w1t_h);
    cudaGetSymbolAddress((void**)&p_w1t_l, g_w1t_l);
    cudaGetSymbolAddress((void**)&p_w2t_h, g_w2t_h);
    cudaGetSymbolAddress((void**)&p_w2t_l, g_w2t_l);

    zero_small_kernel<<<1, 32>>>();

    // weight transpose + hi/lo bf16 conversion
    trans_conv<<<dim3(3 * DM / 32, DM / 32, 1), 256>>>(w_qkv, p_wqkvt_h, p_wqkvt_l, DM, 3 * DM);
    trans_conv<<<dim3(DM / 32, DM / 32, 1), 256>>>(w_proj, p_wprojt_h, p_wprojt_l, DM, DM);
    trans_conv<<<dim3(DFF / 32, DM / 32, NE), 256>>>(w1, p_w1t_h, p_w1t_l, DM, DFF);
    trans_conv<<<dim3(DM / 32, DFF / 32, NE), 256>>>(w2, p_w2t_h, p_w2t_l, DFF, DM);

    // ln1 -> hi/lo
    ln_kernel<<<NTOK, 256>>>(x, ln1_g, ln1_b, nullptr, p_xn1_h, p_xn1_l);
    // qkv gemm (HMMA)
    qkv_gemm<<<dim3(3 * DM / 128, NTOK / 128), 256, GEMM_SMEM>>>();
    // rope
    rope_kernel<<<NTOK, 256>>>(p_qkv, p_q, p_k, p_v);
    // attention -> hi/lo
    attn_kernel<<<NBH * TT / 8, 256>>>(p_q, p_k, p_v, p_attn_h, p_attn_l);
    // proj gemm + residual
    proj_gemm<<<dim3(DM / 128, NTOK / 128), 256, GEMM_SMEM>>>(b_proj, x);
    // ln2 -> fp32 + hi/lo
    ln_kernel<<<NTOK, 256>>>(p_x2, ln2_g, ln2_b, p_xn2, p_xn2_h, p_xn2_l);
    // router + placement
    router_kernel<<<NTOK, 128>>>(p_xn2, w_router);
    scan_kernel<<<1, 1>>>();
    place_kernel<<<NSLOT / 256, 256>>>();
    // grouped expert FFN (HMMA)
    ffn1_gemm<<<dim3(DFF / 128, NSLOT / 128, NE), 256, GEMM_SMEM>>>(b1);
    ffn2_gemm<<<dim3(DM / 128, NSLOT / 128, NE), 256, GEMM_SMEM>>>(b2);
    // combine
    combine_kernel<<<NTOK, 256>>>(out, out_size);
}

// round 4
// speedup vs baseline: 1.3364x; 1.0306x over previous
#include <cuda_runtime.h>
#include <cuda_fp16.h>
#include <math.h>
#include <stdint.h>

#define NTOK 4096      // B*T
#define DM   1024
#define NH   16
#define HD   64
#define NE   8
#define DFF  4096
#define NSLOT 8192     // NTOK * TOP_K
#define TT   1024
#define NBH  64        // B * NH

typedef __half h16;

// ===================== scratch (static device memory) ========================
__device__ h16   g_xn1_h [NTOK * DM];
__device__ h16   g_xn1_l [NTOK * DM];
__device__ float g_qkv   [NTOK * 3 * DM];
__device__ float g_q     [NTOK * DM];   // [B,H,T,HD]
__device__ float g_k     [NTOK * DM];
__device__ float g_v     [NTOK * DM];
__device__ h16   g_attn_h[NTOK * DM];
__device__ h16   g_attn_l[NTOK * DM];
__device__ float g_x2    [NTOK * DM];
__device__ float g_xn2   [NTOK * DM];
__device__ h16   g_xn2_h [NTOK * DM];
__device__ h16   g_hbuf  [(size_t)NSLOT * DFF];
__device__ float g_y     [NSLOT * DM];

// transposed weights ([N,K] K-major per expert)
__device__ h16 g_wqkvt_h[3 * DM * DM];
__device__ h16 g_wqkvt_l[3 * DM * DM];
__device__ h16 g_wprojt_h[DM * DM];
__device__ h16 g_wprojt_l[DM * DM];
__device__ h16 g_w1t[(size_t)NE * DFF * DM];
__device__ h16 g_w2t[(size_t)NE * DM * DFF];

__device__ int   g_cnt[NE];
__device__ int   g_off[NE];
__device__ int   g_cur[NE];
__device__ float g_probsum[NE];
__device__ int   g_top_i[NSLOT];
__device__ float g_top_w[NSLOT];
__device__ int   g_perm_tok[NSLOT];
__device__ float g_slot_gate[NSLOT];
__device__ int   g_slot_of[NSLOT];
__device__ float g_aux;

__device__ __forceinline__ void split_store(float v, h16* h, h16* l) {
    h16 hi = __float2half_rn(v);
    *h = hi;
    *l = __float2half_rn(v - __half2float(hi));
}

__device__ __forceinline__ uint32_t smem_u32(const void* p) {
    uint32_t a;
    asm("{ .reg .u64 t; cvta.to.shared.u64 t, %1; cvt.u32.u64 %0, t; }"
        : "=r"(a) : "l"(p));
    return a;
}
__device__ __forceinline__ void ldsm4(uint32_t* r, uint32_t addr) {
    asm volatile("ldmatrix.sync.aligned.m8n8.x4.shared.b16 {%0,%1,%2,%3}, [%4];"
                 : "=r"(r[0]), "=r"(r[1]), "=r"(r[2]), "=r"(r[3]) : "r"(addr));
}
__device__ __forceinline__ void mma_f16(float* d, const uint32_t* a, const uint32_t* b) {
    asm volatile(
        "mma.sync.aligned.m16n8k16.row.col.f32.f16.f16.f32 "
        "{%0,%1,%2,%3}, {%4,%5,%6,%7}, {%8,%9}, {%0,%1,%2,%3};"
        : "+f"(d[0]), "+f"(d[1]), "+f"(d[2]), "+f"(d[3])
        : "r"(a[0]), "r"(a[1]), "r"(a[2]), "r"(a[3]), "r"(b[0]), "r"(b[1]));
}
__device__ __forceinline__ void cp_async16(uint32_t saddr, const void* g, uint32_t sz) {
    asm volatile("cp.async.cg.shared.global [%0], [%1], 16, %2;"
                 :: "r"(saddr), "l"(g), "r"(sz));
}
__device__ __forceinline__ void cp_commit() {
    asm volatile("cp.async.commit_group;");
}
template<int N> __device__ __forceinline__ void cp_wait() {
    asm volatile("cp.async.wait_group %0;" :: "n"(N));
}
__device__ __forceinline__ uint32_t sw128(uint32_t o) {
    return o ^ ((o >> 3) & 0x70u);
}

// ===================== small helpers ====================
__global__ void zero_small_kernel() {
    int i = threadIdx.x;
    if (i < NE) { g_cnt[i] = 0; g_cur[i] = 0; g_probsum[i] = 0.f; }
}

// ---------------- transpose + convert: w[K,N] -> t[N,K] (lo optional) --------
__global__ void __launch_bounds__(256) trans_conv(
    const float* __restrict__ w, h16* __restrict__ th, h16* __restrict__ tl,
    int K, int N)
{
    const size_t eoff = (size_t)blockIdx.z * K * N;
    const float* wp = w + eoff;
    h16* thp = th + eoff;
    h16* tlp = tl ? tl + eoff : nullptr;
    __shared__ float t[32][33];
    int tx = threadIdx.x & 31, ty = threadIdx.x >> 5;
    int n0 = blockIdx.x * 32, k0 = blockIdx.y * 32;
    #pragma unroll
    for (int i = 0; i < 4; i++)
        t[ty + i * 8][tx] = wp[(size_t)(k0 + ty + i * 8) * N + n0 + tx];
    __syncthreads();
    #pragma unroll
    for (int i = 0; i < 4; i++) {
        float v = t[tx][ty + i * 8];
        int n = n0 + ty + i * 8, k = k0 + tx;
        h16 hi = __float2half_rn(v);
        thp[(size_t)n * K + k] = hi;
        if (tlp) tlp[(size_t)n * K + k] = __float2half_rn(v - __half2float(hi));
    }
}

// ---------------- layernorm (256 thr/row) ----------------
__global__ void __launch_bounds__(256) ln_kernel(
    const float* __restrict__ x, const float* __restrict__ g,
    const float* __restrict__ b, float* __restrict__ o32,
    h16* __restrict__ oh, h16* __restrict__ ol)
{
    int row = blockIdx.x;
    const float* xr = x + (size_t)row * DM;
    float v[4]; float s = 0.f, ss = 0.f;
    #pragma unroll
    for (int i = 0; i < 4; i++) {
        float u = xr[threadIdx.x + i * 256];
        v[i] = u; s += u; ss += u * u;
    }
    #pragma unroll
    for (int ofs = 16; ofs > 0; ofs >>= 1) {
        s  += __shfl_xor_sync(0xffffffffu, s,  ofs);
        ss += __shfl_xor_sync(0xffffffffu, ss, ofs);
    }
    __shared__ float sh[2][8];
    int warp = threadIdx.x >> 5, lane = threadIdx.x & 31;
    if (lane == 0) { sh[0][warp] = s; sh[1][warp] = ss; }
    __syncthreads();
    float S = 0.f, SS = 0.f;
    #pragma unroll
    for (int w = 0; w < 8; w++) { S += sh[0][w]; SS += sh[1][w]; }
    float mu  = S * (1.0f / DM);
    float var = SS * (1.0f / DM) - mu * mu;
    float inv = rsqrtf(var + 1e-5f);
    #pragma unroll
    for (int i = 0; i < 4; i++) {
        int idx = threadIdx.x + i * 256;
        float o = (v[i] - mu) * inv * g[idx] + b[idx];
        size_t p = (size_t)row * DM + idx;
        if (o32) o32[p] = o;
        h16 hi = __float2half_rn(o);
        oh[p] = hi;
        if (ol) ol[p] = __float2half_rn(o - __half2float(hi));
    }
}

// ---------------- RoPE + layout transform ----------------
__global__ void __launch_bounds__(256) rope_kernel(
    const float* __restrict__ qkv, float* __restrict__ q,
    float* __restrict__ k, float* __restrict__ v)
{
    int tok = blockIdx.x;
    int b = tok >> 10, t = tok & 1023;
    const float* row = qkv + (size_t)tok * (3 * DM);
    for (int i = threadIdx.x; i < DM; i += 256) {
        int h = i >> 6, d = i & 63;
        int f = d & 31;
        float freq = powf(10000.0f, -(float)f / 32.0f);
        float ang = (float)t * freq;
        float sv, cv;
        sincosf(ang, &sv, &cv);
        float qa = row[i], ka = row[DM + i];
        float qo, ko;
        if (d < 32) {
            qo = qa * cv - row[i + 32] * sv;
            ko = ka * cv - row[DM + i + 32] * sv;
        } else {
            qo = qa * cv + row[i - 32] * sv;
            ko = ka * cv + row[DM + i - 32] * sv;
        }
        int dst = ((b * NH + h) * TT + t) * HD + d;
        q[dst] = qo;
        k[dst] = ko;
        v[dst] = row[2 * DM + i];
    }
}

// ---------------- causal attention: one warp per query row -------------------
__global__ void __launch_bounds__(256) attn_kernel(
    const float* __restrict__ q, const float* __restrict__ k,
    const float* __restrict__ v, h16* __restrict__ oh, h16* __restrict__ ol)
{
    int warp = threadIdx.x >> 5, lane = threadIdx.x & 31;
    int gr = blockIdx.x * 8 + warp;
    int bh = gr >> 10;
    int t  = gr & 1023;
    const float* qp = q + (size_t)gr * HD;
    float q0 = qp[lane], q1 = qp[lane + 32];
    const float* kb = k + (size_t)bh * TT * HD;
    const float* vb = v + (size_t)bh * TT * HD;
    float m = -1e30f, l = 0.f, a0 = 0.f, a1 = 0.f;
    for (int j = 0; j <= t; j++) {
        const float* kj = kb + j * HD;
        float s = q0 * kj[lane] + q1 * kj[lane + 32];
        #pragma unroll
        for (int ofs = 16; ofs > 0; ofs >>= 1)
            s += __shfl_xor_sync(0xffffffffu, s, ofs);
        s *= 0.125f;
        const float* vj = vb + j * HD;
        float v0 = vj[lane], v1 = vj[lane + 32];
        if (s <= m) {
            float p = __expf(s - m);
            l += p; a0 += p * v0; a1 += p * v1;
        } else {
            float c = __expf(m - s);
            l = l * c + 1.f; a0 = a0 * c + v0; a1 = a1 * c + v1;
            m = s;
        }
    }
    int b = bh >> 4, h = bh & 15;
    size_t op = ((size_t)(b * TT + t)) * DM + h * HD;
    float inv = 1.0f / l;
    split_store(a0 * inv, oh + op + lane, ol + op + lane);
    split_store(a1 * inv, oh + op + lane + 32, ol + op + lane + 32);
}

// ===================== pipelined HMMA GEMM core ==============================
// C[128x128] = A[128,K] x B[128,K]^T, fp32 accum, mma.sync m16n8k16 f16.
// 256 threads = 8 warps (2x4), warp tile 64x32. K chunk 64, SW128 smem,
// 2-stage cp.async pipeline. TERMS=3: A hi/lo + B hi/lo (3 mma);
// TERMS=1: single term.

template<int TERMS>
__device__ __forceinline__ void gemm_pipe(
    uint32_t sb, float (*acc)[4],
    const h16* __restrict__ ah, const h16* __restrict__ al,
    const h16* __restrict__ bh, const h16* __restrict__ bl,
    int K, const int* __restrict__ perm, int row_base, int valid, int b_row0)
{
    constexpr uint32_t T_A_H = 0;
    constexpr uint32_t T_A_L = 16384;
    constexpr uint32_t T_B_H = (TERMS == 3) ? 32768u : 16384u;
    constexpr uint32_t T_B_L = 49152;
    constexpr uint32_t STAGE = (TERMS == 3) ? 65536u : 32768u;

    const int tid = threadIdx.x, lane = tid & 31, wid = tid >> 5;
    const int wm = wid >> 2, wn = wid & 3;
    const int nkb = K >> 6;

    // per-thread load constants (rows fixed across stages)
    size_t aoff[4], boff[4];
    uint32_t soff[4], asz[4];
    int chs[4];
    #pragma unroll
    for (int it = 0; it < 4; it++) {
        int idx = tid + it * 256;
        int row = idx >> 3, ch = idx & 7;
        chs[it] = ch;
        soff[it] = sw128((uint32_t)(row * 128 + ch * 16));
        asz[it] = (row < valid) ? 16u : 0u;
        int gra = (row < valid) ? (perm ? perm[row_base + row] : (row_base + row)) : 0;
        aoff[it] = (size_t)gra * K;
        boff[it] = (size_t)(b_row0 + row) * K;
    }

    auto load_stage = [&](int kb, int buf) {
        uint32_t s0 = sb + buf * STAGE;
        #pragma unroll
        for (int it = 0; it < 4; it++) {
            int koff = kb * 64 + chs[it] * 8;
            cp_async16(s0 + T_A_H + soff[it], ah + aoff[it] + koff, asz[it]);
            if (TERMS == 3)
                cp_async16(s0 + T_A_L + soff[it], al + aoff[it] + koff, asz[it]);
            cp_async16(s0 + T_B_H + soff[it], bh + boff[it] + koff, 16u);
            if (TERMS == 3)
                cp_async16(s0 + T_B_L + soff[it], bl + boff[it] + koff, 16u);
        }
        cp_commit();
    };

    load_stage(0, 0);
    for (int kb = 0; kb < nkb; kb++) {
        if (kb + 1 < nkb) { load_stage(kb + 1, (kb + 1) & 1); cp_wait<1>(); }
        else cp_wait<0>();
        __syncthreads();
        uint32_t s0 = sb + (kb & 1) * STAGE;
        #pragma unroll
        for (int ks = 0; ks < 4; ks++) {
            uint32_t afh[4][4], afl[4][4];
            #pragma unroll
            for (int mt = 0; mt < 4; mt++) {
                int row = wm * 64 + mt * 16 + (lane & 15);
                uint32_t so = sw128((uint32_t)(row * 128 + ks * 32 + (lane >> 4) * 16));
                ldsm4(afh[mt], s0 + T_A_H + so);
                if (TERMS == 3) ldsm4(afl[mt], s0 + T_A_L + so);
            }
            uint32_t bfh[4][2], bfl[4][2];
            #pragma unroll
            for (int n2 = 0; n2 < 2; n2++) {
                int row = wn * 32 + n2 * 16 + (lane & 15);
                uint32_t so = sw128((uint32_t)(row * 128 + ks * 32 + (lane >> 4) * 16));
                uint32_t t4[4];
                ldsm4(t4, s0 + T_B_H + so);
                bfh[n2 * 2][0] = t4[0]; bfh[n2 * 2][1] = t4[2];
                bfh[n2 * 2 + 1][0] = t4[1]; bfh[n2 * 2 + 1][1] = t4[3];
                if (TERMS == 3) {
                    ldsm4(t4, s0 + T_B_L + so);
                    bfl[n2 * 2][0] = t4[0]; bfl[n2 * 2][1] = t4[2];
                    bfl[n2 * 2 + 1][0] = t4[1]; bfl[n2 * 2 + 1][1] = t4[3];
                }
            }
            #pragma unroll
            for (int mt = 0; mt < 4; mt++)
                #pragma unroll
                for (int nt = 0; nt < 4; nt++) {
                    float* d = acc[mt * 4 + nt];
                    mma_f16(d, afh[mt], bfh[nt]);
                    if (TERMS == 3) {
                        mma_f16(d, afl[mt], bfh[nt]);
                        mma_f16(d, afh[mt], bfl[nt]);
                    }
                }
        }
        __syncthreads();
    }
}

// acc[mt*4+nt][r] maps to:
//   row = wm*64 + mt*16 + lane/4 + 8*(r>>1)
//   col = wn*32 + nt*8  + 2*(lane&3) + (r&1)

#define SMEM_T3 131072
#define SMEM_T1 65536

// ---------------- qkv = xn1 @ w_qkv (3-term) ----------------
__global__ void __launch_bounds__(256) qkv_gemm() {
    extern __shared__ char smem[];
    uint32_t sb = smem_u32(smem);
    float acc[16][4];
    #pragma unroll
    for (int i = 0; i < 16; i++)
        #pragma unroll
        for (int j = 0; j < 4; j++) acc[i][j] = 0.f;
    int m0 = blockIdx.y * 128, n0 = blockIdx.x * 128;
    gemm_pipe<3>(sb, acc, g_xn1_h, g_xn1_l, g_wqkvt_h, g_wqkvt_l,
                 DM, nullptr, m0, 128, n0);
    int lane = threadIdx.x & 31, wid = threadIdx.x >> 5;
    int wm = wid >> 2, wn = wid & 3;
    #pragma unroll
    for (int mt = 0; mt < 4; mt++)
        #pragma unroll
        for (int nt = 0; nt < 4; nt++) {
            int r = m0 + wm * 64 + mt * 16 + (lane >> 2);
            int c = n0 + wn * 32 + nt * 8 + 2 * (lane & 3);
            float* d = acc[mt * 4 + nt];
            float* p0 = g_qkv + (size_t)r * (3 * DM) + c;
            p0[0] = d[0]; p0[1] = d[1];
            float* p1 = g_qkv + (size_t)(r + 8) * (3 * DM) + c;
            p1[0] = d[2]; p1[1] = d[3];
        }
}

// ---------------- x2 = attn @ w_proj + b_proj + x (3-term) ----------------
__global__ void __launch_bounds__(256) proj_gemm(
    const float* __restrict__ bias, const float* __restrict__ resid)
{
    extern __shared__ char smem[];
    uint32_t sb = smem_u32(smem);
    float acc[16][4];
    #pragma unroll
    for (int i = 0; i < 16; i++)
        #pragma unroll
        for (int j = 0; j < 4; j++) acc[i][j] = 0.f;
    int m0 = blockIdx.y * 128, n0 = blockIdx.x * 128;
    gemm_pipe<3>(sb, acc, g_attn_h, g_attn_l, g_wprojt_h, g_wprojt_l,
                 DM, nullptr, m0, 128, n0);
    int lane = threadIdx.x & 31, wid = threadIdx.x >> 5;
    int wm = wid >> 2, wn = wid & 3;
    #pragma unroll
    for (int mt = 0; mt < 4; mt++)
        #pragma unroll
        for (int nt = 0; nt < 4; nt++) {
            int r = m0 + wm * 64 + mt * 16 + (lane >> 2);
            int c = n0 + wn * 32 + nt * 8 + 2 * (lane & 3);
            float* d = acc[mt * 4 + nt];
            size_t p0 = (size_t)r * DM + c;
            size_t p1 = (size_t)(r + 8) * DM + c;
            g_x2[p0]     = d[0] + bias[c]     + resid[p0];
            g_x2[p0 + 1] = d[1] + bias[c + 1] + resid[p0 + 1];
            g_x2[p1]     = d[2] + bias[c]     + resid[p1];
            g_x2[p1 + 1] = d[3] + bias[c + 1] + resid[p1 + 1];
        }
}

// ---------------- h = gelu(gather(xn2) @ w1[e] + b1[e]) (1-term) -------------
__global__ void __launch_bounds__(256) ffn1_gemm(const float* __restrict__ B1) {
    int e = blockIdx.z;
    int cnt = g_cnt[e];
    int r0 = blockIdx.y * 128;
    if (r0 >= cnt) return;
    extern __shared__ char smem[];
    uint32_t sb = smem_u32(smem);
    float acc[16][4];
    #pragma unroll
    for (int i = 0; i < 16; i++)
        #pragma unroll
        for (int j = 0; j < 4; j++) acc[i][j] = 0.f;
    int off = g_off[e];
    int n0 = blockIdx.x * 128;
    int valid = cnt - r0; if (valid > 128) valid = 128;
    gemm_pipe<1>(sb, acc, g_xn2_h, nullptr,
                 g_w1t + (size_t)e * DFF * DM, nullptr,
                 DM, g_perm_tok, off + r0, valid, n0);
    int lane = threadIdx.x & 31, wid = threadIdx.x >> 5;
    int wm = wid >> 2, wn = wid & 3;
    const float* bias = B1 + e * DFF;
    #pragma unroll
    for (int mt = 0; mt < 4; mt++)
        #pragma unroll
        for (int nt = 0; nt < 4; nt++) {
            int rl = wm * 64 + mt * 16 + (lane >> 2);
            int c = n0 + wn * 32 + nt * 8 + 2 * (lane & 3);
            float* d = acc[mt * 4 + nt];
            #pragma unroll
            for (int half = 0; half < 2; half++) {
                int row = rl + half * 8;
                if (row >= valid) continue;
                size_t rp = (size_t)(off + r0 + row) * DFF + c;
                #pragma unroll
                for (int u = 0; u < 2; u++) {
                    float v = d[half * 2 + u] + bias[c + u];
                    v = 0.5f * v * (1.0f + erff(v * 0.70710678118654752f));
                    g_hbuf[rp + u] = __float2half_rn(v);
                }
            }
        }
}

// ---------------- y = h @ w2[e] + b2[e] (1-term) ----------------
__global__ void __launch_bounds__(256) ffn2_gemm(const float* __restrict__ B2) {
    int e = blockIdx.z;
    int cnt = g_cnt[e];
    int r0 = blockIdx.y * 128;
    if (r0 >= cnt) return;
    extern __shared__ char smem[];
    uint32_t sb = smem_u32(smem);
    float acc[16][4];
    #pragma unroll
    for (int i = 0; i < 16; i++)
        #pragma unroll
        for (int j = 0; j < 4; j++) acc[i][j] = 0.f;
    int off = g_off[e];
    int n0 = blockIdx.x * 128;
    int valid = cnt - r0; if (valid > 128) valid = 128;
    gemm_pipe<1>(sb, acc, g_hbuf, nullptr,
                 g_w2t + (size_t)e * DM * DFF, nullptr,
                 DFF, nullptr, off + r0, valid, n0);
    int lane = threadIdx.x & 31, wid = threadIdx.x >> 5;
    int wm = wid >> 2, wn = wid & 3;
    const float* bias = B2 + e * DM;
    #pragma unroll
    for (int mt = 0; mt < 4; mt++)
        #pragma unroll
        for (int nt = 0; nt < 4; nt++) {
            int rl = wm * 64 + mt * 16 + (lane >> 2);
            int c = n0 + wn * 32 + nt * 8 + 2 * (lane & 3);
            float* d = acc[mt * 4 + nt];
            #pragma unroll
            for (int half = 0; half < 2; half++) {
                int row = rl + half * 8;
                if (row >= valid) continue;
                size_t rp = (size_t)(off + r0 + row) * DM + c;
                g_y[rp]     = d[half * 2]     + bias[c];
                g_y[rp + 1] = d[half * 2 + 1] + bias[c + 1];
            }
        }
}

// ---------------- router ----------------
__global__ void __launch_bounds__(128) router_kernel(
    const float* __restrict__ xn2, const float* __restrict__ wr)
{
    int tok = blockIdx.x, tid = threadIdx.x;
    const float* xr = xn2 + (size_t)tok * DM;
    float p[NE];
    #pragma unroll
    for (int e = 0; e < NE; e++) p[e] = 0.f;
    for (int i = tid; i < DM; i += 128) {
        float xv = xr[i];
        const float* w = wr + i * NE;
        #pragma unroll
        for (int e = 0; e < NE; e++) p[e] += xv * w[e];
    }
    __shared__ float red[NE][128];
    #pragma unroll
    for (int e = 0; e < NE; e++) red[e][tid] = p[e];
    __syncthreads();
    for (int st = 64; st > 0; st >>= 1) {
        if (tid < st) {
            #pragma unroll
            for (int e = 0; e < NE; e++) red[e][tid] += red[e][tid + st];
        }
        __syncthreads();
    }
    if (tid == 0) {
        float lg[NE], mx = -1e30f;
        #pragma unroll
        for (int e = 0; e < NE; e++) { lg[e] = red[e][0]; mx = fmaxf(mx, lg[e]); }
        float se = 0.f, pr[NE];
        #pragma unroll
        for (int e = 0; e < NE; e++) { pr[e] = __expf(lg[e] - mx); se += pr[e]; }
        float inv = 1.0f / se;
        #pragma unroll
        for (int e = 0; e < NE; e++) {
            pr[e] *= inv;
            atomicAdd(&g_probsum[e], pr[e]);
        }
        int i0 = 0;
        #pragma unroll
        for (int e = 1; e < NE; e++) if (pr[e] > pr[i0]) i0 = e;
        int i1 = (i0 == 0) ? 1 : 0;
        #pragma unroll
        for (int e = 0; e < NE; e++) if (e != i0 && pr[e] > pr[i1]) i1 = e;
        float w0 = pr[i0], w1 = pr[i1], sw = 1.0f / (w0 + w1);
        g_top_i[tok * 2] = i0; g_top_i[tok * 2 + 1] = i1;
        g_top_w[tok * 2] = w0 * sw; g_top_w[tok * 2 + 1] = w1 * sw;
        atomicAdd(&g_cnt[i0], 1);
        atomicAdd(&g_cnt[i1], 1);
    }
}

__global__ void scan_kernel() {
    if (threadIdx.x == 0 && blockIdx.x == 0) {
        int o = 0;
        float aux = 0.f;
        for (int e = 0; e < NE; e++) { g_off[e] = o; o += g_cnt[e]; }
        for (int e = 0; e < NE; e++)
            aux += ((float)g_cnt[e] / (float)(NTOK * 2)) * (g_probsum[e] / (float)NTOK);
        g_aux = (float)NE * aux;
    }
}

__global__ void place_kernel() {
    int s = blockIdx.x * 256 + threadIdx.x;
    if (s >= NSLOT) return;
    int tok = s >> 1;
    int e = g_top_i[s];
    float w = g_top_w[s];
    int pos = atomicAdd(&g_cur[e], 1);
    int slot = g_off[e] + pos;
    g_perm_tok[slot] = tok;
    g_slot_gate[slot] = w;
    g_slot_of[s] = slot;
}

// ---------------- final combine ----------------
__global__ void __launch_bounds__(256) combine_kernel(float* __restrict__ out, int out_size)
{
    int tok = blockIdx.x;
    int s0 = g_slot_of[tok * 2], s1 = g_slot_of[tok * 2 + 1];
    float w0 = g_slot_gate[s0], w1 = g_slot_gate[s1];
    const float* y0 = g_y + (size_t)s0 * DM;
    const float* y1 = g_y + (size_t)s1 * DM;
    const float* xr = g_x2 + (size_t)tok * DM;
    float* orow = out + (size_t)tok * DM;
    #pragma unroll
    for (int l = 0; l < 4; l++) {
        int i = threadIdx.x + l * 256;
        orow[i] = xr[i] + w0 * y0[i] + w1 * y1[i];
    }
    if (tok == 0 && threadIdx.x == 0 && out_size > NTOK * DM)
        out[NTOK * DM] = g_aux;
}

// ===================== launch =====================
extern "C" void kernel_launch(void* const* d_in, const int* in_sizes, int n_in,
                              void* d_out, int out_size)
{
    const float* x        = (const float*)d_in[0];
    const float* ln1_g    = (const float*)d_in[2];
    const float* ln1_b    = (const float*)d_in[3];
    const float* w_qkv    = (const float*)d_in[4];
    const float* w_proj   = (const float*)d_in[5];
    const float* b_proj   = (const float*)d_in[6];
    const float* ln2_g    = (const float*)d_in[7];
    const float* ln2_b    = (const float*)d_in[8];
    const float* w_router = (const float*)d_in[9];
    const float* w1       = (const float*)d_in[10];
    const float* b1       = (const float*)d_in[11];
    const float* w2       = (const float*)d_in[12];
    const float* b2       = (const float*)d_in[13];
    float* out = (float*)d_out;

    static bool attr_done = false;
    if (!attr_done) {
        cudaFuncSetAttribute(qkv_gemm,  cudaFuncAttributeMaxDynamicSharedMemorySize, SMEM_T3);
        cudaFuncSetAttribute(proj_gemm, cudaFuncAttributeMaxDynamicSharedMemorySize, SMEM_T3);
        cudaFuncSetAttribute(ffn1_gemm, cudaFuncAttributeMaxDynamicSharedMemorySize, SMEM_T1);
        cudaFuncSetAttribute(ffn2_gemm, cudaFuncAttributeMaxDynamicSharedMemorySize, SMEM_T1);
        attr_done = true;
    }

    float *p_qkv, *p_q, *p_k, *p_v, *p_x2, *p_xn2;
    h16 *p_xn1_h, *p_xn1_l, *p_attn_h, *p_attn_l, *p_xn2_h;
    h16 *p_wqkvt_h, *p_wqkvt_l, *p_wprojt_h, *p_wprojt_l, *p_w1t, *p_w2t;
    cudaGetSymbolAddress((void**)&p_qkv,  g_qkv);
    cudaGetSymbolAddress((void**)&p_q,    g_q);
    cudaGetSymbolAddress((void**)&p_k,    g_k);
    cudaGetSymbolAddress((void**)&p_v,    g_v);
    cudaGetSymbolAddress((void**)&p_x2,   g_x2);
    cudaGetSymbolAddress((void**)&p_xn2,  g_xn2);
    cudaGetSymbolAddress((void**)&p_xn1_h, g_xn1_h);
    cudaGetSymbolAddress((void**)&p_xn1_l, g_xn1_l);
    cudaGetSymbolAddress((void**)&p_attn_h, g_attn_h);
    cudaGetSymbolAddress((void**)&p_attn_l, g_attn_l);
    cudaGetSymbolAddress((void**)&p_xn2_h, g_xn2_h);
    cudaGetSymbolAddress((void**)&p_wqkvt_h, g_wqkvt_h);
    cudaGetSymbolAddress((void**)&p_wqkvt_l, g_wqkvt_l);
    cudaGetSymbolAddress((void**)&p_wprojt_h, g_wprojt_h);
    cudaGetSymbolAddress((void**)&p_wprojt_l, g_wprojt_l);
    cudaGetSymbolAddress((void**)&p_w1t, g_w1t);
    cudaGetSymbolAddress((void**)&p_w2t, g_w2t);

    zero_small_kernel<<<1, 32>>>();

    // weight transpose + conversion (hi/lo only where needed)
    trans_conv<<<dim3(3 * DM / 32, DM / 32, 1), 256>>>(w_qkv, p_wqkvt_h, p_wqkvt_l, DM, 3 * DM);
    trans_conv<<<dim3(DM / 32, DM / 32, 1), 256>>>(w_proj, p_wprojt_h, p_wprojt_l, DM, DM);
    trans_conv<<<dim3(DFF / 32, DM / 32, NE), 256>>>(w1, p_w1t, nullptr, DM, DFF);
    trans_conv<<<dim3(DM / 32, DFF / 32, NE), 256>>>(w2, p_w2t, nullptr, DFF, DM);

    // ln1 -> hi/lo
    ln_kernel<<<NTOK, 256>>>(x, ln1_g, ln1_b, nullptr, p_xn1_h, p_xn1_l);
    // qkv gemm (3-term, pipelined)
    qkv_gemm<<<dim3(3 * DM / 128, NTOK / 128), 256, SMEM_T3>>>();
    // rope
    rope_kernel<<<NTOK, 256>>>(p_qkv, p_q, p_k, p_v);
    // attention -> hi/lo
    attn_kernel<<<NBH * TT / 8, 256>>>(p_q, p_k, p_v, p_attn_h, p_attn_l);
    // proj gemm + residual (3-term)
    proj_gemm<<<dim3(DM / 128, NTOK / 128), 256, SMEM_T3>>>(b_proj, x);
    // ln2 -> fp32 + hi
    ln_kernel<<<NTOK, 256>>>(p_x2, ln2_g, ln2_b, p_xn2, p_xn2_h, nullptr);
    // router + placement
    router_kernel<<<NTOK, 128>>>(p_xn2, w_router);
    scan_kernel<<<1, 1>>>();
    place_kernel<<<NSLOT / 256, 256>>>();
    // grouped expert FFN (1-term fp16, pipelined)
    ffn1_gemm<<<dim3(DFF / 128, NSLOT / 128, NE), 256, SMEM_T1>>>(b1);
    ffn2_gemm<<<dim3(DM / 128, NSLOT / 128, NE), 256, SMEM_T1>>>(b2);
    // combine
    combine_kernel<<<NTOK, 256>>>(out, out_size);
}

// round 5
// speedup vs baseline: 3.8700x; 2.8959x over previous
#include <cuda_runtime.h>
#include <cuda_fp16.h>
#include <math.h>
#include <stdint.h>

#define NTOK 4096      // B*T
#define DM   1024
#define NH   16
#define HD   64
#define NE   8
#define DFF  4096
#define NSLOT 8192     // NTOK * TOP_K
#define TT   1024
#define NBH  64        // B * NH

typedef __half h16;

// ===================== scratch (static device memory) ========================
__device__ h16   g_xn1_h [NTOK * DM];
__device__ h16   g_xn1_l [NTOK * DM];
__device__ float g_qkv   [NTOK * 3 * DM];
__device__ float g_q     [NTOK * DM];   // [B,H,T,HD]
__device__ float g_k     [NTOK * DM];
__device__ float g_v     [NTOK * DM];
__device__ h16   g_attn_h[NTOK * DM];
__device__ h16   g_attn_l[NTOK * DM];
__device__ float g_x2    [NTOK * DM];
__device__ float g_xn2   [NTOK * DM];
__device__ h16   g_xn2_h [NTOK * DM];
__device__ h16   g_hbuf  [(size_t)NSLOT * DFF];
__device__ float g_y     [NSLOT * DM];

// transposed weights ([N,K] K-major per expert)
__device__ h16 g_wqkvt_h[3 * DM * DM];
__device__ h16 g_wqkvt_l[3 * DM * DM];
__device__ h16 g_wprojt_h[DM * DM];
__device__ h16 g_wprojt_l[DM * DM];
__device__ h16 g_w1t[(size_t)NE * DFF * DM];
__device__ h16 g_w2t[(size_t)NE * DM * DFF];

__device__ int   g_cnt[NE];
__device__ int   g_off[NE];
__device__ int   g_cur[NE];
__device__ float g_probsum[NE];
__device__ int   g_top_i[NSLOT];
__device__ float g_top_w[NSLOT];
__device__ int   g_perm_tok[NSLOT];
__device__ float g_slot_gate[NSLOT];
__device__ int   g_slot_of[NSLOT];
__device__ float g_aux;

__device__ __forceinline__ void split_store(float v, h16* h, h16* l) {
    h16 hi = __float2half_rn(v);
    *h = hi;
    *l = __float2half_rn(v - __half2float(hi));
}

__device__ __forceinline__ uint32_t smem_u32(const void* p) {
    uint32_t a;
    asm("{ .reg .u64 t; cvta.to.shared.u64 t, %1; cvt.u32.u64 %0, t; }"
        : "=r"(a) : "l"(p));
    return a;
}
__device__ __forceinline__ void ldsm4(uint32_t* r, uint32_t addr) {
    asm volatile("ldmatrix.sync.aligned.m8n8.x4.shared.b16 {%0,%1,%2,%3}, [%4];"
                 : "=r"(r[0]), "=r"(r[1]), "=r"(r[2]), "=r"(r[3]) : "r"(addr));
}
__device__ __forceinline__ void mma_f16(float* d, const uint32_t* a, const uint32_t* b) {
    asm volatile(
        "mma.sync.aligned.m16n8k16.row.col.f32.f16.f16.f32 "
        "{%0,%1,%2,%3}, {%4,%5,%6,%7}, {%8,%9}, {%0,%1,%2,%3};"
        : "+f"(d[0]), "+f"(d[1]), "+f"(d[2]), "+f"(d[3])
        : "r"(a[0]), "r"(a[1]), "r"(a[2]), "r"(a[3]), "r"(b[0]), "r"(b[1]));
}
__device__ __forceinline__ void cp_async16(uint32_t saddr, const void* g, uint32_t sz) {
    asm volatile("cp.async.cg.shared.global [%0], [%1], 16, %2;"
                 :: "r"(saddr), "l"(g), "r"(sz));
}
__device__ __forceinline__ void cp_commit() {
    asm volatile("cp.async.commit_group;");
}
template<int N> __device__ __forceinline__ void cp_wait() {
    asm volatile("cp.async.wait_group %0;" :: "n"(N));
}
__device__ __forceinline__ uint32_t sw128(uint32_t o) {
    return o ^ ((o >> 3) & 0x70u);
}

// ===================== small helpers ====================
__global__ void zero_small_kernel() {
    int i = threadIdx.x;
    if (i < NE) { g_cnt[i] = 0; g_cur[i] = 0; g_probsum[i] = 0.f; }
}

// ---------------- transpose + convert: w[K,N] -> t[N,K] (lo optional) --------
__global__ void __launch_bounds__(256) trans_conv(
    const float* __restrict__ w, h16* __restrict__ th, h16* __restrict__ tl,
    int K, int N)
{
    const size_t eoff = (size_t)blockIdx.z * K * N;
    const float* wp = w + eoff;
    h16* thp = th + eoff;
    h16* tlp = tl ? tl + eoff : nullptr;
    __shared__ float t[32][33];
    int tx = threadIdx.x & 31, ty = threadIdx.x >> 5;
    int n0 = blockIdx.x * 32, k0 = blockIdx.y * 32;
    #pragma unroll
    for (int i = 0; i < 4; i++)
        t[ty + i * 8][tx] = wp[(size_t)(k0 + ty + i * 8) * N + n0 + tx];
    __syncthreads();
    #pragma unroll
    for (int i = 0; i < 4; i++) {
        float v = t[tx][ty + i * 8];
        int n = n0 + ty + i * 8, k = k0 + tx;
        h16 hi = __float2half_rn(v);
        thp[(size_t)n * K + k] = hi;
        if (tlp) tlp[(size_t)n * K + k] = __float2half_rn(v - __half2float(hi));
    }
}

// ---------------- layernorm (256 thr/row) ----------------
__global__ void __launch_bounds__(256) ln_kernel(
    const float* __restrict__ x, const float* __restrict__ g,
    const float* __restrict__ b, float* __restrict__ o32,
    h16* __restrict__ oh, h16* __restrict__ ol)
{
    int row = blockIdx.x;
    const float* xr = x + (size_t)row * DM;
    float v[4]; float s = 0.f, ss = 0.f;
    #pragma unroll
    for (int i = 0; i < 4; i++) {
        float u = xr[threadIdx.x + i * 256];
        v[i] = u; s += u; ss += u * u;
    }
    #pragma unroll
    for (int ofs = 16; ofs > 0; ofs >>= 1) {
        s  += __shfl_xor_sync(0xffffffffu, s,  ofs);
        ss += __shfl_xor_sync(0xffffffffu, ss, ofs);
    }
    __shared__ float sh[2][8];
    int warp = threadIdx.x >> 5, lane = threadIdx.x & 31;
    if (lane == 0) { sh[0][warp] = s; sh[1][warp] = ss; }
    __syncthreads();
    float S = 0.f, SS = 0.f;
    #pragma unroll
    for (int w = 0; w < 8; w++) { S += sh[0][w]; SS += sh[1][w]; }
    float mu  = S * (1.0f / DM);
    float var = SS * (1.0f / DM) - mu * mu;
    float inv = rsqrtf(var + 1e-5f);
    #pragma unroll
    for (int i = 0; i < 4; i++) {
        int idx = threadIdx.x + i * 256;
        float o = (v[i] - mu) * inv * g[idx] + b[idx];
        size_t p = (size_t)row * DM + idx;
        if (o32) o32[p] = o;
        h16 hi = __float2half_rn(o);
        oh[p] = hi;
        if (ol) ol[p] = __float2half_rn(o - __half2float(hi));
    }
}

// ---------------- RoPE + layout transform ----------------
__global__ void __launch_bounds__(256) rope_kernel(
    const float* __restrict__ qkv, float* __restrict__ q,
    float* __restrict__ k, float* __restrict__ v)
{
    int tok = blockIdx.x;
    int b = tok >> 10, t = tok & 1023;
    const float* row = qkv + (size_t)tok * (3 * DM);
    for (int i = threadIdx.x; i < DM; i += 256) {
        int h = i >> 6, d = i & 63;
        int f = d & 31;
        float freq = powf(10000.0f, -(float)f / 32.0f);
        float ang = (float)t * freq;
        float sv, cv;
        sincosf(ang, &sv, &cv);
        float qa = row[i], ka = row[DM + i];
        float qo, ko;
        if (d < 32) {
            qo = qa * cv - row[i + 32] * sv;
            ko = ka * cv - row[DM + i + 32] * sv;
        } else {
            qo = qa * cv + row[i - 32] * sv;
            ko = ka * cv + row[DM + i - 32] * sv;
        }
        int dst = ((b * NH + h) * TT + t) * HD + d;
        q[dst] = qo;
        k[dst] = ko;
        v[dst] = row[2 * DM + i];
    }
}

// ---------------- tiled causal attention -------------------------------------
// Block: 256 thr = 8 warps, each warp owns 4 query rows; block owns 32 rows of
// one (b,h). K/V staged via smem in 64-j tiles, shared across all 32 rows.
__global__ void __launch_bounds__(256) attn_kernel(
    const float* __restrict__ q, const float* __restrict__ k,
    const float* __restrict__ v, h16* __restrict__ oh, h16* __restrict__ ol)
{
    __shared__ float  ks[64][68];     // K tile, padded (bank = 4j+c)
    __shared__ float2 vs[64][32];     // V tile as (v[d], v[d+32]) pairs
    __shared__ float  qs[32][68];     // q rows, padded
    __shared__ float4 ps[8][32];      // per-warp p broadcast (4 rows packed)

    int bh = blockIdx.x & (NBH - 1);
    int qc = (TT / 32 - 1) - (blockIdx.x >> 6);   // heavy chunks first
    int t0 = qc * 32;
    int tid = threadIdx.x, lane = tid & 31, w = tid >> 5;
    const float* qb = q + (size_t)bh * TT * HD;
    const float* kb = k + (size_t)bh * TT * HD;
    const float* vb = v + (size_t)bh * TT * HD;

    // load 32 q rows
    for (int i = tid; i < 32 * 16; i += 256) {
        int r = i >> 4, c4 = (i & 15) * 4;
        *(float4*)(&qs[r][c4]) = *(const float4*)(qb + (size_t)(t0 + r) * HD + c4);
    }

    const int r0 = w * 4;
    const int tmax = t0 + r0 + 3;
    float mr[4], lr[4], ac0[4], ac1[4];
    #pragma unroll
    for (int rr = 0; rr < 4; rr++) { mr[rr] = -1e30f; lr[rr] = 0.f; ac0[rr] = 0.f; ac1[rr] = 0.f; }

    const int jend = t0 + 31;
    for (int j0 = 0; j0 <= jend; j0 += 64) {
        __syncthreads();
        // cooperative K/V tile load
        for (int i = tid; i < 64 * 16; i += 256) {
            int r = i >> 4, c4 = (i & 15) * 4;
            *(float4*)(&ks[r][c4]) = *(const float4*)(kb + (size_t)(j0 + r) * HD + c4);
        }
        for (int i = tid; i < 64 * 32; i += 256) {
            int r = i >> 5, c = i & 31;
            const float* vr = vb + (size_t)(j0 + r) * HD;
            vs[r][c] = make_float2(vr[c], vr[c + 32]);
        }
        __syncthreads();
        #pragma unroll
        for (int sub = 0; sub < 2; sub++) {
            int jbase = j0 + sub * 32;
            if (jbase > tmax) break;
            int jg = jbase + lane;
            // scores: lane = j, 4 rows
            float s[4] = {0.f, 0.f, 0.f, 0.f};
            #pragma unroll
            for (int c4 = 0; c4 < 64; c4 += 4) {
                float4 kk = *(const float4*)(&ks[sub * 32 + lane][c4]);
                #pragma unroll
                for (int rr = 0; rr < 4; rr++) {
                    float4 qq = *(const float4*)(&qs[r0 + rr][c4]);
                    s[rr] += kk.x * qq.x + kk.y * qq.y + kk.z * qq.z + kk.w * qq.w;
                }
            }
            float pv[4];
            #pragma unroll
            for (int rr = 0; rr < 4; rr++) {
                int t = t0 + r0 + rr;
                bool valid = (jg <= t);
                float sv = s[rr] * 0.125f;
                float sm = valid ? sv : -1e30f;
                float cm = sm;
                #pragma unroll
                for (int o = 16; o > 0; o >>= 1)
                    cm = fmaxf(cm, __shfl_xor_sync(0xffffffffu, cm, o));
                float nm = fmaxf(mr[rr], cm);
                float p = valid ? __expf(sv - nm) : 0.f;
                float sum = p;
                #pragma unroll
                for (int o = 16; o > 0; o >>= 1)
                    sum += __shfl_xor_sync(0xffffffffu, sum, o);
                float sc = __expf(mr[rr] - nm);
                mr[rr] = nm;
                lr[rr] = lr[rr] * sc + sum;
                ac0[rr] *= sc; ac1[rr] *= sc;
                pv[rr] = p;
            }
            ps[w][lane] = make_float4(pv[0], pv[1], pv[2], pv[3]);
            __syncwarp();
            // P @ V: lane = d, broadcast p from smem
            #pragma unroll 8
            for (int j = 0; j < 32; j++) {
                float4 pj = ps[w][j];
                float2 vv = vs[sub * 32 + j][lane];
                ac0[0] += pj.x * vv.x; ac1[0] += pj.x * vv.y;
                ac0[1] += pj.y * vv.x; ac1[1] += pj.y * vv.y;
                ac0[2] += pj.z * vv.x; ac1[2] += pj.z * vv.y;
                ac0[3] += pj.w * vv.x; ac1[3] += pj.w * vv.y;
            }
            __syncwarp();
        }
    }
    // write out (hi/lo fp16)
    int b = bh >> 4, h = bh & 15;
    #pragma unroll
    for (int rr = 0; rr < 4; rr++) {
        int t = t0 + r0 + rr;
        float inv = 1.0f / lr[rr];
        size_t op = ((size_t)(b * TT + t)) * DM + h * HD;
        split_store(ac0[rr] * inv, oh + op + lane, ol + op + lane);
        split_store(ac1[rr] * inv, oh + op + lane + 32, ol + op + lane + 32);
    }
}

// ===================== pipelined HMMA GEMM core ==============================
template<int TERMS>
__device__ __forceinline__ void gemm_pipe(
    uint32_t sb, float (*acc)[4],
    const h16* __restrict__ ah, const h16* __restrict__ al,
    const h16* __restrict__ bh, const h16* __restrict__ bl,
    int K, const int* __restrict__ perm, int row_base, int valid, int b_row0)
{
    constexpr uint32_t T_A_H = 0;
    constexpr uint32_t T_A_L = 16384;
    constexpr uint32_t T_B_H = (TERMS == 3) ? 32768u : 16384u;
    constexpr uint32_t T_B_L = 49152;
    constexpr uint32_t STAGE = (TERMS == 3) ? 65536u : 32768u;

    const int tid = threadIdx.x, lane = tid & 31, wid = tid >> 5;
    const int wm = wid >> 2, wn = wid & 3;
    const int nkb = K >> 6;

    size_t aoff[4], boff[4];
    uint32_t soff[4], asz[4];
    int chs[4];
    #pragma unroll
    for (int it = 0; it < 4; it++) {
        int idx = tid + it * 256;
        int row = idx >> 3, ch = idx & 7;
        chs[it] = ch;
        soff[it] = sw128((uint32_t)(row * 128 + ch * 16));
        asz[it] = (row < valid) ? 16u : 0u;
        int gra = (row < valid) ? (perm ? perm[row_base + row] : (row_base + row)) : 0;
        aoff[it] = (size_t)gra * K;
        boff[it] = (size_t)(b_row0 + row) * K;
    }

    auto load_stage = [&](int kb, int buf) {
        uint32_t s0 = sb + buf * STAGE;
        #pragma unroll
        for (int it = 0; it < 4; it++) {
            int koff = kb * 64 + chs[it] * 8;
            cp_async16(s0 + T_A_H + soff[it], ah + aoff[it] + koff, asz[it]);
            if (TERMS == 3)
                cp_async16(s0 + T_A_L + soff[it], al + aoff[it] + koff, asz[it]);
            cp_async16(s0 + T_B_H + soff[it], bh + boff[it] + koff, 16u);
            if (TERMS == 3)
                cp_async16(s0 + T_B_L + soff[it], bl + boff[it] + koff, 16u);
        }
        cp_commit();
    };

    load_stage(0, 0);
    for (int kb = 0; kb < nkb; kb++) {
        if (kb + 1 < nkb) { load_stage(kb + 1, (kb + 1) & 1); cp_wait<1>(); }
        else cp_wait<0>();
        __syncthreads();
        uint32_t s0 = sb + (kb & 1) * STAGE;
        #pragma unroll
        for (int ks = 0; ks < 4; ks++) {
            uint32_t afh[4][4], afl[4][4];
            #pragma unroll
            for (int mt = 0; mt < 4; mt++) {
                int row = wm * 64 + mt * 16 + (lane & 15);
                uint32_t so = sw128((uint32_t)(row * 128 + ks * 32 + (lane >> 4) * 16));
                ldsm4(afh[mt], s0 + T_A_H + so);
                if (TERMS == 3) ldsm4(afl[mt], s0 + T_A_L + so);
            }
            uint32_t bfh[4][2], bfl[4][2];
            #pragma unroll
            for (int n2 = 0; n2 < 2; n2++) {
                int row = wn * 32 + n2 * 16 + (lane & 15);
                uint32_t so = sw128((uint32_t)(row * 128 + ks * 32 + (lane >> 4) * 16));
                uint32_t t4[4];
                ldsm4(t4, s0 + T_B_H + so);
                bfh[n2 * 2][0] = t4[0]; bfh[n2 * 2][1] = t4[2];
                bfh[n2 * 2 + 1][0] = t4[1]; bfh[n2 * 2 + 1][1] = t4[3];
                if (TERMS == 3) {
                    ldsm4(t4, s0 + T_B_L + so);
                    bfl[n2 * 2][0] = t4[0]; bfl[n2 * 2][1] = t4[2];
                    bfl[n2 * 2 + 1][0] = t4[1]; bfl[n2 * 2 + 1][1] = t4[3];
                }
            }
            #pragma unroll
            for (int mt = 0; mt < 4; mt++)
                #pragma unroll
                for (int nt = 0; nt < 4; nt++) {
                    float* d = acc[mt * 4 + nt];
                    mma_f16(d, afh[mt], bfh[nt]);
                    if (TERMS == 3) {
                        mma_f16(d, afl[mt], bfh[nt]);
                        mma_f16(d, afh[mt], bfl[nt]);
                    }
                }
        }
        __syncthreads();
    }
}

#define SMEM_T3 131072
#define SMEM_T1 65536

// ---------------- qkv = xn1 @ w_qkv (3-term) ----------------
__global__ void __launch_bounds__(256) qkv_gemm() {
    extern __shared__ char smem[];
    uint32_t sb = smem_u32(smem);
    float acc[16][4];
    #pragma unroll
    for (int i = 0; i < 16; i++)
        #pragma unroll
        for (int j = 0; j < 4; j++) acc[i][j] = 0.f;
    int m0 = blockIdx.y * 128, n0 = blockIdx.x * 128;
    gemm_pipe<3>(sb, acc, g_xn1_h, g_xn1_l, g_wqkvt_h, g_wqkvt_l,
                 DM, nullptr, m0, 128, n0);
    int lane = threadIdx.x & 31, wid = threadIdx.x >> 5;
    int wm = wid >> 2, wn = wid & 3;
    #pragma unroll
    for (int mt = 0; mt < 4; mt++)
        #pragma unroll
        for (int nt = 0; nt < 4; nt++) {
            int r = m0 + wm * 64 + mt * 16 + (lane >> 2);
            int c = n0 + wn * 32 + nt * 8 + 2 * (lane & 3);
            float* d = acc[mt * 4 + nt];
            float* p0 = g_qkv + (size_t)r * (3 * DM) + c;
            p0[0] = d[0]; p0[1] = d[1];
            float* p1 = g_qkv + (size_t)(r + 8) * (3 * DM) + c;
            p1[0] = d[2]; p1[1] = d[3];
        }
}

// ---------------- x2 = attn @ w_proj + b_proj + x (3-term) ----------------
__global__ void __launch_bounds__(256) proj_gemm(
    const float* __restrict__ bias, const float* __restrict__ resid)
{
    extern __shared__ char smem[];
    uint32_t sb = smem_u32(smem);
    float acc[16][4];
    #pragma unroll
    for (int i = 0; i < 16; i++)
        #pragma unroll
        for (int j = 0; j < 4; j++) acc[i][j] = 0.f;
    int m0 = blockIdx.y * 128, n0 = blockIdx.x * 128;
    gemm_pipe<3>(sb, acc, g_attn_h, g_attn_l, g_wprojt_h, g_wprojt_l,
                 DM, nullptr, m0, 128, n0);
    int lane = threadIdx.x & 31, wid = threadIdx.x >> 5;
    int wm = wid >> 2, wn = wid & 3;
    #pragma unroll
    for (int mt = 0; mt < 4; mt++)
        #pragma unroll
        for (int nt = 0; nt < 4; nt++) {
            int r = m0 + wm * 64 + mt * 16 + (lane >> 2);
            int c = n0 + wn * 32 + nt * 8 + 2 * (lane & 3);
            float* d = acc[mt * 4 + nt];
            size_t p0 = (size_t)r * DM + c;
            size_t p1 = (size_t)(r + 8) * DM + c;
            g_x2[p0]     = d[0] + bias[c]     + resid[p0];
            g_x2[p0 + 1] = d[1] + bias[c + 1] + resid[p0 + 1];
            g_x2[p1]     = d[2] + bias[c]     + resid[p1];
            g_x2[p1 + 1] = d[3] + bias[c + 1] + resid[p1 + 1];
        }
}

// ---------------- h = gelu(gather(xn2) @ w1[e] + b1[e]) (1-term) -------------
__global__ void __launch_bounds__(256) ffn1_gemm(const float* __restrict__ B1) {
    int e = blockIdx.z;
    int cnt = g_cnt[e];
    int r0 = blockIdx.y * 128;
    if (r0 >= cnt) return;
    extern __shared__ char smem[];
    uint32_t sb = smem_u32(smem);
    float acc[16][4];
    #pragma unroll
    for (int i = 0; i < 16; i++)
        #pragma unroll
        for (int j = 0; j < 4; j++) acc[i][j] = 0.f;
    int off = g_off[e];
    int n0 = blockIdx.x * 128;
    int valid = cnt - r0; if (valid > 128) valid = 128;
    gemm_pipe<1>(sb, acc, g_xn2_h, nullptr,
                 g_w1t + (size_t)e * DFF * DM, nullptr,
                 DM, g_perm_tok, off + r0, valid, n0);
    int lane = threadIdx.x & 31, wid = threadIdx.x >> 5;
    int wm = wid >> 2, wn = wid & 3;
    const float* bias = B1 + e * DFF;
    #pragma unroll
    for (int mt = 0; mt < 4; mt++)
        #pragma unroll
        for (int nt = 0; nt < 4; nt++) {
            int rl = wm * 64 + mt * 16 + (lane >> 2);
            int c = n0 + wn * 32 + nt * 8 + 2 * (lane & 3);
            float* d = acc[mt * 4 + nt];
            #pragma unroll
            for (int half = 0; half < 2; half++) {
                int row = rl + half * 8;
                if (row >= valid) continue;
                size_t rp = (size_t)(off + r0 + row) * DFF + c;
                #pragma unroll
                for (int u = 0; u < 2; u++) {
                    float v = d[half * 2 + u] + bias[c + u];
                    v = 0.5f * v * (1.0f + erff(v * 0.70710678118654752f));
                    g_hbuf[rp + u] = __float2half_rn(v);
                }
            }
        }
}

// ---------------- y = h @ w2[e] + b2[e] (1-term) ----------------
__global__ void __launch_bounds__(256) ffn2_gemm(const float* __restrict__ B2) {
    int e = blockIdx.z;
    int cnt = g_cnt[e];
    int r0 = blockIdx.y * 128;
    if (r0 >= cnt) return;
    extern __shared__ char smem[];
    uint32_t sb = smem_u32(smem);
    float acc[16][4];
    #pragma unroll
    for (int i = 0; i < 16; i++)
        #pragma unroll
        for (int j = 0; j < 4; j++) acc[i][j] = 0.f;
    int off = g_off[e];
    int n0 = blockIdx.x * 128;
    int valid = cnt - r0; if (valid > 128) valid = 128;
    gemm_pipe<1>(sb, acc, g_hbuf, nullptr,
                 g_w2t + (size_t)e * DM * DFF, nullptr,
                 DFF, nullptr, off + r0, valid, n0);
    int lane = threadIdx.x & 31, wid = threadIdx.x >> 5;
    int wm = wid >> 2, wn = wid & 3;
    const float* bias = B2 + e * DM;
    #pragma unroll
    for (int mt = 0; mt < 4; mt++)
        #pragma unroll
        for (int nt = 0; nt < 4; nt++) {
            int rl = wm * 64 + mt * 16 + (lane >> 2);
            int c = n0 + wn * 32 + nt * 8 + 2 * (lane & 3);
            float* d = acc[mt * 4 + nt];
            #pragma unroll
            for (int half = 0; half < 2; half++) {
                int row = rl + half * 8;
                if (row >= valid) continue;
                size_t rp = (size_t)(off + r0 + row) * DM + c;
                g_y[rp]     = d[half * 2]     + bias[c];
                g_y[rp + 1] = d[half * 2 + 1] + bias[c + 1];
            }
        }
}

// ---------------- router ----------------
__global__ void __launch_bounds__(128) router_kernel(
    const float* __restrict__ xn2, const float* __restrict__ wr)
{
    int tok = blockIdx.x, tid = threadIdx.x;
    const float* xr = xn2 + (size_t)tok * DM;
    float p[NE];
    #pragma unroll
    for (int e = 0; e < NE; e++) p[e] = 0.f;
    for (int i = tid; i < DM; i += 128) {
        float xv = xr[i];
        const float* w = wr + i * NE;
        #pragma unroll
        for (int e = 0; e < NE; e++) p[e] += xv * w[e];
    }
    __shared__ float red[NE][128];
    #pragma unroll
    for (int e = 0; e < NE; e++) red[e][tid] = p[e];
    __syncthreads();
    for (int st = 64; st > 0; st >>= 1) {
        if (tid < st) {
            #pragma unroll
            for (int e = 0; e < NE; e++) red[e][tid] += red[e][tid + st];
        }
        __syncthreads();
    }
    if (tid == 0) {
        float lg[NE], mx = -1e30f;
        #pragma unroll
        for (int e = 0; e < NE; e++) { lg[e] = red[e][0]; mx = fmaxf(mx, lg[e]); }
        float se = 0.f, pr[NE];
        #pragma unroll
        for (int e = 0; e < NE; e++) { pr[e] = __expf(lg[e] - mx); se += pr[e]; }
        float inv = 1.0f / se;
        #pragma unroll
        for (int e = 0; e < NE; e++) {
            pr[e] *= inv;
            atomicAdd(&g_probsum[e], pr[e]);
        }
        int i0 = 0;
        #pragma unroll
        for (int e = 1; e < NE; e++) if (pr[e] > pr[i0]) i0 = e;
        int i1 = (i0 == 0) ? 1 : 0;
        #pragma unroll
        for (int e = 0; e < NE; e++) if (e != i0 && pr[e] > pr[i1]) i1 = e;
        float w0 = pr[i0], w1 = pr[i1], sw = 1.0f / (w0 + w1);
        g_top_i[tok * 2] = i0; g_top_i[tok * 2 + 1] = i1;
        g_top_w[tok * 2] = w0 * sw; g_top_w[tok * 2 + 1] = w1 * sw;
        atomicAdd(&g_cnt[i0], 1);
        atomicAdd(&g_cnt[i1], 1);
    }
}

__global__ void scan_kernel() {
    if (threadIdx.x == 0 && blockIdx.x == 0) {
        int o = 0;
        float aux = 0.f;
        for (int e = 0; e < NE; e++) { g_off[e] = o; o += g_cnt[e]; }
        for (int e = 0; e < NE; e++)
            aux += ((float)g_cnt[e] / (float)(NTOK * 2)) * (g_probsum[e] / (float)NTOK);
        g_aux = (float)NE * aux;
    }
}

__global__ void place_kernel() {
    int s = blockIdx.x * 256 + threadIdx.x;
    if (s >= NSLOT) return;
    int tok = s >> 1;
    int e = g_top_i[s];
    float w = g_top_w[s];
    int pos = atomicAdd(&g_cur[e], 1);
    int slot = g_off[e] + pos;
    g_perm_tok[slot] = tok;
    g_slot_gate[slot] = w;
    g_slot_of[s] = slot;
}

// ---------------- final combine ----------------
__global__ void __launch_bounds__(256) combine_kernel(float* __restrict__ out, int out_size)
{
    int tok = blockIdx.x;
    int s0 = g_slot_of[tok * 2], s1 = g_slot_of[tok * 2 + 1];
    float w0 = g_slot_gate[s0], w1 = g_slot_gate[s1];
    const float* y0 = g_y + (size_t)s0 * DM;
    const float* y1 = g_y + (size_t)s1 * DM;
    const float* xr = g_x2 + (size_t)tok * DM;
    float* orow = out + (size_t)tok * DM;
    #pragma unroll
    for (int l = 0; l < 4; l++) {
        int i = threadIdx.x + l * 256;
        orow[i] = xr[i] + w0 * y0[i] + w1 * y1[i];
    }
    if (tok == 0 && threadIdx.x == 0 && out_size > NTOK * DM)
        out[NTOK * DM] = g_aux;
}

// ===================== launch =====================
extern "C" void kernel_launch(void* const* d_in, const int* in_sizes, int n_in,
                              void* d_out, int out_size)
{
    const float* x        = (const float*)d_in[0];
    const float* ln1_g    = (const float*)d_in[2];
    const float* ln1_b    = (const float*)d_in[3];
    const float* w_qkv    = (const float*)d_in[4];
    const float* w_proj   = (const float*)d_in[5];
    const float* b_proj   = (const float*)d_in[6];
    const float* ln2_g    = (const float*)d_in[7];
    const float* ln2_b    = (const float*)d_in[8];
    const float* w_router = (const float*)d_in[9];
    const float* w1       = (const float*)d_in[10];
    const float* b1       = (const float*)d_in[11];
    const float* w2       = (const float*)d_in[12];
    const float* b2       = (const float*)d_in[13];
    float* out = (float*)d_out;

    static bool attr_done = false;
    if (!attr_done) {
        cudaFuncSetAttribute(qkv_gemm,  cudaFuncAttributeMaxDynamicSharedMemorySize, SMEM_T3);
        cudaFuncSetAttribute(proj_gemm, cudaFuncAttributeMaxDynamicSharedMemorySize, SMEM_T3);
        cudaFuncSetAttribute(ffn1_gemm, cudaFuncAttributeMaxDynamicSharedMemorySize, SMEM_T1);
        cudaFuncSetAttribute(ffn2_gemm, cudaFuncAttributeMaxDynamicSharedMemorySize, SMEM_T1);
        attr_done = true;
    }

    float *p_qkv, *p_q, *p_k, *p_v, *p_x2, *p_xn2;
    h16 *p_xn1_h, *p_xn1_l, *p_attn_h, *p_attn_l, *p_xn2_h;
    h16 *p_wqkvt_h, *p_wqkvt_l, *p_wprojt_h, *p_wprojt_l, *p_w1t, *p_w2t;
    cudaGetSymbolAddress((void**)&p_qkv,  g_qkv);
    cudaGetSymbolAddress((void**)&p_q,    g_q);
    cudaGetSymbolAddress((void**)&p_k,    g_k);
    cudaGetSymbolAddress((void**)&p_v,    g_v);
    cudaGetSymbolAddress((void**)&p_x2,   g_x2);
    cudaGetSymbolAddress((void**)&p_xn2,  g_xn2);
    cudaGetSymbolAddress((void**)&p_xn1_h, g_xn1_h);
    cudaGetSymbolAddress((void**)&p_xn1_l, g_xn1_l);
    cudaGetSymbolAddress((void**)&p_attn_h, g_attn_h);
    cudaGetSymbolAddress((void**)&p_attn_l, g_attn_l);
    cudaGetSymbolAddress((void**)&p_xn2_h, g_xn2_h);
    cudaGetSymbolAddress((void**)&p_wqkvt_h, g_wqkvt_h);
    cudaGetSymbolAddress((void**)&p_wqkvt_l, g_wqkvt_l);
    cudaGetSymbolAddress((void**)&p_wprojt_h, g_wprojt_h);
    cudaGetSymbolAddress((void**)&p_wprojt_l, g_wprojt_l);
    cudaGetSymbolAddress((void**)&p_w1t, g_w1t);
    cudaGetSymbolAddress((void**)&p_w2t, g_w2t);

    zero_small_kernel<<<1, 32>>>();

    // weight transpose + conversion
    trans_conv<<<dim3(3 * DM / 32, DM / 32, 1), 256>>>(w_qkv, p_wqkvt_h, p_wqkvt_l, DM, 3 * DM);
    trans_conv<<<dim3(DM / 32, DM / 32, 1), 256>>>(w_proj, p_wprojt_h, p_wprojt_l, DM, DM);
    trans_conv<<<dim3(DFF / 32, DM / 32, NE), 256>>>(w1, p_w1t, nullptr, DM, DFF);
    trans_conv<<<dim3(DM / 32, DFF / 32, NE), 256>>>(w2, p_w2t, nullptr, DFF, DM);

    // ln1 -> hi/lo
    ln_kernel<<<NTOK, 256>>>(x, ln1_g, ln1_b, nullptr, p_xn1_h, p_xn1_l);
    // qkv gemm (3-term, pipelined)
    qkv_gemm<<<dim3(3 * DM / 128, NTOK / 128), 256, SMEM_T3>>>();
    // rope
    rope_kernel<<<NTOK, 256>>>(p_qkv, p_q, p_k, p_v);
    // tiled attention -> hi/lo
    attn_kernel<<<NBH * (TT / 32), 256>>>(p_q, p_k, p_v, p_attn_h, p_attn_l);
    // proj gemm + residual (3-term)
    proj_gemm<<<dim3(DM / 128, NTOK / 128), 256, SMEM_T3>>>(b_proj, x);
    // ln2 -> fp32 + hi
    ln_kernel<<<NTOK, 256>>>(p_x2, ln2_g, ln2_b, p_xn2, p_xn2_h, nullptr);
    // router + placement
    router_kernel<<<NTOK, 128>>>(p_xn2, w_router);
    scan_kernel<<<1, 1>>>();
    place_kernel<<<NSLOT / 256, 256>>>();
    // grouped expert FFN (1-term fp16, pipelined)
    ffn1_gemm<<<dim3(DFF / 128, NSLOT / 128, NE), 256, SMEM_T1>>>(b1);
    ffn2_gemm<<<dim3(DM / 128, NSLOT / 128, NE), 256, SMEM_T1>>>(b2);
    // combine
    combine_kernel<<<NTOK, 256>>>(out, out_size);
}

// round 6
// speedup vs baseline: 4.5623x; 1.1789x over previous
#include <cuda_runtime.h>
#include <cuda_fp16.h>
#include <math.h>
#include <stdint.h>

#define NTOK 4096      // B*T
#define DM   1024
#define NH   16
#define HD   64
#define NE   8
#define DFF  4096
#define NSLOT 8192     // NTOK * TOP_K
#define TT   1024
#define NBH  64        // B * NH

typedef __half h16;

// ===================== scratch (static device memory) ========================
__device__ h16   g_xn1_h [NTOK * DM];
__device__ h16   g_xn1_l [NTOK * DM];
__device__ float g_qkv   [NTOK * 3 * DM];
__device__ float g_q     [NTOK * DM];   // [B,H,T,HD]
__device__ float g_k     [NTOK * DM];
__device__ float g_v     [NTOK * DM];
__device__ h16   g_attn_h[NTOK * DM];
__device__ float g_x2    [NTOK * DM];
__device__ float g_xn2   [NTOK * DM];
__device__ h16   g_xn2_h [NTOK * DM];
__device__ h16   g_hbuf  [(size_t)NSLOT * DFF];
__device__ float g_y     [NSLOT * DM];

// transposed weights ([N,K] K-major per expert)
__device__ h16 g_wqkvt_h[3 * DM * DM];
__device__ h16 g_wprojt_h[DM * DM];
__device__ h16 g_w1t[(size_t)NE * DFF * DM];
__device__ h16 g_w2t[(size_t)NE * DM * DFF];

__device__ int   g_cnt[NE];
__device__ int   g_off[NE];
__device__ int   g_cur[NE];
__device__ float g_probsum[NE];
__device__ int   g_top_i[NSLOT];
__device__ float g_top_w[NSLOT];
__device__ int   g_perm_tok[NSLOT];
__device__ float g_slot_gate[NSLOT];
__device__ int   g_slot_of[NSLOT];
__device__ float g_aux;

__device__ __forceinline__ uint32_t smem_u32(const void* p) {
    uint32_t a;
    asm("{ .reg .u64 t; cvta.to.shared.u64 t, %1; cvt.u32.u64 %0, t; }"
        : "=r"(a) : "l"(p));
    return a;
}
__device__ __forceinline__ void ldsm4(uint32_t* r, uint32_t addr) {
    asm volatile("ldmatrix.sync.aligned.m8n8.x4.shared.b16 {%0,%1,%2,%3}, [%4];"
                 : "=r"(r[0]), "=r"(r[1]), "=r"(r[2]), "=r"(r[3]) : "r"(addr));
}
__device__ __forceinline__ void mma_f16(float* d, const uint32_t* a, const uint32_t* b) {
    asm volatile(
        "mma.sync.aligned.m16n8k16.row.col.f32.f16.f16.f32 "
        "{%0,%1,%2,%3}, {%4,%5,%6,%7}, {%8,%9}, {%0,%1,%2,%3};"
        : "+f"(d[0]), "+f"(d[1]), "+f"(d[2]), "+f"(d[3])
        : "r"(a[0]), "r"(a[1]), "r"(a[2]), "r"(a[3]), "r"(b[0]), "r"(b[1]));
}
__device__ __forceinline__ void cp_async16(uint32_t saddr, const void* g, uint32_t sz) {
    asm volatile("cp.async.cg.shared.global [%0], [%1], 16, %2;"
                 :: "r"(saddr), "l"(g), "r"(sz));
}
__device__ __forceinline__ void cp_commit() {
    asm volatile("cp.async.commit_group;");
}
template<int N> __device__ __forceinline__ void cp_wait() {
    asm volatile("cp.async.wait_group %0;" :: "n"(N));
}
__device__ __forceinline__ uint32_t sw128(uint32_t o) {
    return o ^ ((o >> 3) & 0x70u);
}

// ===================== small helpers ====================
__global__ void zero_small_kernel() {
    int i = threadIdx.x;
    if (i < NE) { g_cnt[i] = 0; g_cur[i] = 0; g_probsum[i] = 0.f; }
}

// ---------------- transpose + convert: w[K,N] -> t[N,K] (lo optional) --------
__global__ void __launch_bounds__(256) trans_conv(
    const float* __restrict__ w, h16* __restrict__ th, h16* __restrict__ tl,
    int K, int N)
{
    const size_t eoff = (size_t)blockIdx.z * K * N;
    const float* wp = w + eoff;
    h16* thp = th + eoff;
    h16* tlp = tl ? tl + eoff : nullptr;
    __shared__ float t[32][33];
    int tx = threadIdx.x & 31, ty = threadIdx.x >> 5;
    int n0 = blockIdx.x * 32, k0 = blockIdx.y * 32;
    #pragma unroll
    for (int i = 0; i < 4; i++)
        t[ty + i * 8][tx] = wp[(size_t)(k0 + ty + i * 8) * N + n0 + tx];
    __syncthreads();
    #pragma unroll
    for (int i = 0; i < 4; i++) {
        float v = t[tx][ty + i * 8];
        int n = n0 + ty + i * 8, k = k0 + tx;
        h16 hi = __float2half_rn(v);
        thp[(size_t)n * K + k] = hi;
        if (tlp) tlp[(size_t)n * K + k] = __float2half_rn(v - __half2float(hi));
    }
}

// ---------------- layernorm (256 thr/row) ----------------
__global__ void __launch_bounds__(256) ln_kernel(
    const float* __restrict__ x, const float* __restrict__ g,
    const float* __restrict__ b, float* __restrict__ o32,
    h16* __restrict__ oh, h16* __restrict__ ol)
{
    int row = blockIdx.x;
    const float* xr = x + (size_t)row * DM;
    float v[4]; float s = 0.f, ss = 0.f;
    #pragma unroll
    for (int i = 0; i < 4; i++) {
        float u = xr[threadIdx.x + i * 256];
        v[i] = u; s += u; ss += u * u;
    }
    #pragma unroll
    for (int ofs = 16; ofs > 0; ofs >>= 1) {
        s  += __shfl_xor_sync(0xffffffffu, s,  ofs);
        ss += __shfl_xor_sync(0xffffffffu, ss, ofs);
    }
    __shared__ float sh[2][8];
    int warp = threadIdx.x >> 5, lane = threadIdx.x & 31;
    if (lane == 0) { sh[0][warp] = s; sh[1][warp] = ss; }
    __syncthreads();
    float S = 0.f, SS = 0.f;
    #pragma unroll
    for (int w = 0; w < 8; w++) { S += sh[0][w]; SS += sh[1][w]; }
    float mu  = S * (1.0f / DM);
    float var = SS * (1.0f / DM) - mu * mu;
    float inv = rsqrtf(var + 1e-5f);
    #pragma unroll
    for (int i = 0; i < 4; i++) {
        int idx = threadIdx.x + i * 256;
        float o = (v[i] - mu) * inv * g[idx] + b[idx];
        size_t p = (size_t)row * DM + idx;
        if (o32) o32[p] = o;
        h16 hi = __float2half_rn(o);
        oh[p] = hi;
        if (ol) ol[p] = __float2half_rn(o - __half2float(hi));
    }
}

// ---------------- RoPE + layout transform ----------------
__global__ void __launch_bounds__(256) rope_kernel(
    const float* __restrict__ qkv, float* __restrict__ q,
    float* __restrict__ k, float* __restrict__ v)
{
    int tok = blockIdx.x;
    int b = tok >> 10, t = tok & 1023;
    const float* row = qkv + (size_t)tok * (3 * DM);
    for (int i = threadIdx.x; i < DM; i += 256) {
        int h = i >> 6, d = i & 63;
        int f = d & 31;
        float freq = powf(10000.0f, -(float)f / 32.0f);
        float ang = (float)t * freq;
        float sv, cv;
        sincosf(ang, &sv, &cv);
        float qa = row[i], ka = row[DM + i];
        float qo, ko;
        if (d < 32) {
            qo = qa * cv - row[i + 32] * sv;
            ko = ka * cv - row[DM + i + 32] * sv;
        } else {
            qo = qa * cv + row[i - 32] * sv;
            ko = ka * cv + row[DM + i - 32] * sv;
        }
        int dst = ((b * NH + h) * TT + t) * HD + d;
        q[dst] = qo;
        k[dst] = ko;
        v[dst] = row[2 * DM + i];
    }
}

// ---------------- tiled causal attention -------------------------------------
__global__ void __launch_bounds__(256) attn_kernel(
    const float* __restrict__ q, const float* __restrict__ k,
    const float* __restrict__ v, h16* __restrict__ oh)
{
    __shared__ float  ks[64][68];
    __shared__ float2 vs[64][32];
    __shared__ float  qs[32][68];
    __shared__ float4 ps[8][32];

    int bh = blockIdx.x & (NBH - 1);
    int qc = (TT / 32 - 1) - (blockIdx.x >> 6);
    int t0 = qc * 32;
    int tid = threadIdx.x, lane = tid & 31, w = tid >> 5;
    const float* qb = q + (size_t)bh * TT * HD;
    const float* kb = k + (size_t)bh * TT * HD;
    const float* vb = v + (size_t)bh * TT * HD;

    for (int i = tid; i < 32 * 16; i += 256) {
        int r = i >> 4, c4 = (i & 15) * 4;
        *(float4*)(&qs[r][c4]) = *(const float4*)(qb + (size_t)(t0 + r) * HD + c4);
    }

    const int r0 = w * 4;
    const int tmax = t0 + r0 + 3;
    float mr[4], lr[4], ac0[4], ac1[4];
    #pragma unroll
    for (int rr = 0; rr < 4; rr++) { mr[rr] = -1e30f; lr[rr] = 0.f; ac0[rr] = 0.f; ac1[rr] = 0.f; }

    const int jend = t0 + 31;
    for (int j0 = 0; j0 <= jend; j0 += 64) {
        __syncthreads();
        for (int i = tid; i < 64 * 16; i += 256) {
            int r = i >> 4, c4 = (i & 15) * 4;
            *(float4*)(&ks[r][c4]) = *(const float4*)(kb + (size_t)(j0 + r) * HD + c4);
        }
        for (int i = tid; i < 64 * 32; i += 256) {
            int r = i >> 5, c = i & 31;
            const float* vr = vb + (size_t)(j0 + r) * HD;
            vs[r][c] = make_float2(vr[c], vr[c + 32]);
        }
        __syncthreads();
        #pragma unroll
        for (int sub = 0; sub < 2; sub++) {
            int jbase = j0 + sub * 32;
            if (jbase > tmax) break;
            int jg = jbase + lane;
            float s[4] = {0.f, 0.f, 0.f, 0.f};
            #pragma unroll
            for (int c4 = 0; c4 < 64; c4 += 4) {
                float4 kk = *(const float4*)(&ks[sub * 32 + lane][c4]);
                #pragma unroll
                for (int rr = 0; rr < 4; rr++) {
                    float4 qq = *(const float4*)(&qs[r0 + rr][c4]);
                    s[rr] += kk.x * qq.x + kk.y * qq.y + kk.z * qq.z + kk.w * qq.w;
                }
            }
            float pv[4];
            #pragma unroll
            for (int rr = 0; rr < 4; rr++) {
                int t = t0 + r0 + rr;
                bool valid = (jg <= t);
                float sv = s[rr] * 0.125f;
                float sm = valid ? sv : -1e30f;
                float cm = sm;
                #pragma unroll
                for (int o = 16; o > 0; o >>= 1)
                    cm = fmaxf(cm, __shfl_xor_sync(0xffffffffu, cm, o));
                float nm = fmaxf(mr[rr], cm);
                float p = valid ? __expf(sv - nm) : 0.f;
                float sum = p;
                #pragma unroll
                for (int o = 16; o > 0; o >>= 1)
                    sum += __shfl_xor_sync(0xffffffffu, sum, o);
                float sc = __expf(mr[rr] - nm);
                mr[rr] = nm;
                lr[rr] = lr[rr] * sc + sum;
                ac0[rr] *= sc; ac1[rr] *= sc;
                pv[rr] = p;
            }
            ps[w][lane] = make_float4(pv[0], pv[1], pv[2], pv[3]);
            __syncwarp();
            #pragma unroll 8
            for (int j = 0; j < 32; j++) {
                float4 pj = ps[w][j];
                float2 vv = vs[sub * 32 + j][lane];
                ac0[0] += pj.x * vv.x; ac1[0] += pj.x * vv.y;
                ac0[1] += pj.y * vv.x; ac1[1] += pj.y * vv.y;
                ac0[2] += pj.z * vv.x; ac1[2] += pj.z * vv.y;
                ac0[3] += pj.w * vv.x; ac1[3] += pj.w * vv.y;
            }
            __syncwarp();
        }
    }
    int b = bh >> 4, h = bh & 15;
    #pragma unroll
    for (int rr = 0; rr < 4; rr++) {
        int t = t0 + r0 + rr;
        float inv = 1.0f / lr[rr];
        size_t op = ((size_t)(b * TT + t)) * DM + h * HD;
        oh[op + lane]      = __float2half_rn(ac0[rr] * inv);
        oh[op + lane + 32] = __float2half_rn(ac1[rr] * inv);
    }
}

// ===================== pipelined HMMA GEMM core ==============================
// TERMS=2: Ah*Bh + Al*Bh (acts hi/lo x weights hi), 2 stages x 48KB.
// TERMS=1: Ah*Bh, 3 stages x 32KB. Both 96KB total.
template<int TERMS, int NST>
__device__ __forceinline__ void gemm_pipe(
    uint32_t sb, float (*acc)[4],
    const h16* __restrict__ ah, const h16* __restrict__ al,
    const h16* __restrict__ bh,
    int K, const int* __restrict__ perm, int row_base, int valid, int b_row0)
{
    constexpr uint32_t T_A_H = 0;
    constexpr uint32_t T_A_L = 16384;
    constexpr uint32_t T_B_H = (TERMS == 2) ? 32768u : 16384u;
    constexpr uint32_t STAGE = (TERMS == 2) ? 49152u : 32768u;

    const int tid = threadIdx.x, lane = tid & 31, wid = tid >> 5;
    const int wm = wid >> 2, wn = wid & 3;
    const int nkb = K >> 6;

    size_t aoff[4], boff[4];
    uint32_t soff[4], asz[4];
    int chs[4];
    #pragma unroll
    for (int it = 0; it < 4; it++) {
        int idx = tid + it * 256;
        int row = idx >> 3, ch = idx & 7;
        chs[it] = ch;
        soff[it] = sw128((uint32_t)(row * 128 + ch * 16));
        asz[it] = (row < valid) ? 16u : 0u;
        int gra = (row < valid) ? (perm ? perm[row_base + row] : (row_base + row)) : 0;
        aoff[it] = (size_t)gra * K;
        boff[it] = (size_t)(b_row0 + row) * K;
    }

    auto load_stage = [&](int kb) {
        uint32_t s0 = sb + (uint32_t)(kb % NST) * STAGE;
        #pragma unroll
        for (int it = 0; it < 4; it++) {
            int koff = kb * 64 + chs[it] * 8;
            cp_async16(s0 + T_A_H + soff[it], ah + aoff[it] + koff, asz[it]);
            if (TERMS == 2)
                cp_async16(s0 + T_A_L + soff[it], al + aoff[it] + koff, asz[it]);
            cp_async16(s0 + T_B_H + soff[it], bh + boff[it] + koff, 16u);
        }
        cp_commit();
    };

    #pragma unroll
    for (int s = 0; s < NST - 1; s++)
        if (s < nkb) load_stage(s);

    for (int kb = 0; kb < nkb; kb++) {
        if (kb + NST - 1 < nkb) { load_stage(kb + NST - 1); cp_wait<NST - 1>(); }
        else if (NST >= 3 && kb + NST - 2 < nkb) cp_wait<(NST >= 3) ? NST - 2 : 0>();
        else cp_wait<0>();
        __syncthreads();
        uint32_t s0 = sb + (uint32_t)(kb % NST) * STAGE;
        #pragma unroll
        for (int ks = 0; ks < 4; ks++) {
            uint32_t afh[4][4], afl[4][4];
            #pragma unroll
            for (int mt = 0; mt < 4; mt++) {
                int row = wm * 64 + mt * 16 + (lane & 15);
                uint32_t so = sw128((uint32_t)(row * 128 + ks * 32 + (lane >> 4) * 16));
                ldsm4(afh[mt], s0 + T_A_H + so);
                if (TERMS == 2) ldsm4(afl[mt], s0 + T_A_L + so);
            }
            uint32_t bfh[4][2];
            #pragma unroll
            for (int n2 = 0; n2 < 2; n2++) {
                int row = wn * 32 + n2 * 16 + (lane & 15);
                uint32_t so = sw128((uint32_t)(row * 128 + ks * 32 + (lane >> 4) * 16));
                uint32_t t4[4];
                ldsm4(t4, s0 + T_B_H + so);
                bfh[n2 * 2][0] = t4[0]; bfh[n2 * 2][1] = t4[2];
                bfh[n2 * 2 + 1][0] = t4[1]; bfh[n2 * 2 + 1][1] = t4[3];
            }
            #pragma unroll
            for (int mt = 0; mt < 4; mt++)
                #pragma unroll
                for (int nt = 0; nt < 4; nt++) {
                    float* d = acc[mt * 4 + nt];
                    mma_f16(d, afh[mt], bfh[nt]);
                    if (TERMS == 2) mma_f16(d, afl[mt], bfh[nt]);
                }
        }
        __syncthreads();
    }
}

#define GEMM_SMEM 98304

// ---------------- qkv = xn1 @ w_qkv (2-term) ----------------
__global__ void __launch_bounds__(256) qkv_gemm() {
    extern __shared__ char smem[];
    uint32_t sb = smem_u32(smem);
    float acc[16][4];
    #pragma unroll
    for (int i = 0; i < 16; i++)
        #pragma unroll
        for (int j = 0; j < 4; j++) acc[i][j] = 0.f;
    int m0 = blockIdx.y * 128, n0 = blockIdx.x * 128;
    gemm_pipe<2, 2>(sb, acc, g_xn1_h, g_xn1_l, g_wqkvt_h,
                    DM, nullptr, m0, 128, n0);
    int lane = threadIdx.x & 31, wid = threadIdx.x >> 5;
    int wm = wid >> 2, wn = wid & 3;
    #pragma unroll
    for (int mt = 0; mt < 4; mt++)
        #pragma unroll
        for (int nt = 0; nt < 4; nt++) {
            int r = m0 + wm * 64 + mt * 16 + (lane >> 2);
            int c = n0 + wn * 32 + nt * 8 + 2 * (lane & 3);
            float* d = acc[mt * 4 + nt];
            float* p0 = g_qkv + (size_t)r * (3 * DM) + c;
            p0[0] = d[0]; p0[1] = d[1];
            float* p1 = g_qkv + (size_t)(r + 8) * (3 * DM) + c;
            p1[0] = d[2]; p1[1] = d[3];
        }
}

// ---------------- x2 = attn @ w_proj + b_proj + x (1-term) ----------------
__global__ void __launch_bounds__(256, 2) proj_gemm(
    const float* __restrict__ bias, const float* __restrict__ resid)
{
    extern __shared__ char smem[];
    uint32_t sb = smem_u32(smem);
    float acc[16][4];
    #pragma unroll
    for (int i = 0; i < 16; i++)
        #pragma unroll
        for (int j = 0; j < 4; j++) acc[i][j] = 0.f;
    int m0 = blockIdx.y * 128, n0 = blockIdx.x * 128;
    gemm_pipe<1, 3>(sb, acc, g_attn_h, nullptr, g_wprojt_h,
                    DM, nullptr, m0, 128, n0);
    int lane = threadIdx.x & 31, wid = threadIdx.x >> 5;
    int wm = wid >> 2, wn = wid & 3;
    #pragma unroll
    for (int mt = 0; mt < 4; mt++)
        #pragma unroll
        for (int nt = 0; nt < 4; nt++) {
            int r = m0 + wm * 64 + mt * 16 + (lane >> 2);
            int c = n0 + wn * 32 + nt * 8 + 2 * (lane & 3);
            float* d = acc[mt * 4 + nt];
            size_t p0 = (size_t)r * DM + c;
            size_t p1 = (size_t)(r + 8) * DM + c;
            g_x2[p0]     = d[0] + bias[c]     + resid[p0];
            g_x2[p0 + 1] = d[1] + bias[c + 1] + resid[p0 + 1];
            g_x2[p1]     = d[2] + bias[c]     + resid[p1];
            g_x2[p1 + 1] = d[3] + bias[c + 1] + resid[p1 + 1];
        }
}

// ---------------- h = gelu(gather(xn2) @ w1[e] + b1[e]) (1-term) -------------
__global__ void __launch_bounds__(256, 2) ffn1_gemm(const float* __restrict__ B1) {
    int e = blockIdx.z;
    int cnt = g_cnt[e];
    int r0 = blockIdx.y * 128;
    if (r0 >= cnt) return;
    extern __shared__ char smem[];
    uint32_t sb = smem_u32(smem);
    float acc[16][4];
    #pragma unroll
    for (int i = 0; i < 16; i++)
        #pragma unroll
        for (int j = 0; j < 4; j++) acc[i][j] = 0.f;
    int off = g_off[e];
    int n0 = blockIdx.x * 128;
    int valid = cnt - r0; if (valid > 128) valid = 128;
    gemm_pipe<1, 3>(sb, acc, g_xn2_h, nullptr,
                    g_w1t + (size_t)e * DFF * DM,
                    DM, g_perm_tok, off + r0, valid, n0);
    int lane = threadIdx.x & 31, wid = threadIdx.x >> 5;
    int wm = wid >> 2, wn = wid & 3;
    const float* bias = B1 + e * DFF;
    #pragma unroll
    for (int mt = 0; mt < 4; mt++)
        #pragma unroll
        for (int nt = 0; nt < 4; nt++) {
            int rl = wm * 64 + mt * 16 + (lane >> 2);
            int c = n0 + wn * 32 + nt * 8 + 2 * (lane & 3);
            float* d = acc[mt * 4 + nt];
            #pragma unroll
            for (int half = 0; half < 2; half++) {
                int row = rl + half * 8;
                if (row >= valid) continue;
                size_t rp = (size_t)(off + r0 + row) * DFF + c;
                #pragma unroll
                for (int u = 0; u < 2; u++) {
                    float v = d[half * 2 + u] + bias[c + u];
                    v = 0.5f * v * (1.0f + erff(v * 0.70710678118654752f));
                    g_hbuf[rp + u] = __float2half_rn(v);
                }
            }
        }
}

// ---------------- y = h @ w2[e] + b2[e] (1-term) ----------------
__global__ void __launch_bounds__(256, 2) ffn2_gemm(const float* __restrict__ B2) {
    int e = blockIdx.z;
    int cnt = g_cnt[e];
    int r0 = blockIdx.y * 128;
    if (r0 >= cnt) return;
    extern __shared__ char smem[];
    uint32_t sb = smem_u32(smem);
    float acc[16][4];
    #pragma unroll
    for (int i = 0; i < 16; i++)
        #pragma unroll
        for (int j = 0; j < 4; j++) acc[i][j] = 0.f;
    int off = g_off[e];
    int n0 = blockIdx.x * 128;
    int valid = cnt - r0; if (valid > 128) valid = 128;
    gemm_pipe<1, 3>(sb, acc, g_hbuf, nullptr,
                    g_w2t + (size_t)e * DM * DFF,
                    DFF, nullptr, off + r0, valid, n0);
    int lane = threadIdx.x & 31, wid = threadIdx.x >> 5;
    int wm = wid >> 2, wn = wid & 3;
    const float* bias = B2 + e * DM;
    #pragma unroll
    for (int mt = 0; mt < 4; mt++)
        #pragma unroll
        for (int nt = 0; nt < 4; nt++) {
            int rl = wm * 64 + mt * 16 + (lane >> 2);
            int c = n0 + wn * 32 + nt * 8 + 2 * (lane & 3);
            float* d = acc[mt * 4 + nt];
            #pragma unroll
            for (int half = 0; half < 2; half++) {
                int row = rl + half * 8;
                if (row >= valid) continue;
                size_t rp = (size_t)(off + r0 + row) * DM + c;
                g_y[rp]     = d[half * 2]     + bias[c];
                g_y[rp + 1] = d[half * 2 + 1] + bias[c + 1];
            }
        }
}

// ---------------- router ----------------
__global__ void __launch_bounds__(128) router_kernel(
    const float* __restrict__ xn2, const float* __restrict__ wr)
{
    int tok = blockIdx.x, tid = threadIdx.x;
    const float* xr = xn2 + (size_t)tok * DM;
    float p[NE];
    #pragma unroll
    for (int e = 0; e < NE; e++) p[e] = 0.f;
    for (int i = tid; i < DM; i += 128) {
        float xv = xr[i];
        const float* w = wr + i * NE;
        #pragma unroll
        for (int e = 0; e < NE; e++) p[e] += xv * w[e];
    }
    __shared__ float red[NE][128];
    #pragma unroll
    for (int e = 0; e < NE; e++) red[e][tid] = p[e];
    __syncthreads();
    for (int st = 64; st > 0; st >>= 1) {
        if (tid < st) {
            #pragma unroll
            for (int e = 0; e < NE; e++) red[e][tid] += red[e][tid + st];
        }
        __syncthreads();
    }
    if (tid == 0) {
        float lg[NE], mx = -1e30f;
        #pragma unroll
        for (int e = 0; e < NE; e++) { lg[e] = red[e][0]; mx = fmaxf(mx, lg[e]); }
        float se = 0.f, pr[NE];
        #pragma unroll
        for (int e = 0; e < NE; e++) { pr[e] = __expf(lg[e] - mx); se += pr[e]; }
        float inv = 1.0f / se;
        #pragma unroll
        for (int e = 0; e < NE; e++) {
            pr[e] *= inv;
            atomicAdd(&g_probsum[e], pr[e]);
        }
        int i0 = 0;
        #pragma unroll
        for (int e = 1; e < NE; e++) if (pr[e] > pr[i0]) i0 = e;
        int i1 = (i0 == 0) ? 1 : 0;
        #pragma unroll
        for (int e = 0; e < NE; e++) if (e != i0 && pr[e] > pr[i1]) i1 = e;
        float w0 = pr[i0], w1 = pr[i1], sw = 1.0f / (w0 + w1);
        g_top_i[tok * 2] = i0; g_top_i[tok * 2 + 1] = i1;
        g_top_w[tok * 2] = w0 * sw; g_top_w[tok * 2 + 1] = w1 * sw;
        atomicAdd(&g_cnt[i0], 1);
        atomicAdd(&g_cnt[i1], 1);
    }
}

__global__ void scan_kernel() {
    if (threadIdx.x == 0 && blockIdx.x == 0) {
        int o = 0;
        float aux = 0.f;
        for (int e = 0; e < NE; e++) { g_off[e] = o; o += g_cnt[e]; }
        for (int e = 0; e < NE; e++)
            aux += ((float)g_cnt[e] / (float)(NTOK * 2)) * (g_probsum[e] / (float)NTOK);
        g_aux = (float)NE * aux;
    }
}

__global__ void place_kernel() {
    int s = blockIdx.x * 256 + threadIdx.x;
    if (s >= NSLOT) return;
    int tok = s >> 1;
    int e = g_top_i[s];
    float w = g_top_w[s];
    int pos = atomicAdd(&g_cur[e], 1);
    int slot = g_off[e] + pos;
    g_perm_tok[slot] = tok;
    g_slot_gate[slot] = w;
    g_slot_of[s] = slot;
}

// ---------------- final combine ----------------
__global__ void __launch_bounds__(256) combine_kernel(float* __restrict__ out, int out_size)
{
    int tok = blockIdx.x;
    int s0 = g_slot_of[tok * 2], s1 = g_slot_of[tok * 2 + 1];
    float w0 = g_slot_gate[s0], w1 = g_slot_gate[s1];
    const float* y0 = g_y + (size_t)s0 * DM;
    const float* y1 = g_y + (size_t)s1 * DM;
    const float* xr = g_x2 + (size_t)tok * DM;
    float* orow = out + (size_t)tok * DM;
    #pragma unroll
    for (int l = 0; l < 4; l++) {
        int i = threadIdx.x + l * 256;
        orow[i] = xr[i] + w0 * y0[i] + w1 * y1[i];
    }
    if (tok == 0 && threadIdx.x == 0 && out_size > NTOK * DM)
        out[NTOK * DM] = g_aux;
}

// ===================== launch =====================
extern "C" void kernel_launch(void* const* d_in, const int* in_sizes, int n_in,
                              void* d_out, int out_size)
{
    const float* x        = (const float*)d_in[0];
    const float* ln1_g    = (const float*)d_in[2];
    const float* ln1_b    = (const float*)d_in[3];
    const float* w_qkv    = (const float*)d_in[4];
    const float* w_proj   = (const float*)d_in[5];
    const float* b_proj   = (const float*)d_in[6];
    const float* ln2_g    = (const float*)d_in[7];
    const float* ln2_b    = (const float*)d_in[8];
    const float* w_router = (const float*)d_in[9];
    const float* w1       = (const float*)d_in[10];
    const float* b1       = (const float*)d_in[11];
    const float* w2       = (const float*)d_in[12];
    const float* b2       = (const float*)d_in[13];
    float* out = (float*)d_out;

    static cudaStream_t s_side = nullptr;
    static cudaEvent_t ev_fork = nullptr, ev_join = nullptr;
    static bool attr_done = false;
    if (!attr_done) {
        cudaFuncSetAttribute(qkv_gemm,  cudaFuncAttributeMaxDynamicSharedMemorySize, GEMM_SMEM);
        cudaFuncSetAttribute(proj_gemm, cudaFuncAttributeMaxDynamicSharedMemorySize, GEMM_SMEM);
        cudaFuncSetAttribute(ffn1_gemm, cudaFuncAttributeMaxDynamicSharedMemorySize, GEMM_SMEM);
        cudaFuncSetAttribute(ffn2_gemm, cudaFuncAttributeMaxDynamicSharedMemorySize, GEMM_SMEM);
        cudaStreamCreateWithFlags(&s_side, cudaStreamNonBlocking);
        cudaEventCreateWithFlags(&ev_fork, cudaEventDisableTiming);
        cudaEventCreateWithFlags(&ev_join, cudaEventDisableTiming);
        attr_done = true;
    }

    float *p_qkv, *p_q, *p_k, *p_v, *p_x2, *p_xn2;
    h16 *p_xn1_h, *p_xn1_l, *p_attn_h, *p_xn2_h;
    h16 *p_wqkvt_h, *p_wprojt_h, *p_w1t, *p_w2t;
    cudaGetSymbolAddress((void**)&p_qkv,  g_qkv);
    cudaGetSymbolAddress((void**)&p_q,    g_q);
    cudaGetSymbolAddress((void**)&p_k,    g_k);
    cudaGetSymbolAddress((void**)&p_v,    g_v);
    cudaGetSymbolAddress((void**)&p_x2,   g_x2);
    cudaGetSymbolAddress((void**)&p_xn2,  g_xn2);
    cudaGetSymbolAddress((void**)&p_xn1_h, g_xn1_h);
    cudaGetSymbolAddress((void**)&p_xn1_l, g_xn1_l);
    cudaGetSymbolAddress((void**)&p_attn_h, g_attn_h);
    cudaGetSymbolAddress((void**)&p_xn2_h, g_xn2_h);
    cudaGetSymbolAddress((void**)&p_wqkvt_h, g_wqkvt_h);
    cudaGetSymbolAddress((void**)&p_wprojt_h, g_wprojt_h);
    cudaGetSymbolAddress((void**)&p_w1t, g_w1t);
    cudaGetSymbolAddress((void**)&p_w2t, g_w2t);

    zero_small_kernel<<<1, 32>>>();

    // fork: heavy FFN weight conversion on side stream, overlapped with
    // the ln1 -> qkv -> rope -> attention chain
    cudaEventRecord(ev_fork, 0);
    cudaStreamWaitEvent(s_side, ev_fork, 0);
    trans_conv<<<dim3(DFF / 32, DM / 32, NE), 256, 0, s_side>>>(w1, p_w1t, nullptr, DM, DFF);
    trans_conv<<<dim3(DM / 32, DFF / 32, NE), 256, 0, s_side>>>(w2, p_w2t, nullptr, DFF, DM);
    cudaEventRecord(ev_join, s_side);

    // main chain
    trans_conv<<<dim3(3 * DM / 32, DM / 32, 1), 256>>>(w_qkv, p_wqkvt_h, nullptr, DM, 3 * DM);
    trans_conv<<<dim3(DM / 32, DM / 32, 1), 256>>>(w_proj, p_wprojt_h, nullptr, DM, DM);
    ln_kernel<<<NTOK, 256>>>(x, ln1_g, ln1_b, nullptr, p_xn1_h, p_xn1_l);
    qkv_gemm<<<dim3(3 * DM / 128, NTOK / 128), 256, GEMM_SMEM>>>();
    rope_kernel<<<NTOK, 256>>>(p_qkv, p_q, p_k, p_v);
    attn_kernel<<<NBH * (TT / 32), 256>>>(p_q, p_k, p_v, p_attn_h);
    proj_gemm<<<dim3(DM / 128, NTOK / 128), 256, GEMM_SMEM>>>(b_proj, x);
    ln_kernel<<<NTOK, 256>>>(p_x2, ln2_g, ln2_b, p_xn2, p_xn2_h, nullptr);
    router_kernel<<<NTOK, 128>>>(p_xn2, w_router);
    scan_kernel<<<1, 1>>>();
    place_kernel<<<NSLOT / 256, 256>>>();

    // join before expert GEMMs need w1t/w2t
    cudaStreamWaitEvent(0, ev_join, 0);
    ffn1_gemm<<<dim3(DFF / 128, NSLOT / 128, NE), 256, GEMM_SMEM>>>(b1);
    ffn2_gemm<<<dim3(DM / 128, NSLOT / 128, NE), 256, GEMM_SMEM>>>(b2);
    combine_kernel<<<NTOK, 256>>>(out, out_size);
}

// round 7
// speedup vs baseline: 6.2254x; 1.3645x over previous
#include <cuda_runtime.h>
#include <cuda_fp16.h>
#include <math.h>
#include <stdint.h>

#define NTOK 4096      // B*T
#define DM   1024
#define NH   16
#define HD   64
#define NE   8
#define DFF  4096
#define NSLOT 8192     // NTOK * TOP_K
#define TT   1024
#define NBH  64        // B * NH

typedef __half h16;

// ===================== scratch (static device memory) ========================
__device__ h16   g_xn1_h [NTOK * DM];
__device__ h16   g_xn1_l [NTOK * DM];
__device__ float g_qkv   [NTOK * 3 * DM];
__device__ h16   g_qh    [NTOK * DM];   // [B,H,T,HD] fp16, pre-scaled by 0.125
__device__ h16   g_kh    [NTOK * DM];
__device__ h16   g_vh    [NTOK * DM];
__device__ h16   g_attn_h[NTOK * DM];
__device__ float g_x2    [NTOK * DM];
__device__ float g_xn2   [NTOK * DM];
__device__ h16   g_xn2_h [NTOK * DM];
__device__ h16   g_hbuf  [(size_t)NSLOT * DFF];
__device__ float g_y     [NSLOT * DM];

// transposed weights ([N,K] K-major per expert)
__device__ h16 g_wqkvt_h[3 * DM * DM];
__device__ h16 g_wprojt_h[DM * DM];
__device__ h16 g_w1t[(size_t)NE * DFF * DM];
__device__ h16 g_w2t[(size_t)NE * DM * DFF];

__device__ int   g_cnt[NE];
__device__ int   g_off[NE];
__device__ int   g_cur[NE];
__device__ float g_probsum[NE];
__device__ int   g_top_i[NSLOT];
__device__ float g_top_w[NSLOT];
__device__ int   g_perm_tok[NSLOT];
__device__ float g_slot_gate[NSLOT];
__device__ int   g_slot_of[NSLOT];
__device__ float g_aux;

__device__ __forceinline__ uint32_t smem_u32(const void* p) {
    uint32_t a;
    asm("{ .reg .u64 t; cvta.to.shared.u64 t, %1; cvt.u32.u64 %0, t; }"
        : "=r"(a) : "l"(p));
    return a;
}
__device__ __forceinline__ void ldsm4(uint32_t* r, uint32_t addr) {
    asm volatile("ldmatrix.sync.aligned.m8n8.x4.shared.b16 {%0,%1,%2,%3}, [%4];"
                 : "=r"(r[0]), "=r"(r[1]), "=r"(r[2]), "=r"(r[3]) : "r"(addr));
}
__device__ __forceinline__ void ldsm4t(uint32_t* r, uint32_t addr) {
    asm volatile("ldmatrix.sync.aligned.m8n8.x4.trans.shared.b16 {%0,%1,%2,%3}, [%4];"
                 : "=r"(r[0]), "=r"(r[1]), "=r"(r[2]), "=r"(r[3]) : "r"(addr));
}
__device__ __forceinline__ void mma_f16(float* d, const uint32_t* a, const uint32_t* b) {
    asm volatile(
        "mma.sync.aligned.m16n8k16.row.col.f32.f16.f16.f32 "
        "{%0,%1,%2,%3}, {%4,%5,%6,%7}, {%8,%9}, {%0,%1,%2,%3};"
        : "+f"(d[0]), "+f"(d[1]), "+f"(d[2]), "+f"(d[3])
        : "r"(a[0]), "r"(a[1]), "r"(a[2]), "r"(a[3]), "r"(b[0]), "r"(b[1]));
}
__device__ __forceinline__ void cp_async16(uint32_t saddr, const void* g, uint32_t sz) {
    asm volatile("cp.async.cg.shared.global [%0], [%1], 16, %2;"
                 :: "r"(saddr), "l"(g), "r"(sz));
}
__device__ __forceinline__ void cp_commit() {
    asm volatile("cp.async.commit_group;");
}
template<int N> __device__ __forceinline__ void cp_wait() {
    asm volatile("cp.async.wait_group %0;" :: "n"(N));
}
__device__ __forceinline__ uint32_t sw128(uint32_t o) {
    return o ^ ((o >> 3) & 0x70u);
}
__device__ __forceinline__ uint32_t h2pack(float a, float b) {
    half2 h = __floats2half2_rn(a, b);
    return *(uint32_t*)&h;
}

// ===================== small helpers ====================
__global__ void zero_small_kernel() {
    int i = threadIdx.x;
    if (i < NE) { g_cnt[i] = 0; g_cur[i] = 0; g_probsum[i] = 0.f; }
}

// ---------------- transpose + convert: w[K,N] -> t[N,K] (lo optional) --------
__global__ void __launch_bounds__(256) trans_conv(
    const float* __restrict__ w, h16* __restrict__ th, h16* __restrict__ tl,
    int K, int N)
{
    const size_t eoff = (size_t)blockIdx.z * K * N;
    const float* wp = w + eoff;
    h16* thp = th + eoff;
    h16* tlp = tl ? tl + eoff : nullptr;
    __shared__ float t[32][33];
    int tx = threadIdx.x & 31, ty = threadIdx.x >> 5;
    int n0 = blockIdx.x * 32, k0 = blockIdx.y * 32;
    #pragma unroll
    for (int i = 0; i < 4; i++)
        t[ty + i * 8][tx] = wp[(size_t)(k0 + ty + i * 8) * N + n0 + tx];
    __syncthreads();
    #pragma unroll
    for (int i = 0; i < 4; i++) {
        float v = t[tx][ty + i * 8];
        int n = n0 + ty + i * 8, k = k0 + tx;
        h16 hi = __float2half_rn(v);
        thp[(size_t)n * K + k] = hi;
        if (tlp) tlp[(size_t)n * K + k] = __float2half_rn(v - __half2float(hi));
    }
}

// ---------------- layernorm (256 thr/row) ----------------
__global__ void __launch_bounds__(256) ln_kernel(
    const float* __restrict__ x, const float* __restrict__ g,
    const float* __restrict__ b, float* __restrict__ o32,
    h16* __restrict__ oh, h16* __restrict__ ol)
{
    int row = blockIdx.x;
    const float* xr = x + (size_t)row * DM;
    float v[4]; float s = 0.f, ss = 0.f;
    #pragma unroll
    for (int i = 0; i < 4; i++) {
        float u = xr[threadIdx.x + i * 256];
        v[i] = u; s += u; ss += u * u;
    }
    #pragma unroll
    for (int ofs = 16; ofs > 0; ofs >>= 1) {
        s  += __shfl_xor_sync(0xffffffffu, s,  ofs);
        ss += __shfl_xor_sync(0xffffffffu, ss, ofs);
    }
    __shared__ float sh[2][8];
    int warp = threadIdx.x >> 5, lane = threadIdx.x & 31;
    if (lane == 0) { sh[0][warp] = s; sh[1][warp] = ss; }
    __syncthreads();
    float S = 0.f, SS = 0.f;
    #pragma unroll
    for (int w = 0; w < 8; w++) { S += sh[0][w]; SS += sh[1][w]; }
    float mu  = S * (1.0f / DM);
    float var = SS * (1.0f / DM) - mu * mu;
    float inv = rsqrtf(var + 1e-5f);
    #pragma unroll
    for (int i = 0; i < 4; i++) {
        int idx = threadIdx.x + i * 256;
        float o = (v[i] - mu) * inv * g[idx] + b[idx];
        size_t p = (size_t)row * DM + idx;
        if (o32) o32[p] = o;
        h16 hi = __float2half_rn(o);
        oh[p] = hi;
        if (ol) ol[p] = __float2half_rn(o - __half2float(hi));
    }
}

// ---------------- RoPE + layout transform -> fp16 q/k/v ----------------------
__global__ void __launch_bounds__(256) rope_kernel(
    const float* __restrict__ qkv, h16* __restrict__ q,
    h16* __restrict__ k, h16* __restrict__ v)
{
    int tok = blockIdx.x;
    int b = tok >> 10, t = tok & 1023;
    const float* row = qkv + (size_t)tok * (3 * DM);
    for (int i = threadIdx.x; i < DM; i += 256) {
        int h = i >> 6, d = i & 63;
        int f = d & 31;
        float freq = powf(10000.0f, -(float)f / 32.0f);
        float ang = (float)t * freq;
        float sv, cv;
        sincosf(ang, &sv, &cv);
        float qa = row[i], ka = row[DM + i];
        float qo, ko;
        if (d < 32) {
            qo = qa * cv - row[i + 32] * sv;
            ko = ka * cv - row[DM + i + 32] * sv;
        } else {
            qo = qa * cv + row[i - 32] * sv;
            ko = ka * cv + row[DM + i - 32] * sv;
        }
        int dst = ((b * NH + h) * TT + t) * HD + d;
        q[dst] = __float2half_rn(qo * 0.125f);   // fold score scale
        k[dst] = __float2half_rn(ko);
        v[dst] = __float2half_rn(row[2 * DM + i]);
    }
}

// ---------------- tensor-core flash attention --------------------------------
// Block = one (b,h) x 128 q rows; 8 warps x 16 rows. KV tiles of 64, double
// buffered cp.async. S = QK^T (mma), online softmax on C-frags, PV via
// ldmatrix.trans. attn output fp16.
#define ATTN_SMEM 49152
__global__ void __launch_bounds__(256, 2) attn_kernel(
    const h16* __restrict__ q, const h16* __restrict__ k,
    const h16* __restrict__ v, h16* __restrict__ oh)
{
    extern __shared__ char smem[];
    uint32_t sb = smem_u32(smem);
    const uint32_t SQ = 0, SKV = 16384, STG = 16384;   // per-stage: K 8K + V 8K

    int bh = blockIdx.x & (NBH - 1);
    int chunk = (TT / 128 - 1) - (blockIdx.x >> 6);    // heavy chunks first
    int qb0 = chunk * 128;
    int tid = threadIdx.x, lane = tid & 31, w = tid >> 5;
    const h16* qb = q + (size_t)bh * TT * HD;
    const h16* kb = k + (size_t)bh * TT * HD;
    const h16* vb = v + (size_t)bh * TT * HD;

    // Q tile 128x64 fp16, swizzled
    for (int i = tid; i < 128 * 8; i += 256) {
        int r = i >> 3, ch = i & 7;
        uint32_t so = sw128((uint32_t)(r * 128 + ch * 16));
        *(uint4*)(smem + SQ + so) = *(const uint4*)(qb + (size_t)(qb0 + r) * HD + ch * 8);
    }

    auto load_kv = [&](int j0, int st) {
        uint32_t s0 = sb + SKV + (uint32_t)st * STG;
        #pragma unroll
        for (int i = 0; i < 2; i++) {
            int idx = tid + i * 256;
            int r = idx >> 3, ch = idx & 7;
            uint32_t so = sw128((uint32_t)(r * 128 + ch * 16));
            cp_async16(s0 + so, kb + (size_t)(j0 + r) * HD + ch * 8, 16);
            cp_async16(s0 + 8192 + so, vb + (size_t)(j0 + r) * HD + ch * 8, 16);
        }
        cp_commit();
    };
    load_kv(0, 0);
    __syncthreads();   // Q visible before ldsm

    uint32_t qf[4][4];
    #pragma unroll
    for (int ks = 0; ks < 4; ks++) {
        int row = w * 16 + (lane & 15);
        uint32_t so = sw128((uint32_t)(row * 128 + ks * 32 + (lane >> 4) * 16));
        ldsm4(qf[ks], sb + SQ + so);
    }

    float oacc[8][4];
    #pragma unroll
    for (int i = 0; i < 8; i++)
        #pragma unroll
        for (int j = 0; j < 4; j++) oacc[i][j] = 0.f;
    float mrun[2] = {-1e30f, -1e30f}, lsum[2] = {0.f, 0.f};

    const int wrow = qb0 + w * 16 + (lane >> 2);  // row for r<2; +8 for r>=2
    const int wt_last = qb0 + w * 16 + 15;
    const int wt_first = qb0 + w * 16;
    const int ntiles = (qb0 + 128) / 64;

    for (int ti = 0; ti < ntiles; ti++) {
        int j0 = ti * 64;
        if (ti + 1 < ntiles) { load_kv(j0 + 64, (ti + 1) & 1); cp_wait<1>(); }
        else cp_wait<0>();
        __syncthreads();
        if (j0 <= wt_last) {
            uint32_t s0 = sb + SKV + (uint32_t)(ti & 1) * STG;
            // ---- S = Q K^T ----
            float sacc[8][4];
            #pragma unroll
            for (int i = 0; i < 8; i++)
                #pragma unroll
                for (int j = 0; j < 4; j++) sacc[i][j] = 0.f;
            #pragma unroll
            for (int ks = 0; ks < 4; ks++) {
                #pragma unroll
                for (int n2 = 0; n2 < 4; n2++) {
                    int row = n2 * 16 + (lane & 15);
                    uint32_t so = sw128((uint32_t)(row * 128 + ks * 32 + (lane >> 4) * 16));
                    uint32_t t4[4]; ldsm4(t4, s0 + so);
                    uint32_t b0[2] = {t4[0], t4[2]}, b1[2] = {t4[1], t4[3]};
                    mma_f16(sacc[2 * n2], qf[ks], b0);
                    mma_f16(sacc[2 * n2 + 1], qf[ks], b1);
                }
            }
            // ---- causal mask ----
            if (j0 + 63 > wt_first) {
                #pragma unroll
                for (int nt = 0; nt < 8; nt++)
                    #pragma unroll
                    for (int r = 0; r < 4; r++) {
                        int col = j0 + 8 * nt + 2 * (lane & 3) + (r & 1);
                        int rowt = wrow + 8 * (r >> 1);
                        if (col > rowt) sacc[nt][r] = -1e30f;
                    }
            }
            // ---- online softmax (2 row-halves per lane, quad reduce) ----
            float psc[2];
            #pragma unroll
            for (int hh = 0; hh < 2; hh++) {
                float mx = -1e30f;
                #pragma unroll
                for (int nt = 0; nt < 8; nt++) {
                    mx = fmaxf(mx, sacc[nt][2 * hh]);
                    mx = fmaxf(mx, sacc[nt][2 * hh + 1]);
                }
                mx = fmaxf(mx, __shfl_xor_sync(0xffffffffu, mx, 1));
                mx = fmaxf(mx, __shfl_xor_sync(0xffffffffu, mx, 2));
                float nm = fmaxf(mrun[hh], mx);
                float sc = __expf(mrun[hh] - nm);
                mrun[hh] = nm;
                float sum = 0.f;
                #pragma unroll
                for (int nt = 0; nt < 8; nt++) {
                    float p0 = __expf(sacc[nt][2 * hh] - nm);
                    float p1 = __expf(sacc[nt][2 * hh + 1] - nm);
                    sacc[nt][2 * hh] = p0; sacc[nt][2 * hh + 1] = p1;
                    sum += p0 + p1;
                }
                sum += __shfl_xor_sync(0xffffffffu, sum, 1);
                sum += __shfl_xor_sync(0xffffffffu, sum, 2);
                lsum[hh] = lsum[hh] * sc + sum;
                psc[hh] = sc;
            }
            #pragma unroll
            for (int nt = 0; nt < 8; nt++)
                #pragma unroll
                for (int r = 0; r < 4; r++)
                    oacc[nt][r] *= psc[r >> 1];
            // ---- P -> fp16 A frags (C->A layout identity) ----
            uint32_t pf[4][4];
            #pragma unroll
            for (int kt = 0; kt < 4; kt++) {
                pf[kt][0] = h2pack(sacc[2 * kt][0], sacc[2 * kt][1]);
                pf[kt][1] = h2pack(sacc[2 * kt][2], sacc[2 * kt][3]);
                pf[kt][2] = h2pack(sacc[2 * kt + 1][0], sacc[2 * kt + 1][1]);
                pf[kt][3] = h2pack(sacc[2 * kt + 1][2], sacc[2 * kt + 1][3]);
            }
            // ---- O += P V (V via ldmatrix.trans) ----
            uint32_t sv = s0 + 8192;
            int g = lane >> 3, rr = lane & 7;
            #pragma unroll
            for (int dp = 0; dp < 4; dp++) {
                #pragma unroll
                for (int kt = 0; kt < 4; kt++) {
                    int kvr = 16 * kt + 8 * (g & 1) + rr;
                    int dc = dp * 16 + 8 * (g >> 1);
                    uint32_t so = sw128((uint32_t)(kvr * 128 + dc * 2));
                    uint32_t t4[4]; ldsm4t(t4, sv + so);
                    uint32_t b0[2] = {t4[0], t4[1]}, b1[2] = {t4[2], t4[3]};
                    mma_f16(oacc[2 * dp], pf[kt], b0);
                    mma_f16(oacc[2 * dp + 1], pf[kt], b1);
                }
            }
        }
        __syncthreads();
    }
    // ---- write O (fp16) ----
    int b = bh >> 4, hH = bh & 15;
    #pragma unroll
    for (int hh = 0; hh < 2; hh++) {
        float inv = 1.0f / lsum[hh];
        int t = wrow + 8 * hh;
        size_t op = ((size_t)(b * TT + t)) * DM + hH * HD;
        #pragma unroll
        for (int nt = 0; nt < 8; nt++) {
            int d = 8 * nt + 2 * (lane & 3);
            half2 hv = __floats2half2_rn(oacc[nt][2 * hh] * inv, oacc[nt][2 * hh + 1] * inv);
            *(half2*)(oh + op + d) = hv;
        }
    }
}

// ===================== pipelined HMMA GEMM core ==============================
template<int TERMS, int NST>
__device__ __forceinline__ void gemm_pipe(
    uint32_t sb, float (*acc)[4],
    const h16* __restrict__ ah, const h16* __restrict__ al,
    const h16* __restrict__ bh,
    int K, const int* __restrict__ perm, int row_base, int valid, int b_row0)
{
    constexpr uint32_t T_A_H = 0;
    constexpr uint32_t T_A_L = 16384;
    constexpr uint32_t T_B_H = (TERMS == 2) ? 32768u : 16384u;
    constexpr uint32_t STAGE = (TERMS == 2) ? 49152u : 32768u;

    const int tid = threadIdx.x, lane = tid & 31, wid = tid >> 5;
    const int wm = wid >> 2, wn = wid & 3;
    const int nkb = K >> 6;

    size_t aoff[4], boff[4];
    uint32_t soff[4], asz[4];
    int chs[4];
    #pragma unroll
    for (int it = 0; it < 4; it++) {
        int idx = tid + it * 256;
        int row = idx >> 3, ch = idx & 7;
        chs[it] = ch;
        soff[it] = sw128((uint32_t)(row * 128 + ch * 16));
        asz[it] = (row < valid) ? 16u : 0u;
        int gra = (row < valid) ? (perm ? perm[row_base + row] : (row_base + row)) : 0;
        aoff[it] = (size_t)gra * K;
        boff[it] = (size_t)(b_row0 + row) * K;
    }

    auto load_stage = [&](int kb) {
        uint32_t s0 = sb + (uint32_t)(kb % NST) * STAGE;
        #pragma unroll
        for (int it = 0; it < 4; it++) {
            int koff = kb * 64 + chs[it] * 8;
            cp_async16(s0 + T_A_H + soff[it], ah + aoff[it] + koff, asz[it]);
            if (TERMS == 2)
                cp_async16(s0 + T_A_L + soff[it], al + aoff[it] + koff, asz[it]);
            cp_async16(s0 + T_B_H + soff[it], bh + boff[it] + koff, 16u);
        }
        cp_commit();
    };

    #pragma unroll
    for (int s = 0; s < NST - 1; s++)
        if (s < nkb) load_stage(s);

    for (int kb = 0; kb < nkb; kb++) {
        if (kb + NST - 1 < nkb) { load_stage(kb + NST - 1); cp_wait<NST - 1>(); }
        else if (NST >= 3 && kb + NST - 2 < nkb) cp_wait<(NST >= 3) ? NST - 2 : 0>();
        else cp_wait<0>();
        __syncthreads();
        uint32_t s0 = sb + (uint32_t)(kb % NST) * STAGE;
        #pragma unroll
        for (int ks = 0; ks < 4; ks++) {
            uint32_t afh[4][4], afl[4][4];
            #pragma unroll
            for (int mt = 0; mt < 4; mt++) {
                int row = wm * 64 + mt * 16 + (lane & 15);
                uint32_t so = sw128((uint32_t)(row * 128 + ks * 32 + (lane >> 4) * 16));
                ldsm4(afh[mt], s0 + T_A_H + so);
                if (TERMS == 2) ldsm4(afl[mt], s0 + T_A_L + so);
            }
            uint32_t bfh[4][2];
            #pragma unroll
            for (int n2 = 0; n2 < 2; n2++) {
                int row = wn * 32 + n2 * 16 + (lane & 15);
                uint32_t so = sw128((uint32_t)(row * 128 + ks * 32 + (lane >> 4) * 16));
                uint32_t t4[4];
                ldsm4(t4, s0 + T_B_H + so);
                bfh[n2 * 2][0] = t4[0]; bfh[n2 * 2][1] = t4[2];
                bfh[n2 * 2 + 1][0] = t4[1]; bfh[n2 * 2 + 1][1] = t4[3];
            }
            #pragma unroll
            for (int mt = 0; mt < 4; mt++)
                #pragma unroll
                for (int nt = 0; nt < 4; nt++) {
                    float* d = acc[mt * 4 + nt];
                    mma_f16(d, afh[mt], bfh[nt]);
                    if (TERMS == 2) mma_f16(d, afl[mt], bfh[nt]);
                }
        }
        __syncthreads();
    }
}

#define GEMM_SMEM 98304

// ---------------- qkv = xn1 @ w_qkv (2-term) ----------------
__global__ void __launch_bounds__(256) qkv_gemm() {
    extern __shared__ char smem[];
    uint32_t sb = smem_u32(smem);
    float acc[16][4];
    #pragma unroll
    for (int i = 0; i < 16; i++)
        #pragma unroll
        for (int j = 0; j < 4; j++) acc[i][j] = 0.f;
    int m0 = blockIdx.y * 128, n0 = blockIdx.x * 128;
    gemm_pipe<2, 2>(sb, acc, g_xn1_h, g_xn1_l, g_wqkvt_h,
                    DM, nullptr, m0, 128, n0);
    int lane = threadIdx.x & 31, wid = threadIdx.x >> 5;
    int wm = wid >> 2, wn = wid & 3;
    #pragma unroll
    for (int mt = 0; mt < 4; mt++)
        #pragma unroll
        for (int nt = 0; nt < 4; nt++) {
            int r = m0 + wm * 64 + mt * 16 + (lane >> 2);
            int c = n0 + wn * 32 + nt * 8 + 2 * (lane & 3);
            float* d = acc[mt * 4 + nt];
            float* p0 = g_qkv + (size_t)r * (3 * DM) + c;
            p0[0] = d[0]; p0[1] = d[1];
            float* p1 = g_qkv + (size_t)(r + 8) * (3 * DM) + c;
            p1[0] = d[2]; p1[1] = d[3];
        }
}

// ---------------- x2 = attn @ w_proj + b_proj + x (1-term) ----------------
__global__ void __launch_bounds__(256, 2) proj_gemm(
    const float* __restrict__ bias, const float* __restrict__ resid)
{
    extern __shared__ char smem[];
    uint32_t sb = smem_u32(smem);
    float acc[16][4];
    #pragma unroll
    for (int i = 0; i < 16; i++)
        #pragma unroll
        for (int j = 0; j < 4; j++) acc[i][j] = 0.f;
    int m0 = blockIdx.y * 128, n0 = blockIdx.x * 128;
    gemm_pipe<1, 3>(sb, acc, g_attn_h, nullptr, g_wprojt_h,
                    DM, nullptr, m0, 128, n0);
    int lane = threadIdx.x & 31, wid = threadIdx.x >> 5;
    int wm = wid >> 2, wn = wid & 3;
    #pragma unroll
    for (int mt = 0; mt < 4; mt++)
        #pragma unroll
        for (int nt = 0; nt < 4; nt++) {
            int r = m0 + wm * 64 + mt * 16 + (lane >> 2);
            int c = n0 + wn * 32 + nt * 8 + 2 * (lane & 3);
            float* d = acc[mt * 4 + nt];
            size_t p0 = (size_t)r * DM + c;
            size_t p1 = (size_t)(r + 8) * DM + c;
            g_x2[p0]     = d[0] + bias[c]     + resid[p0];
            g_x2[p0 + 1] = d[1] + bias[c + 1] + resid[p0 + 1];
            g_x2[p1]     = d[2] + bias[c]     + resid[p1];
            g_x2[p1 + 1] = d[3] + bias[c + 1] + resid[p1 + 1];
        }
}

// ---------------- h = gelu(gather(xn2) @ w1[e] + b1[e]) (1-term) -------------
__global__ void __launch_bounds__(256, 2) ffn1_gemm(const float* __restrict__ B1) {
    int e = blockIdx.z;
    int cnt = g_cnt[e];
    int r0 = blockIdx.y * 128;
    if (r0 >= cnt) return;
    extern __shared__ char smem[];
    uint32_t sb = smem_u32(smem);
    float acc[16][4];
    #pragma unroll
    for (int i = 0; i < 16; i++)
        #pragma unroll
        for (int j = 0; j < 4; j++) acc[i][j] = 0.f;
    int off = g_off[e];
    int n0 = blockIdx.x * 128;
    int valid = cnt - r0; if (valid > 128) valid = 128;
    gemm_pipe<1, 3>(sb, acc, g_xn2_h, nullptr,
                    g_w1t + (size_t)e * DFF * DM,
                    DM, g_perm_tok, off + r0, valid, n0);
    int lane = threadIdx.x & 31, wid = threadIdx.x >> 5;
    int wm = wid >> 2, wn = wid & 3;
    const float* bias = B1 + e * DFF;
    #pragma unroll
    for (int mt = 0; mt < 4; mt++)
        #pragma unroll
        for (int nt = 0; nt < 4; nt++) {
            int rl = wm * 64 + mt * 16 + (lane >> 2);
            int c = n0 + wn * 32 + nt * 8 + 2 * (lane & 3);
            float* d = acc[mt * 4 + nt];
            #pragma unroll
            for (int half = 0; half < 2; half++) {
                int row = rl + half * 8;
                if (row >= valid) continue;
                size_t rp = (size_t)(off + r0 + row) * DFF + c;
                #pragma unroll
                for (int u = 0; u < 2; u++) {
                    float v = d[half * 2 + u] + bias[c + u];
                    v = 0.5f * v * (1.0f + erff(v * 0.70710678118654752f));
                    g_hbuf[rp + u] = __float2half_rn(v);
                }
            }
        }
}

// ---------------- y = h @ w2[e] + b2[e] (1-term) ----------------
__global__ void __launch_bounds__(256, 2) ffn2_gemm(const float* __restrict__ B2) {
    int e = blockIdx.z;
    int cnt = g_cnt[e];
    int r0 = blockIdx.y * 128;
    if (r0 >= cnt) return;
    extern __shared__ char smem[];
    uint32_t sb = smem_u32(smem);
    float acc[16][4];
    #pragma unroll
    for (int i = 0; i < 16; i++)
        #pragma unroll
        for (int j = 0; j < 4; j++) acc[i][j] = 0.f;
    int off = g_off[e];
    int n0 = blockIdx.x * 128;
    int valid = cnt - r0; if (valid > 128) valid = 128;
    gemm_pipe<1, 3>(sb, acc, g_hbuf, nullptr,
                    g_w2t + (size_t)e * DM * DFF,
                    DFF, nullptr, off + r0, valid, n0);
    int lane = threadIdx.x & 31, wid = threadIdx.x >> 5;
    int wm = wid >> 2, wn = wid & 3;
    const float* bias = B2 + e * DM;
    #pragma unroll
    for (int mt = 0; mt < 4; mt++)
        #pragma unroll
        for (int nt = 0; nt < 4; nt++) {
            int rl = wm * 64 + mt * 16 + (lane >> 2);
            int c = n0 + wn * 32 + nt * 8 + 2 * (lane & 3);
            float* d = acc[mt * 4 + nt];
            #pragma unroll
            for (int half = 0; half < 2; half++) {
                int row = rl + half * 8;
                if (row >= valid) continue;
                size_t rp = (size_t)(off + r0 + row) * DM + c;
                g_y[rp]     = d[half * 2]     + bias[c];
                g_y[rp + 1] = d[half * 2 + 1] + bias[c + 1];
            }
        }
}

// ---------------- router ----------------
__global__ void __launch_bounds__(128) router_kernel(
    const float* __restrict__ xn2, const float* __restrict__ wr)
{
    int tok = blockIdx.x, tid = threadIdx.x;
    const float* xr = xn2 + (size_t)tok * DM;
    float p[NE];
    #pragma unroll
    for (int e = 0; e < NE; e++) p[e] = 0.f;
    for (int i = tid; i < DM; i += 128) {
        float xv = xr[i];
        const float* w = wr + i * NE;
        #pragma unroll
        for (int e = 0; e < NE; e++) p[e] += xv * w[e];
    }
    __shared__ float red[NE][128];
    #pragma unroll
    for (int e = 0; e < NE; e++) red[e][tid] = p[e];
    __syncthreads();
    for (int st = 64; st > 0; st >>= 1) {
        if (tid < st) {
            #pragma unroll
            for (int e = 0; e < NE; e++) red[e][tid] += red[e][tid + st];
        }
        __syncthreads();
    }
    if (tid == 0) {
        float lg[NE], mx = -1e30f;
        #pragma unroll
        for (int e = 0; e < NE; e++) { lg[e] = red[e][0]; mx = fmaxf(mx, lg[e]); }
        float se = 0.f, pr[NE];
        #pragma unroll
        for (int e = 0; e < NE; e++) { pr[e] = __expf(lg[e] - mx); se += pr[e]; }
        float inv = 1.0f / se;
        #pragma unroll
        for (int e = 0; e < NE; e++) {
            pr[e] *= inv;
            atomicAdd(&g_probsum[e], pr[e]);
        }
        int i0 = 0;
        #pragma unroll
        for (int e = 1; e < NE; e++) if (pr[e] > pr[i0]) i0 = e;
        int i1 = (i0 == 0) ? 1 : 0;
        #pragma unroll
        for (int e = 0; e < NE; e++) if (e != i0 && pr[e] > pr[i1]) i1 = e;
        float w0 = pr[i0], w1 = pr[i1], sw = 1.0f / (w0 + w1);
        g_top_i[tok * 2] = i0; g_top_i[tok * 2 + 1] = i1;
        g_top_w[tok * 2] = w0 * sw; g_top_w[tok * 2 + 1] = w1 * sw;
        atomicAdd(&g_cnt[i0], 1);
        atomicAdd(&g_cnt[i1], 1);
    }
}

__global__ void scan_kernel() {
    if (threadIdx.x == 0 && blockIdx.x == 0) {
        int o = 0;
        float aux = 0.f;
        for (int e = 0; e < NE; e++) { g_off[e] = o; o += g_cnt[e]; }
        for (int e = 0; e < NE; e++)
            aux += ((float)g_cnt[e] / (float)(NTOK * 2)) * (g_probsum[e] / (float)NTOK);
        g_aux = (float)NE * aux;
    }
}

__global__ void place_kernel() {
    int s = blockIdx.x * 256 + threadIdx.x;
    if (s >= NSLOT) return;
    int tok = s >> 1;
    int e = g_top_i[s];
    float w = g_top_w[s];
    int pos = atomicAdd(&g_cur[e], 1);
    int slot = g_off[e] + pos;
    g_perm_tok[slot] = tok;
    g_slot_gate[slot] = w;
    g_slot_of[s] = slot;
}

// ---------------- final combine ----------------
__global__ void __launch_bounds__(256) combine_kernel(float* __restrict__ out, int out_size)
{
    int tok = blockIdx.x;
    int s0 = g_slot_of[tok * 2], s1 = g_slot_of[tok * 2 + 1];
    float w0 = g_slot_gate[s0], w1 = g_slot_gate[s1];
    const float* y0 = g_y + (size_t)s0 * DM;
    const float* y1 = g_y + (size_t)s1 * DM;
    const float* xr = g_x2 + (size_t)tok * DM;
    float* orow = out + (size_t)tok * DM;
    #pragma unroll
    for (int l = 0; l < 4; l++) {
        int i = threadIdx.x + l * 256;
        orow[i] = xr[i] + w0 * y0[i] + w1 * y1[i];
    }
    if (tok == 0 && threadIdx.x == 0 && out_size > NTOK * DM)
        out[NTOK * DM] = g_aux;
}

// ===================== launch =====================
extern "C" void kernel_launch(void* const* d_in, const int* in_sizes, int n_in,
                              void* d_out, int out_size)
{
    const float* x        = (const float*)d_in[0];
    const float* ln1_g    = (const float*)d_in[2];
    const float* ln1_b    = (const float*)d_in[3];
    const float* w_qkv    = (const float*)d_in[4];
    const float* w_proj   = (const float*)d_in[5];
    const float* b_proj   = (const float*)d_in[6];
    const float* ln2_g    = (const float*)d_in[7];
    const float* ln2_b    = (const float*)d_in[8];
    const float* w_router = (const float*)d_in[9];
    const float* w1       = (const float*)d_in[10];
    const float* b1       = (const float*)d_in[11];
    const float* w2       = (const float*)d_in[12];
    const float* b2       = (const float*)d_in[13];
    float* out = (float*)d_out;

    static cudaStream_t s_side = nullptr;
    static cudaEvent_t ev_fork = nullptr, ev_join = nullptr;
    static bool attr_done = false;
    if (!attr_done) {
        cudaFuncSetAttribute(qkv_gemm,  cudaFuncAttributeMaxDynamicSharedMemorySize, GEMM_SMEM);
        cudaFuncSetAttribute(proj_gemm, cudaFuncAttributeMaxDynamicSharedMemorySize, GEMM_SMEM);
        cudaFuncSetAttribute(ffn1_gemm, cudaFuncAttributeMaxDynamicSharedMemorySize, GEMM_SMEM);
        cudaFuncSetAttribute(ffn2_gemm, cudaFuncAttributeMaxDynamicSharedMemorySize, GEMM_SMEM);
        cudaFuncSetAttribute(attn_kernel, cudaFuncAttributeMaxDynamicSharedMemorySize, ATTN_SMEM);
        cudaStreamCreateWithFlags(&s_side, cudaStreamNonBlocking);
        cudaEventCreateWithFlags(&ev_fork, cudaEventDisableTiming);
        cudaEventCreateWithFlags(&ev_join, cudaEventDisableTiming);
        attr_done = true;
    }

    float *p_qkv, *p_x2, *p_xn2;
    h16 *p_qh, *p_kh, *p_vh;
    h16 *p_xn1_h, *p_xn1_l, *p_attn_h, *p_xn2_h;
    h16 *p_wqkvt_h, *p_wprojt_h, *p_w1t, *p_w2t;
    cudaGetSymbolAddress((void**)&p_qkv,  g_qkv);
    cudaGetSymbolAddress((void**)&p_qh,   g_qh);
    cudaGetSymbolAddress((void**)&p_kh,   g_kh);
    cudaGetSymbolAddress((void**)&p_vh,   g_vh);
    cudaGetSymbolAddress((void**)&p_x2,   g_x2);
    cudaGetSymbolAddress((void**)&p_xn2,  g_xn2);
    cudaGetSymbolAddress((void**)&p_xn1_h, g_xn1_h);
    cudaGetSymbolAddress((void**)&p_xn1_l, g_xn1_l);
    cudaGetSymbolAddress((void**)&p_attn_h, g_attn_h);
    cudaGetSymbolAddress((void**)&p_xn2_h, g_xn2_h);
    cudaGetSymbolAddress((void**)&p_wqkvt_h, g_wqkvt_h);
    cudaGetSymbolAddress((void**)&p_wprojt_h, g_wprojt_h);
    cudaGetSymbolAddress((void**)&p_w1t, g_w1t);
    cudaGetSymbolAddress((void**)&p_w2t, g_w2t);

    zero_small_kernel<<<1, 32>>>();

    // fork: FFN weight conversion on side stream (overlaps attention chain)
    cudaEventRecord(ev_fork, 0);
    cudaStreamWaitEvent(s_side, ev_fork, 0);
    trans_conv<<<dim3(DFF / 32, DM / 32, NE), 256, 0, s_side>>>(w1, p_w1t, nullptr, DM, DFF);
    trans_conv<<<dim3(DM / 32, DFF / 32, NE), 256, 0, s_side>>>(w2, p_w2t, nullptr, DFF, DM);
    cudaEventRecord(ev_join, s_side);

    // main chain
    trans_conv<<<dim3(3 * DM / 32, DM / 32, 1), 256>>>(w_qkv, p_wqkvt_h, nullptr, DM, 3 * DM);
    trans_conv<<<dim3(DM / 32, DM / 32, 1), 256>>>(w_proj, p_wprojt_h, nullptr, DM, DM);
    ln_kernel<<<NTOK, 256>>>(x, ln1_g, ln1_b, nullptr, p_xn1_h, p_xn1_l);
    qkv_gemm<<<dim3(3 * DM / 128, NTOK / 128), 256, GEMM_SMEM>>>();
    rope_kernel<<<NTOK, 256>>>(p_qkv, p_qh, p_kh, p_vh);
    attn_kernel<<<NBH * (TT / 128), 256, ATTN_SMEM>>>(p_qh, p_kh, p_vh, p_attn_h);
    proj_gemm<<<dim3(DM / 128, NTOK / 128), 256, GEMM_SMEM>>>(b_proj, x);
    ln_kernel<<<NTOK, 256>>>(p_x2, ln2_g, ln2_b, p_xn2, p_xn2_h, nullptr);
    router_kernel<<<NTOK, 128>>>(p_xn2, w_router);
    scan_kernel<<<1, 1>>>();
    place_kernel<<<NSLOT / 256, 256>>>();

    // join before expert GEMMs
    cudaStreamWaitEvent(0, ev_join, 0);
    ffn1_gemm<<<dim3(DFF / 128, NSLOT / 128, NE), 256, GEMM_SMEM>>>(b1);
    ffn2_gemm<<<dim3(DM / 128, NSLOT / 128, NE), 256, GEMM_SMEM>>>(b2);
    combine_kernel<<<NTOK, 256>>>(out, out_size);
}

// round 9
// speedup vs baseline: 6.3614x; 1.0219x over previous
#include <cuda_runtime.h>
#include <cuda_fp16.h>
#include <math.h>
#include <stdint.h>

#define NTOK 4096      // B*T
#define DM   1024
#define NH   16
#define HD   64
#define NE   8
#define DFF  4096
#define NSLOT 8192     // NTOK * TOP_K
#define TT   1024
#define NBH  64        // B * NH

typedef __half h16;

// ===================== scratch (static device memory) ========================
__device__ h16   g_xn1_h [NTOK * DM];
__device__ float g_qkv   [NTOK * 3 * DM];
__device__ h16   g_qh    [NTOK * DM];   // [B,H,T,HD] fp16, pre-scaled 0.125
__device__ h16   g_kh    [NTOK * DM];
__device__ h16   g_vh    [NTOK * DM];
__device__ h16   g_attn_h[NTOK * DM];
__device__ float g_x2    [NTOK * DM];
__device__ float g_xn2   [NTOK * DM];
__device__ h16   g_xn2_h [NTOK * DM];
__device__ h16   g_hbuf  [(size_t)NSLOT * DFF];
__device__ float g_y     [NSLOT * DM];

// transposed weights ([N,K] K-major per expert)
__device__ h16 g_wqkvt_h[3 * DM * DM];
__device__ h16 g_wprojt_h[DM * DM];
__device__ h16 g_w1t[(size_t)NE * DFF * DM];
__device__ h16 g_w2t[(size_t)NE * DM * DFF];

__device__ int   g_cnt[NE];
__device__ int   g_off[NE];
__device__ int   g_cur[NE];
__device__ float g_probsum[NE];
__device__ int   g_top_i[NSLOT];
__device__ float g_top_w[NSLOT];
__device__ int   g_perm_tok[NSLOT];
__device__ float g_slot_gate[NSLOT];
__device__ int   g_slot_of[NSLOT];
__device__ float g_aux;

__device__ __forceinline__ uint32_t smem_u32(const void* p) {
    uint32_t a;
    asm("{ .reg .u64 t; cvta.to.shared.u64 t, %1; cvt.u32.u64 %0, t; }"
        : "=r"(a) : "l"(p));
    return a;
}
__device__ __forceinline__ void ldsm4(uint32_t* r, uint32_t addr) {
    asm volatile("ldmatrix.sync.aligned.m8n8.x4.shared.b16 {%0,%1,%2,%3}, [%4];"
                 : "=r"(r[0]), "=r"(r[1]), "=r"(r[2]), "=r"(r[3]) : "r"(addr));
}
__device__ __forceinline__ void ldsm4t(uint32_t* r, uint32_t addr) {
    asm volatile("ldmatrix.sync.aligned.m8n8.x4.trans.shared.b16 {%0,%1,%2,%3}, [%4];"
                 : "=r"(r[0]), "=r"(r[1]), "=r"(r[2]), "=r"(r[3]) : "r"(addr));
}
__device__ __forceinline__ void mma_f16(float* d, const uint32_t* a, const uint32_t* b) {
    asm volatile(
        "mma.sync.aligned.m16n8k16.row.col.f32.f16.f16.f32 "
        "{%0,%1,%2,%3}, {%4,%5,%6,%7}, {%8,%9}, {%0,%1,%2,%3};"
        : "+f"(d[0]), "+f"(d[1]), "+f"(d[2]), "+f"(d[3])
        : "r"(a[0]), "r"(a[1]), "r"(a[2]), "r"(a[3]), "r"(b[0]), "r"(b[1]));
}
__device__ __forceinline__ void cp_async16(uint32_t saddr, const void* g, uint32_t sz) {
    asm volatile("cp.async.cg.shared.global [%0], [%1], 16, %2;"
                 :: "r"(saddr), "l"(g), "r"(sz));
}
__device__ __forceinline__ void cp_commit() {
    asm volatile("cp.async.commit_group;");
}
template<int N> __device__ __forceinline__ void cp_wait() {
    asm volatile("cp.async.wait_group %0;" :: "n"(N));
}
__device__ __forceinline__ uint32_t sw128(uint32_t o) {
    return o ^ ((o >> 3) & 0x70u);
}
__device__ __forceinline__ uint32_t h2pack(float a, float b) {
    half2 h = __floats2half2_rn(a, b);
    return *(uint32_t*)&h;
}

// ===================== small helpers ====================
__global__ void zero_small_kernel() {
    int i = threadIdx.x;
    if (i < NE) { g_cnt[i] = 0; g_cur[i] = 0; g_probsum[i] = 0.f; }
}

// ---------------- transpose + convert: w[K,N] -> t[N,K] ----------------------
__global__ void __launch_bounds__(256) trans_conv(
    const float* __restrict__ w, h16* __restrict__ th, int K, int N)
{
    const size_t eoff = (size_t)blockIdx.z * K * N;
    const float* wp = w + eoff;
    h16* thp = th + eoff;
    __shared__ float t[32][33];
    int tx = threadIdx.x & 31, ty = threadIdx.x >> 5;
    int n0 = blockIdx.x * 32, k0 = blockIdx.y * 32;
    #pragma unroll
    for (int i = 0; i < 4; i++)
        t[ty + i * 8][tx] = wp[(size_t)(k0 + ty + i * 8) * N + n0 + tx];
    __syncthreads();
    #pragma unroll
    for (int i = 0; i < 4; i++) {
        float v = t[tx][ty + i * 8];
        int n = n0 + ty + i * 8, k = k0 + tx;
        thp[(size_t)n * K + k] = __float2half_rn(v);
    }
}

// ---------------- layernorm (256 thr/row) ----------------
__global__ void __launch_bounds__(256) ln_kernel(
    const float* __restrict__ x, const float* __restrict__ g,
    const float* __restrict__ b, float* __restrict__ o32,
    h16* __restrict__ oh)
{
    int row = blockIdx.x;
    const float* xr = x + (size_t)row * DM;
    float v[4]; float s = 0.f, ss = 0.f;
    #pragma unroll
    for (int i = 0; i < 4; i++) {
        float u = xr[threadIdx.x + i * 256];
        v[i] = u; s += u; ss += u * u;
    }
    #pragma unroll
    for (int ofs = 16; ofs > 0; ofs >>= 1) {
        s  += __shfl_xor_sync(0xffffffffu, s,  ofs);
        ss += __shfl_xor_sync(0xffffffffu, ss, ofs);
    }
    __shared__ float sh[2][8];
    int warp = threadIdx.x >> 5, lane = threadIdx.x & 31;
    if (lane == 0) { sh[0][warp] = s; sh[1][warp] = ss; }
    __syncthreads();
    float S = 0.f, SS = 0.f;
    #pragma unroll
    for (int w = 0; w < 8; w++) { S += sh[0][w]; SS += sh[1][w]; }
    float mu  = S * (1.0f / DM);
    float var = SS * (1.0f / DM) - mu * mu;
    float inv = rsqrtf(var + 1e-5f);
    #pragma unroll
    for (int i = 0; i < 4; i++) {
        int idx = threadIdx.x + i * 256;
        float o = (v[i] - mu) * inv * g[idx] + b[idx];
        size_t p = (size_t)row * DM + idx;
        if (o32) o32[p] = o;
        oh[p] = __float2half_rn(o);
    }
}

// ---------------- RoPE + layout transform -> fp16 q/k/v ----------------------
__global__ void __launch_bounds__(256) rope_kernel(
    const float* __restrict__ qkv, h16* __restrict__ q,
    h16* __restrict__ k, h16* __restrict__ v)
{
    int tok = blockIdx.x;
    int b = tok >> 10, t = tok & 1023;
    const float* row = qkv + (size_t)tok * (3 * DM);
    for (int i = threadIdx.x; i < DM; i += 256) {
        int h = i >> 6, d = i & 63;
        int f = d & 31;
        // 10000^(-f/32) = exp2(-f * log2(10000)/32)
        float freq = exp2f(-(float)f * 0.41524101186092029f);
        float ang = (float)t * freq;
        float sv, cv;
        __sincosf(ang, &sv, &cv);
        float qa = row[i], ka = row[DM + i];
        float qo, ko;
        if (d < 32) {
            qo = qa * cv - row[i + 32] * sv;
            ko = ka * cv - row[DM + i + 32] * sv;
        } else {
            qo = qa * cv + row[i - 32] * sv;
            ko = ka * cv + row[DM + i - 32] * sv;
        }
        int dst = ((b * NH + h) * TT + t) * HD + d;
        q[dst] = __float2half_rn(qo * 0.125f);
        k[dst] = __float2half_rn(ko);
        v[dst] = __float2half_rn(row[2 * DM + i]);
    }
}

// ---------------- tensor-core flash attention --------------------------------
#define ATTN_SMEM 49152
__global__ void __launch_bounds__(256, 2) attn_kernel(
    const h16* __restrict__ q, const h16* __restrict__ k,
    const h16* __restrict__ v, h16* __restrict__ oh)
{
    extern __shared__ char smem[];
    uint32_t sb = smem_u32(smem);
    const uint32_t SQ = 0, SKV = 16384, STG = 16384;

    int bh = blockIdx.x & (NBH - 1);
    int chunk = (TT / 128 - 1) - (blockIdx.x >> 6);
    int qb0 = chunk * 128;
    int tid = threadIdx.x, lane = tid & 31, w = tid >> 5;
    const h16* qb = q + (size_t)bh * TT * HD;
    const h16* kb = k + (size_t)bh * TT * HD;
    const h16* vb = v + (size_t)bh * TT * HD;

    for (int i = tid; i < 128 * 8; i += 256) {
        int r = i >> 3, ch = i & 7;
        uint32_t so = sw128((uint32_t)(r * 128 + ch * 16));
        *(uint4*)(smem + SQ + so) = *(const uint4*)(qb + (size_t)(qb0 + r) * HD + ch * 8);
    }

    auto load_kv = [&](int j0, int st) {
        uint32_t s0 = sb + SKV + (uint32_t)st * STG;
        #pragma unroll
        for (int i = 0; i < 2; i++) {
            int idx = tid + i * 256;
            int r = idx >> 3, ch = idx & 7;
            uint32_t so = sw128((uint32_t)(r * 128 + ch * 16));
            cp_async16(s0 + so, kb + (size_t)(j0 + r) * HD + ch * 8, 16);
            cp_async16(s0 + 8192 + so, vb + (size_t)(j0 + r) * HD + ch * 8, 16);
        }
        cp_commit();
    };
    load_kv(0, 0);
    __syncthreads();

    uint32_t qf[4][4];
    #pragma unroll
    for (int ks = 0; ks < 4; ks++) {
        int row = w * 16 + (lane & 15);
        uint32_t so = sw128((uint32_t)(row * 128 + ks * 32 + (lane >> 4) * 16));
        ldsm4(qf[ks], sb + SQ + so);
    }

    float oacc[8][4];
    #pragma unroll
    for (int i = 0; i < 8; i++)
        #pragma unroll
        for (int j = 0; j < 4; j++) oacc[i][j] = 0.f;
    float mrun[2] = {-1e30f, -1e30f}, lsum[2] = {0.f, 0.f};

    const int wrow = qb0 + w * 16 + (lane >> 2);
    const int wt_last = qb0 + w * 16 + 15;
    const int wt_first = qb0 + w * 16;
    const int ntiles = (qb0 + 128) / 64;

    for (int ti = 0; ti < ntiles; ti++) {
        int j0 = ti * 64;
        if (ti + 1 < ntiles) { load_kv(j0 + 64, (ti + 1) & 1); cp_wait<1>(); }
        else cp_wait<0>();
        __syncthreads();
        if (j0 <= wt_last) {
            uint32_t s0 = sb + SKV + (uint32_t)(ti & 1) * STG;
            float sacc[8][4];
            #pragma unroll
            for (int i = 0; i < 8; i++)
                #pragma unroll
                for (int j = 0; j < 4; j++) sacc[i][j] = 0.f;
            #pragma unroll
            for (int ks = 0; ks < 4; ks++) {
                #pragma unroll
                for (int n2 = 0; n2 < 4; n2++) {
                    int row = n2 * 16 + (lane & 15);
                    uint32_t so = sw128((uint32_t)(row * 128 + ks * 32 + (lane >> 4) * 16));
                    uint32_t t4[4]; ldsm4(t4, s0 + so);
                    uint32_t b0[2] = {t4[0], t4[2]}, b1[2] = {t4[1], t4[3]};
                    mma_f16(sacc[2 * n2], qf[ks], b0);
                    mma_f16(sacc[2 * n2 + 1], qf[ks], b1);
                }
            }
            if (j0 + 63 > wt_first) {
                #pragma unroll
                for (int nt = 0; nt < 8; nt++)
                    #pragma unroll
                    for (int r = 0; r < 4; r++) {
                        int col = j0 + 8 * nt + 2 * (lane & 3) + (r & 1);
                        int rowt = wrow + 8 * (r >> 1);
                        if (col > rowt) sacc[nt][r] = -1e30f;
                    }
            }
            float psc[2];
            #pragma unroll
            for (int hh = 0; hh < 2; hh++) {
                float mx = -1e30f;
                #pragma unroll
                for (int nt = 0; nt < 8; nt++) {
                    mx = fmaxf(mx, sacc[nt][2 * hh]);
                    mx = fmaxf(mx, sacc[nt][2 * hh + 1]);
                }
                mx = fmaxf(mx, __shfl_xor_sync(0xffffffffu, mx, 1));
                mx = fmaxf(mx, __shfl_xor_sync(0xffffffffu, mx, 2));
                float nm = fmaxf(mrun[hh], mx);
                float sc = __expf(mrun[hh] - nm);
                mrun[hh] = nm;
                float sum = 0.f;
                #pragma unroll
                for (int nt = 0; nt < 8; nt++) {
                    float p0 = __expf(sacc[nt][2 * hh] - nm);
                    float p1 = __expf(sacc[nt][2 * hh + 1] - nm);
                    sacc[nt][2 * hh] = p0; sacc[nt][2 * hh + 1] = p1;
                    sum += p0 + p1;
                }
                sum += __shfl_xor_sync(0xffffffffu, sum, 1);
                sum += __shfl_xor_sync(0xffffffffu, sum, 2);
                lsum[hh] = lsum[hh] * sc + sum;
                psc[hh] = sc;
            }
            #pragma unroll
            for (int nt = 0; nt < 8; nt++)
                #pragma unroll
                for (int r = 0; r < 4; r++)
                    oacc[nt][r] *= psc[r >> 1];
            uint32_t pf[4][4];
            #pragma unroll
            for (int kt = 0; kt < 4; kt++) {
                pf[kt][0] = h2pack(sacc[2 * kt][0], sacc[2 * kt][1]);
                pf[kt][1] = h2pack(sacc[2 * kt][2], sacc[2 * kt][3]);
                pf[kt][2] = h2pack(sacc[2 * kt + 1][0], sacc[2 * kt + 1][1]);
                pf[kt][3] = h2pack(sacc[2 * kt + 1][2], sacc[2 * kt + 1][3]);
            }
            uint32_t sv = s0 + 8192;
            int g = lane >> 3, rr = lane & 7;
            #pragma unroll
            for (int dp = 0; dp < 4; dp++) {
                #pragma unroll
                for (int kt = 0; kt < 4; kt++) {
                    int kvr = 16 * kt + 8 * (g & 1) + rr;
                    int dc = dp * 16 + 8 * (g >> 1);
                    uint32_t so = sw128((uint32_t)(kvr * 128 + dc * 2));
                    uint32_t t4[4]; ldsm4t(t4, sv + so);
                    uint32_t b0[2] = {t4[0], t4[1]}, b1[2] = {t4[2], t4[3]};
                    mma_f16(oacc[2 * dp], pf[kt], b0);
                    mma_f16(oacc[2 * dp + 1], pf[kt], b1);
                }
            }
        }
        __syncthreads();
    }
    int b = bh >> 4, hH = bh & 15;
    #pragma unroll
    for (int hh = 0; hh < 2; hh++) {
        float inv = 1.0f / lsum[hh];
        int t = wrow + 8 * hh;
        size_t op = ((size_t)(b * TT + t)) * DM + hH * HD;
        #pragma unroll
        for (int nt = 0; nt < 8; nt++) {
            int d = 8 * nt + 2 * (lane & 3);
            half2 hv = __floats2half2_rn(oacc[nt][2 * hh] * inv, oacc[nt][2 * hh + 1] * inv);
            *(half2*)(oh + op + d) = hv;
        }
    }
}

// ===================== 128x256 HMMA GEMM core ================================
// C[128 x 256] = A[128,K] x B[256,K]^T, fp16 single-term, fp32 accum.
// 256 threads = 8 warps (2 x 4), warp tile 64x64. K chunk 64, SW128 smem,
// 2-stage cp.async pipeline (stage = A 16KB + B 32KB = 48KB).
__device__ __forceinline__ void gemm256(
    uint32_t sb, float (*acc)[4],
    const h16* __restrict__ A, const h16* __restrict__ B,
    int K, const int* __restrict__ perm, int row_base, int valid, int n0)
{
    constexpr uint32_t T_B = 16384;
    constexpr uint32_t STAGE = 49152;
    const int tid = threadIdx.x, lane = tid & 31, wid = tid >> 5;
    const int wm = wid >> 2, wn = wid & 3;
    const int nkb = K >> 6;

    // A: 4 chunks/thread; B: 8 chunks/thread
    const int arow = tid >> 3, ach = tid & 7;
    uint32_t asz[4];
    size_t aoff[4];
    #pragma unroll
    for (int it = 0; it < 4; it++) {
        int row = arow + it * 32;
        asz[it] = (row < valid) ? 16u : 0u;
        int gra = (row < valid) ? (perm ? perm[row_base + row] : (row_base + row)) : 0;
        aoff[it] = (size_t)gra * K;
    }

    auto load_stage = [&](int kb) {
        uint32_t s0 = sb + (uint32_t)(kb & 1) * STAGE;
        int koff = kb * 64 + ach * 8;
        #pragma unroll
        for (int it = 0; it < 4; it++) {
            int row = arow + it * 32;
            uint32_t so = sw128((uint32_t)(row * 128 + ach * 16));
            cp_async16(s0 + so, A + aoff[it] + koff, asz[it]);
        }
        #pragma unroll
        for (int it = 0; it < 8; it++) {
            int row = arow + it * 32;
            uint32_t so = sw128((uint32_t)(row * 128 + ach * 16));
            cp_async16(s0 + T_B + so, B + (size_t)(n0 + row) * K + koff, 16u);
        }
        cp_commit();
    };

    load_stage(0);
    for (int kb = 0; kb < nkb; kb++) {
        if (kb + 1 < nkb) { load_stage(kb + 1); cp_wait<1>(); }
        else cp_wait<0>();
        __syncthreads();
        uint32_t s0 = sb + (uint32_t)(kb & 1) * STAGE;
        #pragma unroll
        for (int ks = 0; ks < 4; ks++) {
            uint32_t af[4][4];
            #pragma unroll
            for (int mt = 0; mt < 4; mt++) {
                int row = wm * 64 + mt * 16 + (lane & 15);
                uint32_t so = sw128((uint32_t)(row * 128 + ks * 32 + (lane >> 4) * 16));
                ldsm4(af[mt], s0 + so);
            }
            uint32_t bf[8][2];
            #pragma unroll
            for (int n2 = 0; n2 < 4; n2++) {
                int row = wn * 64 + n2 * 16 + (lane & 15);
                uint32_t so = sw128((uint32_t)(row * 128 + ks * 32 + (lane >> 4) * 16));
                uint32_t t4[4];
                ldsm4(t4, s0 + T_B + so);
                bf[n2 * 2][0] = t4[0]; bf[n2 * 2][1] = t4[2];
                bf[n2 * 2 + 1][0] = t4[1]; bf[n2 * 2 + 1][1] = t4[3];
            }
            #pragma unroll
            for (int mt = 0; mt < 4; mt++)
                #pragma unroll
                for (int nt = 0; nt < 8; nt++)
                    mma_f16(acc[mt * 8 + nt], af[mt], bf[nt]);
        }
        __syncthreads();
    }
}
// acc[mt*8+nt][r]: row = wm*64 + mt*16 + lane/4 + 8*(r>>1)
//                  col = wn*64 + nt*8  + 2*(lane&3) + (r&1)

#define GEMM_SMEM 98304
#define ACC_INIT float acc[32][4]; \
    _Pragma("unroll") for (int i = 0; i < 32; i++) \
    _Pragma("unroll") for (int j = 0; j < 4; j++) acc[i][j] = 0.f;

// ---------------- qkv = xn1 @ w_qkv ----------------
__global__ void __launch_bounds__(256, 1) qkv_gemm() {
    extern __shared__ char smem[];
    uint32_t sb = smem_u32(smem);
    ACC_INIT
    int m0 = blockIdx.y * 128, n0 = blockIdx.x * 256;
    gemm256(sb, acc, g_xn1_h, g_wqkvt_h, DM, nullptr, m0, 128, n0);
    int lane = threadIdx.x & 31, wid = threadIdx.x >> 5;
    int wm = wid >> 2, wn = wid & 3;
    #pragma unroll
    for (int mt = 0; mt < 4; mt++)
        #pragma unroll
        for (int nt = 0; nt < 8; nt++) {
            int r = m0 + wm * 64 + mt * 16 + (lane >> 2);
            int c = n0 + wn * 64 + nt * 8 + 2 * (lane & 3);
            float* d = acc[mt * 8 + nt];
            float* p0 = g_qkv + (size_t)r * (3 * DM) + c;
            p0[0] = d[0]; p0[1] = d[1];
            float* p1 = g_qkv + (size_t)(r + 8) * (3 * DM) + c;
            p1[0] = d[2]; p1[1] = d[3];
        }
}

// ---------------- x2 = attn @ w_proj + b_proj + x ----------------
__global__ void __launch_bounds__(256, 1) proj_gemm(
    const float* __restrict__ bias, const float* __restrict__ resid)
{
    extern __shared__ char smem[];
    uint32_t sb = smem_u32(smem);
    ACC_INIT
    int m0 = blockIdx.y * 128, n0 = blockIdx.x * 256;
    gemm256(sb, acc, g_attn_h, g_wprojt_h, DM, nullptr, m0, 128, n0);
    int lane = threadIdx.x & 31, wid = threadIdx.x >> 5;
    int wm = wid >> 2, wn = wid & 3;
    #pragma unroll
    for (int mt = 0; mt < 4; mt++)
        #pragma unroll
        for (int nt = 0; nt < 8; nt++) {
            int r = m0 + wm * 64 + mt * 16 + (lane >> 2);
            int c = n0 + wn * 64 + nt * 8 + 2 * (lane & 3);
            float* d = acc[mt * 8 + nt];
            size_t p0 = (size_t)r * DM + c;
            size_t p1 = (size_t)(r + 8) * DM + c;
            g_x2[p0]     = d[0] + bias[c]     + resid[p0];
            g_x2[p0 + 1] = d[1] + bias[c + 1] + resid[p0 + 1];
            g_x2[p1]     = d[2] + bias[c]     + resid[p1];
            g_x2[p1 + 1] = d[3] + bias[c + 1] + resid[p1 + 1];
        }
}

// ---------------- h = gelu(gather(xn2) @ w1[e] + b1[e]) ----------------------
__global__ void __launch_bounds__(256, 1) ffn1_gemm(const float* __restrict__ B1) {
    int e = blockIdx.z;
    int cnt = g_cnt[e];
    int r0 = blockIdx.y * 128;
    if (r0 >= cnt) return;
    extern __shared__ char smem[];
    uint32_t sb = smem_u32(smem);
    ACC_INIT
    int off = g_off[e];
    int n0 = blockIdx.x * 256;
    int valid = cnt - r0; if (valid > 128) valid = 128;
    gemm256(sb, acc, g_xn2_h, g_w1t + (size_t)e * DFF * DM,
            DM, g_perm_tok, off + r0, valid, n0);
    int lane = threadIdx.x & 31, wid = threadIdx.x >> 5;
    int wm = wid >> 2, wn = wid & 3;
    const float* bias = B1 + e * DFF;
    #pragma unroll
    for (int mt = 0; mt < 4; mt++)
        #pragma unroll
        for (int nt = 0; nt < 8; nt++) {
            int rl = wm * 64 + mt * 16 + (lane >> 2);
            int c = n0 + wn * 64 + nt * 8 + 2 * (lane & 3);
            float* d = acc[mt * 8 + nt];
            #pragma unroll
            for (int half = 0; half < 2; half++) {
                int row = rl + half * 8;
                if (row >= valid) continue;
                size_t rp = (size_t)(off + r0 + row) * DFF + c;
                #pragma unroll
                for (int u = 0; u < 2; u++) {
                    float v = d[half * 2 + u] + bias[c + u];
                    v = 0.5f * v * (1.0f + erff(v * 0.70710678118654752f));
                    g_hbuf[rp + u] = __float2half_rn(v);
                }
            }
        }
}

// ---------------- y = h @ w2[e] + b2[e] ----------------
__global__ void __launch_bounds__(256, 1) ffn2_gemm(const float* __restrict__ B2) {
    int e = blockIdx.z;
    int cnt = g_cnt[e];
    int r0 = blockIdx.y * 128;
    if (r0 >= cnt) return;
    extern __shared__ char smem[];
    uint32_t sb = smem_u32(smem);
    ACC_INIT
    int off = g_off[e];
    int n0 = blockIdx.x * 256;
    int valid = cnt - r0; if (valid > 128) valid = 128;
    gemm256(sb, acc, g_hbuf, g_w2t + (size_t)e * DM * DFF,
            DFF, nullptr, off + r0, valid, n0);
    int lane = threadIdx.x & 31, wid = threadIdx.x >> 5;
    int wm = wid >> 2, wn = wid & 3;
    const float* bias = B2 + e * DM;
    #pragma unroll
    for (int mt = 0; mt < 4; mt++)
        #pragma unroll
        for (int nt = 0; nt < 8; nt++) {
            int rl = wm * 64 + mt * 16 + (lane >> 2);
            int c = n0 + wn * 64 + nt * 8 + 2 * (lane & 3);
            float* d = acc[mt * 8 + nt];
            #pragma unroll
            for (int half = 0; half < 2; half++) {
                int row = rl + half * 8;
                if (row >= valid) continue;
                size_t rp = (size_t)(off + r0 + row) * DM + c;
                g_y[rp]     = d[half * 2]     + bias[c];
                g_y[rp + 1] = d[half * 2 + 1] + bias[c + 1];
            }
        }
}

// ---------------- router ----------------
__global__ void __launch_bounds__(128) router_kernel(
    const float* __restrict__ xn2, const float* __restrict__ wr)
{
    int tok = blockIdx.x, tid = threadIdx.x;
    const float* xr = xn2 + (size_t)tok * DM;
    float p[NE];
    #pragma unroll
    for (int e = 0; e < NE; e++) p[e] = 0.f;
    for (int i = tid; i < DM; i += 128) {
        float xv = xr[i];
        const float* w = wr + i * NE;
        #pragma unroll
        for (int e = 0; e < NE; e++) p[e] += xv * w[e];
    }
    __shared__ float red[NE][128];
    #pragma unroll
    for (int e = 0; e < NE; e++) red[e][tid] = p[e];
    __syncthreads();
    for (int st = 64; st > 0; st >>= 1) {
        if (tid < st) {
            #pragma unroll
            for (int e = 0; e < NE; e++) red[e][tid] += red[e][tid + st];
        }
        __syncthreads();
    }
    if (tid == 0) {
        float lg[NE], mx = -1e30f;
        #pragma unroll
        for (int e = 0; e < NE; e++) { lg[e] = red[e][0]; mx = fmaxf(mx, lg[e]); }
        float se = 0.f, pr[NE];
        #pragma unroll
        for (int e = 0; e < NE; e++) { pr[e] = __expf(lg[e] - mx); se += pr[e]; }
        float inv = 1.0f / se;
        #pragma unroll
        for (int e = 0; e < NE; e++) {
            pr[e] *= inv;
            atomicAdd(&g_probsum[e], pr[e]);
        }
        int i0 = 0;
        #pragma unroll
        for (int e = 1; e < NE; e++) if (pr[e] > pr[i0]) i0 = e;
        int i1 = (i0 == 0) ? 1 : 0;
        #pragma unroll
        for (int e = 0; e < NE; e++) if (e != i0 && pr[e] > pr[i1]) i1 = e;
        float w0 = pr[i0], w1 = pr[i1], sw = 1.0f / (w0 + w1);
        g_top_i[tok * 2] = i0; g_top_i[tok * 2 + 1] = i1;
        g_top_w[tok * 2] = w0 * sw; g_top_w[tok * 2 + 1] = w1 * sw;
        atomicAdd(&g_cnt[i0], 1);
        atomicAdd(&g_cnt[i1], 1);
    }
}

__global__ void scan_kernel() {
    if (threadIdx.x == 0 && blockIdx.x == 0) {
        int o = 0;
        float aux = 0.f;
        for (int e = 0; e < NE; e++) { g_off[e] = o; o += g_cnt[e]; }
        for (int e = 0; e < NE; e++)
            aux += ((float)g_cnt[e] / (float)(NTOK * 2)) * (g_probsum[e] / (float)NTOK);
        g_aux = (float)NE * aux;
    }
}

__global__ void place_kernel() {
    int s = blockIdx.x * 256 + threadIdx.x;
    if (s >= NSLOT) return;
    int tok = s >> 1;
    int e = g_top_i[s];
    float w = g_top_w[s];
    int pos = atomicAdd(&g_cur[e], 1);
    int slot = g_off[e] + pos;
    g_perm_tok[slot] = tok;
    g_slot_gate[slot] = w;
    g_slot_of[s] = slot;
}

// ---------------- final combine ----------------
__global__ void __launch_bounds__(256) combine_kernel(float* __restrict__ out, int out_size)
{
    int tok = blockIdx.x;
    int s0 = g_slot_of[tok * 2], s1 = g_slot_of[tok * 2 + 1];
    float w0 = g_slot_gate[s0], w1 = g_slot_gate[s1];
    const float* y0 = g_y + (size_t)s0 * DM;
    const float* y1 = g_y + (size_t)s1 * DM;
    const float* xr = g_x2 + (size_t)tok * DM;
    float* orow = out + (size_t)tok * DM;
    #pragma unroll
    for (int l = 0; l < 4; l++) {
        int i = threadIdx.x + l * 256;
        orow[i] = xr[i] + w0 * y0[i] + w1 * y1[i];
    }
    if (tok == 0 && threadIdx.x == 0 && out_size > NTOK * DM)
        out[NTOK * DM] = g_aux;
}

// ===================== launch =====================
extern "C" void kernel_launch(void* const* d_in, const int* in_sizes, int n_in,
                              void* d_out, int out_size)
{
    const float* x        = (const float*)d_in[0];
    const float* ln1_g    = (const float*)d_in[2];
    const float* ln1_b    = (const float*)d_in[3];
    const float* w_qkv    = (const float*)d_in[4];
    const float* w_proj   = (const float*)d_in[5];
    const float* b_proj   = (const float*)d_in[6];
    const float* ln2_g    = (const float*)d_in[7];
    const float* ln2_b    = (const float*)d_in[8];
    const float* w_router = (const float*)d_in[9];
    const float* w1       = (const float*)d_in[10];
    const float* b1       = (const float*)d_in[11];
    const float* w2       = (const float*)d_in[12];
    const float* b2       = (const float*)d_in[13];
    float* out = (float*)d_out;

    static cudaStream_t s_side = nullptr;
    static cudaEvent_t ev_fork = nullptr, ev_join = nullptr;
    static bool attr_done = false;
    if (!attr_done) {
        cudaFuncSetAttribute(qkv_gemm,  cudaFuncAttributeMaxDynamicSharedMemorySize, GEMM_SMEM);
        cudaFuncSetAttribute(proj_gemm, cudaFuncAttributeMaxDynamicSharedMemorySize, GEMM_SMEM);
        cudaFuncSetAttribute(ffn1_gemm, cudaFuncAttributeMaxDynamicSharedMemorySize, GEMM_SMEM);
        cudaFuncSetAttribute(ffn2_gemm, cudaFuncAttributeMaxDynamicSharedMemorySize, GEMM_SMEM);
        cudaFuncSetAttribute(attn_kernel, cudaFuncAttributeMaxDynamicSharedMemorySize, ATTN_SMEM);
        cudaStreamCreateWithFlags(&s_side, cudaStreamNonBlocking);
        cudaEventCreateWithFlags(&ev_fork, cudaEventDisableTiming);
        cudaEventCreateWithFlags(&ev_join, cudaEventDisableTiming);
        attr_done = true;
    }

    float *p_qkv, *p_x2, *p_xn2;
    h16 *p_qh, *p_kh, *p_vh;
    h16 *p_xn1_h, *p_attn_h, *p_xn2_h;
    h16 *p_wqkvt_h, *p_wprojt_h, *p_w1t, *p_w2t;
    cudaGetSymbolAddress((void**)&p_qkv,  g_qkv);
    cudaGetSymbolAddress((void**)&p_qh,   g_qh);
    cudaGetSymbolAddress((void**)&p_kh,   g_kh);
    cudaGetSymbolAddress((void**)&p_vh,   g_vh);
    cudaGetSymbolAddress((void**)&p_x2,   g_x2);
    cudaGetSymbolAddress((void**)&p_xn2,  g_xn2);
    cudaGetSymbolAddress((void**)&p_xn1_h, g_xn1_h);
    cudaGetSymbolAddress((void**)&p_attn_h, g_attn_h);
    cudaGetSymbolAddress((void**)&p_xn2_h, g_xn2_h);
    cudaGetSymbolAddress((void**)&p_wqkvt_h, g_wqkvt_h);
    cudaGetSymbolAddress((void**)&p_wprojt_h, g_wprojt_h);
    cudaGetSymbolAddress((void**)&p_w1t, g_w1t);
    cudaGetSymbolAddress((void**)&p_w2t, g_w2t);

    zero_small_kernel<<<1, 32>>>();

    // fork: FFN weight conversion on side stream (overlaps attention chain)
    cudaEventRecord(ev_fork, 0);
    cudaStreamWaitEvent(s_side, ev_fork, 0);
    trans_conv<<<dim3(DFF / 32, DM / 32, NE), 256, 0, s_side>>>(w1, p_w1t, DM, DFF);
    trans_conv<<<dim3(DM / 32, DFF / 32, NE), 256, 0, s_side>>>(w2, p_w2t, DFF, DM);
    cudaEventRecord(ev_join, s_side);

    // main chain
    trans_conv<<<dim3(3 * DM / 32, DM / 32, 1), 256>>>(w_qkv, p_wqkvt_h, DM, 3 * DM);
    trans_conv<<<dim3(DM / 32, DM / 32, 1), 256>>>(w_proj, p_wprojt_h, DM, DM);
    ln_kernel<<<NTOK, 256>>>(x, ln1_g, ln1_b, nullptr, p_xn1_h);
    qkv_gemm<<<dim3(3 * DM / 256, NTOK / 128), 256, GEMM_SMEM>>>();
    rope_kernel<<<NTOK, 256>>>(p_qkv, p_qh, p_kh, p_vh);
    attn_kernel<<<NBH * (TT / 128), 256, ATTN_SMEM>>>(p_qh, p_kh, p_vh, p_attn_h);
    proj_gemm<<<dim3(DM / 256, NTOK / 128), 256, GEMM_SMEM>>>(b_proj, x);
    ln_kernel<<<NTOK, 256>>>(p_x2, ln2_g, ln2_b, p_xn2, p_xn2_h);
    router_kernel<<<NTOK, 128>>>(p_xn2, w_router);
    scan_kernel<<<1, 1>>>();
    place_kernel<<<NSLOT / 256, 256>>>();

    // join before expert GEMMs
    cudaStreamWaitEvent(0, ev_join, 0);
    ffn1_gemm<<<dim3(DFF / 256, NSLOT / 128, NE), 256, GEMM_SMEM>>>(b1);
    ffn2_gemm<<<dim3(DM / 256, NSLOT / 128, NE), 256, GEMM_SMEM>>>(b2);
    combine_kernel<<<NTOK, 256>>>(out, out_size);
}

// round 10
// speedup vs baseline: 6.3986x; 1.0058x over previous
#include <cuda_runtime.h>
#include <cuda_fp16.h>
#include <math.h>
#include <stdint.h>

#define NTOK 4096      // B*T
#define DM   1024
#define NH   16
#define HD   64
#define NE   8
#define DFF  4096
#define NSLOT 8192     // NTOK * TOP_K
#define TT   1024
#define NBH  64        // B * NH

typedef __half h16;

// ===================== scratch (static device memory) ========================
__device__ h16    g_xn1_h [NTOK * DM];
__device__ float  g_qkv   [NTOK * 3 * DM];
__device__ h16    g_qh    [NTOK * DM];   // [B,H,T,HD] fp16, pre-scaled 0.125
__device__ h16    g_kh    [NTOK * DM];
__device__ h16    g_vh    [NTOK * DM];
__device__ h16    g_attn_h[NTOK * DM];
__device__ float  g_x2    [NTOK * DM];
__device__ h16    g_xn2_h [NTOK * DM];
__device__ h16    g_hbuf  [(size_t)NSLOT * DFF];
__device__ float  g_y     [NSLOT * DM];
__device__ float2 g_rope_tab[TT * 32];

// transposed weights ([N,K] K-major per expert)
__device__ h16 g_wqkvt_h[3 * DM * DM];
__device__ h16 g_wprojt_h[DM * DM];
__device__ h16 g_w1t[(size_t)NE * DFF * DM];
__device__ h16 g_w2t[(size_t)NE * DM * DFF];

__device__ int   g_cnt[NE];
__device__ int   g_off[NE];
__device__ int   g_cur[NE];
__device__ float g_probsum[NE];
__device__ int   g_top_i[NSLOT];
__device__ float g_top_w[NSLOT];
__device__ int   g_perm_tok[NSLOT];
__device__ float g_slot_gate[NSLOT];
__device__ int   g_slot_of[NSLOT];
__device__ float g_aux;

__device__ __forceinline__ uint32_t smem_u32(const void* p) {
    uint32_t a;
    asm("{ .reg .u64 t; cvta.to.shared.u64 t, %1; cvt.u32.u64 %0, t; }"
        : "=r"(a) : "l"(p));
    return a;
}
__device__ __forceinline__ void ldsm4(uint32_t* r, uint32_t addr) {
    asm volatile("ldmatrix.sync.aligned.m8n8.x4.shared.b16 {%0,%1,%2,%3}, [%4];"
                 : "=r"(r[0]), "=r"(r[1]), "=r"(r[2]), "=r"(r[3]) : "r"(addr));
}
__device__ __forceinline__ void ldsm4t(uint32_t* r, uint32_t addr) {
    asm volatile("ldmatrix.sync.aligned.m8n8.x4.trans.shared.b16 {%0,%1,%2,%3}, [%4];"
                 : "=r"(r[0]), "=r"(r[1]), "=r"(r[2]), "=r"(r[3]) : "r"(addr));
}
__device__ __forceinline__ void mma_f16(float* d, const uint32_t* a, const uint32_t* b) {
    asm volatile(
        "mma.sync.aligned.m16n8k16.row.col.f32.f16.f16.f32 "
        "{%0,%1,%2,%3}, {%4,%5,%6,%7}, {%8,%9}, {%0,%1,%2,%3};"
        : "+f"(d[0]), "+f"(d[1]), "+f"(d[2]), "+f"(d[3])
        : "r"(a[0]), "r"(a[1]), "r"(a[2]), "r"(a[3]), "r"(b[0]), "r"(b[1]));
}
__device__ __forceinline__ void cp_async16(uint32_t saddr, const void* g, uint32_t sz) {
    asm volatile("cp.async.cg.shared.global [%0], [%1], 16, %2;"
                 :: "r"(saddr), "l"(g), "r"(sz));
}
__device__ __forceinline__ void cp_commit() {
    asm volatile("cp.async.commit_group;");
}
template<int N> __device__ __forceinline__ void cp_wait() {
    asm volatile("cp.async.wait_group %0;" :: "n"(N));
}
__device__ __forceinline__ uint32_t sw128(uint32_t o) {
    return o ^ ((o >> 3) & 0x70u);
}
__device__ __forceinline__ uint32_t h2pack(float a, float b) {
    half2 h = __floats2half2_rn(a, b);
    return *(uint32_t*)&h;
}

// ===================== small helpers ====================
__global__ void zero_small_kernel() {
    int i = threadIdx.x;
    if (i < NE) { g_cnt[i] = 0; g_cur[i] = 0; g_probsum[i] = 0.f; }
}

// rope sincos table: tab[t*32+f] = (cos, sin)(t * 10000^(-f/32))
__global__ void __launch_bounds__(256) rope_tab_kernel() {
    int idx = blockIdx.x * 256 + threadIdx.x;   // [0, TT*32)
    int t = idx >> 5, f = idx & 31;
    float freq = exp2f(-(float)f * 0.41524101186092029f);
    float sv, cv;
    __sincosf((float)t * freq, &sv, &cv);
    g_rope_tab[idx] = make_float2(cv, sv);
}

// ---------------- transpose + convert: w[K,N] -> t[N,K] ----------------------
__global__ void __launch_bounds__(256) trans_conv(
    const float* __restrict__ w, h16* __restrict__ th, int K, int N)
{
    const size_t eoff = (size_t)blockIdx.z * K * N;
    const float* wp = w + eoff;
    h16* thp = th + eoff;
    __shared__ float t[32][33];
    int tx = threadIdx.x & 31, ty = threadIdx.x >> 5;
    int n0 = blockIdx.x * 32, k0 = blockIdx.y * 32;
    #pragma unroll
    for (int i = 0; i < 4; i++)
        t[ty + i * 8][tx] = wp[(size_t)(k0 + ty + i * 8) * N + n0 + tx];
    __syncthreads();
    #pragma unroll
    for (int i = 0; i < 4; i++) {
        float v = t[tx][ty + i * 8];
        int n = n0 + ty + i * 8, k = k0 + tx;
        thp[(size_t)n * K + k] = __float2half_rn(v);
    }
}

// ---------------- layernorm (256 thr/row) ----------------
__global__ void __launch_bounds__(256) ln_kernel(
    const float* __restrict__ x, const float* __restrict__ g,
    const float* __restrict__ b, h16* __restrict__ oh)
{
    int row = blockIdx.x;
    const float* xr = x + (size_t)row * DM;
    float v[4]; float s = 0.f, ss = 0.f;
    #pragma unroll
    for (int i = 0; i < 4; i++) {
        float u = xr[threadIdx.x + i * 256];
        v[i] = u; s += u; ss += u * u;
    }
    #pragma unroll
    for (int ofs = 16; ofs > 0; ofs >>= 1) {
        s  += __shfl_xor_sync(0xffffffffu, s,  ofs);
        ss += __shfl_xor_sync(0xffffffffu, ss, ofs);
    }
    __shared__ float sh[2][8];
    int warp = threadIdx.x >> 5, lane = threadIdx.x & 31;
    if (lane == 0) { sh[0][warp] = s; sh[1][warp] = ss; }
    __syncthreads();
    float S = 0.f, SS = 0.f;
    #pragma unroll
    for (int w = 0; w < 8; w++) { S += sh[0][w]; SS += sh[1][w]; }
    float mu  = S * (1.0f / DM);
    float var = SS * (1.0f / DM) - mu * mu;
    float inv = rsqrtf(var + 1e-5f);
    #pragma unroll
    for (int i = 0; i < 4; i++) {
        int idx = threadIdx.x + i * 256;
        float o = (v[i] - mu) * inv * g[idx] + b[idx];
        oh[(size_t)row * DM + idx] = __float2half_rn(o);
    }
}

// ---------------- fused ln2 + router (one block per token) -------------------
__global__ void __launch_bounds__(256) ln2_router_kernel(
    const float* __restrict__ x, const float* __restrict__ g,
    const float* __restrict__ b, h16* __restrict__ oh,
    const float* __restrict__ wr)
{
    int row = blockIdx.x, tid = threadIdx.x;
    const float* xr = x + (size_t)row * DM;
    float v[4]; float s = 0.f, ss = 0.f;
    #pragma unroll
    for (int i = 0; i < 4; i++) {
        float u = xr[tid + i * 256];
        v[i] = u; s += u; ss += u * u;
    }
    #pragma unroll
    for (int ofs = 16; ofs > 0; ofs >>= 1) {
        s  += __shfl_xor_sync(0xffffffffu, s,  ofs);
        ss += __shfl_xor_sync(0xffffffffu, ss, ofs);
    }
    __shared__ float sh[2][8];
    int warp = tid >> 5, lane = tid & 31;
    if (lane == 0) { sh[0][warp] = s; sh[1][warp] = ss; }
    __syncthreads();
    float S = 0.f, SS = 0.f;
    #pragma unroll
    for (int w = 0; w < 8; w++) { S += sh[0][w]; SS += sh[1][w]; }
    float mu  = S * (1.0f / DM);
    float var = SS * (1.0f / DM) - mu * mu;
    float inv = rsqrtf(var + 1e-5f);
    float pe[NE];
    #pragma unroll
    for (int e = 0; e < NE; e++) pe[e] = 0.f;
    #pragma unroll
    for (int i = 0; i < 4; i++) {
        int idx = tid + i * 256;
        float o = (v[i] - mu) * inv * g[idx] + b[idx];
        oh[(size_t)row * DM + idx] = __float2half_rn(o);
        const float* w = wr + idx * NE;
        #pragma unroll
        for (int e = 0; e < NE; e++) pe[e] += o * w[e];
    }
    __shared__ float red[NE][256];
    #pragma unroll
    for (int e = 0; e < NE; e++) red[e][tid] = pe[e];
    __syncthreads();
    for (int st = 128; st > 0; st >>= 1) {
        if (tid < st) {
            #pragma unroll
            for (int e = 0; e < NE; e++) red[e][tid] += red[e][tid + st];
        }
        __syncthreads();
    }
    if (tid == 0) {
        float lg[NE], mx = -1e30f;
        #pragma unroll
        for (int e = 0; e < NE; e++) { lg[e] = red[e][0]; mx = fmaxf(mx, lg[e]); }
        float se = 0.f, pr[NE];
        #pragma unroll
        for (int e = 0; e < NE; e++) { pr[e] = __expf(lg[e] - mx); se += pr[e]; }
        float invs = 1.0f / se;
        #pragma unroll
        for (int e = 0; e < NE; e++) {
            pr[e] *= invs;
            atomicAdd(&g_probsum[e], pr[e]);
        }
        int i0 = 0;
        #pragma unroll
        for (int e = 1; e < NE; e++) if (pr[e] > pr[i0]) i0 = e;
        int i1 = (i0 == 0) ? 1 : 0;
        #pragma unroll
        for (int e = 0; e < NE; e++) if (e != i0 && pr[e] > pr[i1]) i1 = e;
        float w0 = pr[i0], w1 = pr[i1], sw = 1.0f / (w0 + w1);
        g_top_i[row * 2] = i0; g_top_i[row * 2 + 1] = i1;
        g_top_w[row * 2] = w0 * sw; g_top_w[row * 2 + 1] = w1 * sw;
        atomicAdd(&g_cnt[i0], 1);
        atomicAdd(&g_cnt[i1], 1);
    }
}

// ---------------- RoPE + layout transform -> fp16 q/k/v (table) --------------
__global__ void __launch_bounds__(256) rope_kernel(
    const float* __restrict__ qkv, h16* __restrict__ q,
    h16* __restrict__ k, h16* __restrict__ v)
{
    int tok = blockIdx.x;
    int b = tok >> 10, t = tok & 1023;
    const float* row = qkv + (size_t)tok * (3 * DM);
    const float2* tab = g_rope_tab + t * 32;
    for (int i = threadIdx.x; i < DM; i += 256) {
        int h = i >> 6, d = i & 63;
        int f = d & 31;
        float2 cs = tab[f];
        float cv = cs.x, sv = cs.y;
        float qa = row[i], ka = row[DM + i];
        float qo, ko;
        if (d < 32) {
            qo = qa * cv - row[i + 32] * sv;
            ko = ka * cv - row[DM + i + 32] * sv;
        } else {
            qo = qa * cv + row[i - 32] * sv;
            ko = ka * cv + row[DM + i - 32] * sv;
        }
        int dst = ((b * NH + h) * TT + t) * HD + d;
        q[dst] = __float2half_rn(qo * 0.125f);
        k[dst] = __float2half_rn(ko);
        v[dst] = __float2half_rn(row[2 * DM + i]);
    }
}

// ---------------- tensor-core flash attention --------------------------------
#define ATTN_SMEM 49152
__global__ void __launch_bounds__(256, 2) attn_kernel(
    const h16* __restrict__ q, const h16* __restrict__ k,
    const h16* __restrict__ v, h16* __restrict__ oh)
{
    extern __shared__ char smem[];
    uint32_t sb = smem_u32(smem);
    const uint32_t SQ = 0, SKV = 16384, STG = 16384;

    int bh = blockIdx.x & (NBH - 1);
    int chunk = (TT / 128 - 1) - (blockIdx.x >> 6);
    int qb0 = chunk * 128;
    int tid = threadIdx.x, lane = tid & 31, w = tid >> 5;
    const h16* qb = q + (size_t)bh * TT * HD;
    const h16* kb = k + (size_t)bh * TT * HD;
    const h16* vb = v + (size_t)bh * TT * HD;

    for (int i = tid; i < 128 * 8; i += 256) {
        int r = i >> 3, ch = i & 7;
        uint32_t so = sw128((uint32_t)(r * 128 + ch * 16));
        *(uint4*)(smem + SQ + so) = *(const uint4*)(qb + (size_t)(qb0 + r) * HD + ch * 8);
    }

    auto load_kv = [&](int j0, int st) {
        uint32_t s0 = sb + SKV + (uint32_t)st * STG;
        #pragma unroll
        for (int i = 0; i < 2; i++) {
            int idx = tid + i * 256;
            int r = idx >> 3, ch = idx & 7;
            uint32_t so = sw128((uint32_t)(r * 128 + ch * 16));
            cp_async16(s0 + so, kb + (size_t)(j0 + r) * HD + ch * 8, 16);
            cp_async16(s0 + 8192 + so, vb + (size_t)(j0 + r) * HD + ch * 8, 16);
        }
        cp_commit();
    };
    load_kv(0, 0);
    __syncthreads();

    uint32_t qf[4][4];
    #pragma unroll
    for (int ks = 0; ks < 4; ks++) {
        int row = w * 16 + (lane & 15);
        uint32_t so = sw128((uint32_t)(row * 128 + ks * 32 + (lane >> 4) * 16));
        ldsm4(qf[ks], sb + SQ + so);
    }

    float oacc[8][4];
    #pragma unroll
    for (int i = 0; i < 8; i++)
        #pragma unroll
        for (int j = 0; j < 4; j++) oacc[i][j] = 0.f;
    float mrun[2] = {-1e30f, -1e30f}, lsum[2] = {0.f, 0.f};

    const int wrow = qb0 + w * 16 + (lane >> 2);
    const int wt_last = qb0 + w * 16 + 15;
    const int wt_first = qb0 + w * 16;
    const int ntiles = (qb0 + 128) / 64;

    for (int ti = 0; ti < ntiles; ti++) {
        int j0 = ti * 64;
        if (ti + 1 < ntiles) { load_kv(j0 + 64, (ti + 1) & 1); cp_wait<1>(); }
        else cp_wait<0>();
        __syncthreads();
        if (j0 <= wt_last) {
            uint32_t s0 = sb + SKV + (uint32_t)(ti & 1) * STG;
            float sacc[8][4];
            #pragma unroll
            for (int i = 0; i < 8; i++)
                #pragma unroll
                for (int j = 0; j < 4; j++) sacc[i][j] = 0.f;
            #pragma unroll
            for (int ks = 0; ks < 4; ks++) {
                #pragma unroll
                for (int n2 = 0; n2 < 4; n2++) {
                    int row = n2 * 16 + (lane & 15);
                    uint32_t so = sw128((uint32_t)(row * 128 + ks * 32 + (lane >> 4) * 16));
                    uint32_t t4[4]; ldsm4(t4, s0 + so);
                    uint32_t b0[2] = {t4[0], t4[2]}, b1[2] = {t4[1], t4[3]};
                    mma_f16(sacc[2 * n2], qf[ks], b0);
                    mma_f16(sacc[2 * n2 + 1], qf[ks], b1);
                }
            }
            if (j0 + 63 > wt_first) {
                #pragma unroll
                for (int nt = 0; nt < 8; nt++)
                    #pragma unroll
                    for (int r = 0; r < 4; r++) {
                        int col = j0 + 8 * nt + 2 * (lane & 3) + (r & 1);
                        int rowt = wrow + 8 * (r >> 1);
                        if (col > rowt) sacc[nt][r] = -1e30f;
                    }
            }
            float psc[2];
            #pragma unroll
            for (int hh = 0; hh < 2; hh++) {
                float mx = -1e30f;
                #pragma unroll
                for (int nt = 0; nt < 8; nt++) {
                    mx = fmaxf(mx, sacc[nt][2 * hh]);
                    mx = fmaxf(mx, sacc[nt][2 * hh + 1]);
                }
                mx = fmaxf(mx, __shfl_xor_sync(0xffffffffu, mx, 1));
                mx = fmaxf(mx, __shfl_xor_sync(0xffffffffu, mx, 2));
                float nm = fmaxf(mrun[hh], mx);
                float sc = __expf(mrun[hh] - nm);
                mrun[hh] = nm;
                float sum = 0.f;
                #pragma unroll
                for (int nt = 0; nt < 8; nt++) {
                    float p0 = __expf(sacc[nt][2 * hh] - nm);
                    float p1 = __expf(sacc[nt][2 * hh + 1] - nm);
                    sacc[nt][2 * hh] = p0; sacc[nt][2 * hh + 1] = p1;
                    sum += p0 + p1;
                }
                sum += __shfl_xor_sync(0xffffffffu, sum, 1);
                sum += __shfl_xor_sync(0xffffffffu, sum, 2);
                lsum[hh] = lsum[hh] * sc + sum;
                psc[hh] = sc;
            }
            #pragma unroll
            for (int nt = 0; nt < 8; nt++)
                #pragma unroll
                for (int r = 0; r < 4; r++)
                    oacc[nt][r] *= psc[r >> 1];
            uint32_t pf[4][4];
            #pragma unroll
            for (int kt = 0; kt < 4; kt++) {
                pf[kt][0] = h2pack(sacc[2 * kt][0], sacc[2 * kt][1]);
                pf[kt][1] = h2pack(sacc[2 * kt][2], sacc[2 * kt][3]);
                pf[kt][2] = h2pack(sacc[2 * kt + 1][0], sacc[2 * kt + 1][1]);
                pf[kt][3] = h2pack(sacc[2 * kt + 1][2], sacc[2 * kt + 1][3]);
            }
            uint32_t sv = s0 + 8192;
            int g = lane >> 3, rr = lane & 7;
            #pragma unroll
            for (int dp = 0; dp < 4; dp++) {
                #pragma unroll
                for (int kt = 0; kt < 4; kt++) {
                    int kvr = 16 * kt + 8 * (g & 1) + rr;
                    int dc = dp * 16 + 8 * (g >> 1);
                    uint32_t so = sw128((uint32_t)(kvr * 128 + dc * 2));
                    uint32_t t4[4]; ldsm4t(t4, sv + so);
                    uint32_t b0[2] = {t4[0], t4[1]}, b1[2] = {t4[2], t4[3]};
                    mma_f16(oacc[2 * dp], pf[kt], b0);
                    mma_f16(oacc[2 * dp + 1], pf[kt], b1);
                }
            }
        }
        __syncthreads();
    }
    int b = bh >> 4, hH = bh & 15;
    #pragma unroll
    for (int hh = 0; hh < 2; hh++) {
        float inv = 1.0f / lsum[hh];
        int t = wrow + 8 * hh;
        size_t op = ((size_t)(b * TT + t)) * DM + hH * HD;
        #pragma unroll
        for (int nt = 0; nt < 8; nt++) {
            int d = 8 * nt + 2 * (lane & 3);
            half2 hv = __floats2half2_rn(oacc[nt][2 * hh] * inv, oacc[nt][2 * hh + 1] * inv);
            *(half2*)(oh + op + d) = hv;
        }
    }
}

// ===================== 128x256 HMMA GEMM core (4-stage) ======================
#define NSTG 4
__device__ __forceinline__ void gemm256(
    uint32_t sb, float (*acc)[4],
    const h16* __restrict__ A, const h16* __restrict__ B,
    int K, const int* __restrict__ perm, int row_base, int valid, int n0)
{
    constexpr uint32_t T_B = 16384;
    constexpr uint32_t STAGE = 49152;
    const int tid = threadIdx.x, lane = tid & 31, wid = tid >> 5;
    const int wm = wid >> 2, wn = wid & 3;
    const int nkb = K >> 6;

    const int arow = tid >> 3, ach = tid & 7;
    uint32_t asz[4];
    size_t aoff[4];
    #pragma unroll
    for (int it = 0; it < 4; it++) {
        int row = arow + it * 32;
        asz[it] = (row < valid) ? 16u : 0u;
        int gra = (row < valid) ? (perm ? perm[row_base + row] : (row_base + row)) : 0;
        aoff[it] = (size_t)gra * K;
    }

    auto load_stage = [&](int kb) {
        uint32_t s0 = sb + (uint32_t)(kb & (NSTG - 1)) * STAGE;
        int koff = kb * 64 + ach * 8;
        #pragma unroll
        for (int it = 0; it < 4; it++) {
            int row = arow + it * 32;
            uint32_t so = sw128((uint32_t)(row * 128 + ach * 16));
            cp_async16(s0 + so, A + aoff[it] + koff, asz[it]);
        }
        #pragma unroll
        for (int it = 0; it < 8; it++) {
            int row = arow + it * 32;
            uint32_t so = sw128((uint32_t)(row * 128 + ach * 16));
            cp_async16(s0 + T_B + so, B + (size_t)(n0 + row) * K + koff, 16u);
        }
        cp_commit();
    };

    #pragma unroll
    for (int s = 0; s < NSTG - 1; s++)
        if (s < nkb) load_stage(s);

    for (int kb = 0; kb < nkb; kb++) {
        if (kb + NSTG - 1 < nkb) { load_stage(kb + NSTG - 1); cp_wait<NSTG - 1>(); }
        else {
            int rem = nkb - 1 - kb;
            if (rem >= 2) cp_wait<2>();
            else if (rem == 1) cp_wait<1>();
            else cp_wait<0>();
        }
        __syncthreads();
        uint32_t s0 = sb + (uint32_t)(kb & (NSTG - 1)) * STAGE;
        #pragma unroll
        for (int ks = 0; ks < 4; ks++) {
            uint32_t af[4][4];
            #pragma unroll
            for (int mt = 0; mt < 4; mt++) {
                int row = wm * 64 + mt * 16 + (lane & 15);
                uint32_t so = sw128((uint32_t)(row * 128 + ks * 32 + (lane >> 4) * 16));
                ldsm4(af[mt], s0 + so);
            }
            uint32_t bf[8][2];
            #pragma unroll
            for (int n2 = 0; n2 < 4; n2++) {
                int row = wn * 64 + n2 * 16 + (lane & 15);
                uint32_t so = sw128((uint32_t)(row * 128 + ks * 32 + (lane >> 4) * 16));
                uint32_t t4[4];
                ldsm4(t4, s0 + T_B + so);
                bf[n2 * 2][0] = t4[0]; bf[n2 * 2][1] = t4[2];
                bf[n2 * 2 + 1][0] = t4[1]; bf[n2 * 2 + 1][1] = t4[3];
            }
            #pragma unroll
            for (int mt = 0; mt < 4; mt++)
                #pragma unroll
                for (int nt = 0; nt < 8; nt++)
                    mma_f16(acc[mt * 8 + nt], af[mt], bf[nt]);
        }
        __syncthreads();
    }
}
// acc[mt*8+nt][r]: row = wm*64 + mt*16 + lane/4 + 8*(r>>1)
//                  col = wn*64 + nt*8  + 2*(lane&3) + (r&1)

#define GEMM_SMEM 196608
#define ACC_INIT float acc[32][4]; \
    _Pragma("unroll") for (int i = 0; i < 32; i++) \
    _Pragma("unroll") for (int j = 0; j < 4; j++) acc[i][j] = 0.f;

// ---------------- qkv = xn1 @ w_qkv ----------------
__global__ void __launch_bounds__(256, 1) qkv_gemm() {
    extern __shared__ char smem[];
    uint32_t sb = smem_u32(smem);
    ACC_INIT
    int m0 = blockIdx.y * 128, n0 = blockIdx.x * 256;
    gemm256(sb, acc, g_xn1_h, g_wqkvt_h, DM, nullptr, m0, 128, n0);
    int lane = threadIdx.x & 31, wid = threadIdx.x >> 5;
    int wm = wid >> 2, wn = wid & 3;
    #pragma unroll
    for (int mt = 0; mt < 4; mt++)
        #pragma unroll
        for (int nt = 0; nt < 8; nt++) {
            int r = m0 + wm * 64 + mt * 16 + (lane >> 2);
            int c = n0 + wn * 64 + nt * 8 + 2 * (lane & 3);
            float* d = acc[mt * 8 + nt];
            float* p0 = g_qkv + (size_t)r * (3 * DM) + c;
            p0[0] = d[0]; p0[1] = d[1];
            float* p1 = g_qkv + (size_t)(r + 8) * (3 * DM) + c;
            p1[0] = d[2]; p1[1] = d[3];
        }
}

// ---------------- x2 = attn @ w_proj + b_proj + x ----------------
__global__ void __launch_bounds__(256, 1) proj_gemm(
    const float* __restrict__ bias, const float* __restrict__ resid)
{
    extern __shared__ char smem[];
    uint32_t sb = smem_u32(smem);
    ACC_INIT
    int m0 = blockIdx.y * 128, n0 = blockIdx.x * 256;
    gemm256(sb, acc, g_attn_h, g_wprojt_h, DM, nullptr, m0, 128, n0);
    int lane = threadIdx.x & 31, wid = threadIdx.x >> 5;
    int wm = wid >> 2, wn = wid & 3;
    #pragma unroll
    for (int mt = 0; mt < 4; mt++)
        #pragma unroll
        for (int nt = 0; nt < 8; nt++) {
            int r = m0 + wm * 64 + mt * 16 + (lane >> 2);
            int c = n0 + wn * 64 + nt * 8 + 2 * (lane & 3);
            float* d = acc[mt * 8 + nt];
            size_t p0 = (size_t)r * DM + c;
            size_t p1 = (size_t)(r + 8) * DM + c;
            g_x2[p0]     = d[0] + bias[c]     + resid[p0];
            g_x2[p0 + 1] = d[1] + bias[c + 1] + resid[p0 + 1];
            g_x2[p1]     = d[2] + bias[c]     + resid[p1];
            g_x2[p1 + 1] = d[3] + bias[c + 1] + resid[p1 + 1];
        }
}

// ---------------- h = gelu(gather(xn2) @ w1[e] + b1[e]) ----------------------
__global__ void __launch_bounds__(256, 1) ffn1_gemm(const float* __restrict__ B1) {
    int e = blockIdx.z;
    int cnt = g_cnt[e];
    int r0 = blockIdx.y * 128;
    if (r0 >= cnt) return;
    extern __shared__ char smem[];
    uint32_t sb = smem_u32(smem);
    ACC_INIT
    int off = g_off[e];
    int n0 = blockIdx.x * 256;
    int valid = cnt - r0; if (valid > 128) valid = 128;
    gemm256(sb, acc, g_xn2_h, g_w1t + (size_t)e * DFF * DM,
            DM, g_perm_tok, off + r0, valid, n0);
    int lane = threadIdx.x & 31, wid = threadIdx.x >> 5;
    int wm = wid >> 2, wn = wid & 3;
    const float* bias = B1 + e * DFF;
    #pragma unroll
    for (int mt = 0; mt < 4; mt++)
        #pragma unroll
        for (int nt = 0; nt < 8; nt++) {
            int rl = wm * 64 + mt * 16 + (lane >> 2);
            int c = n0 + wn * 64 + nt * 8 + 2 * (lane & 3);
            float* d = acc[mt * 8 + nt];
            #pragma unroll
            for (int half = 0; half < 2; half++) {
                int row = rl + half * 8;
                if (row >= valid) continue;
                size_t rp = (size_t)(off + r0 + row) * DFF + c;
                #pragma unroll
                for (int u = 0; u < 2; u++) {
                    float v = d[half * 2 + u] + bias[c + u];
                    v = 0.5f * v * (1.0f + erff(v * 0.70710678118654752f));
                    g_hbuf[rp + u] = __float2half_rn(v);
                }
            }
        }
}

// ---------------- y = h @ w2[e] + b2[e] ----------------
__global__ void __launch_bounds__(256, 1) ffn2_gemm(const float* __restrict__ B2) {
    int e = blockIdx.z;
    int cnt = g_cnt[e];
    int r0 = blockIdx.y * 128;
    if (r0 >= cnt) return;
    extern __shared__ char smem[];
    uint32_t sb = smem_u32(smem);
    ACC_INIT
    int off = g_off[e];
    int n0 = blockIdx.x * 256;
    int valid = cnt - r0; if (valid > 128) valid = 128;
    gemm256(sb, acc, g_hbuf, g_w2t + (size_t)e * DM * DFF,
            DFF, nullptr, off + r0, valid, n0);
    int lane = threadIdx.x & 31, wid = threadIdx.x >> 5;
    int wm = wid >> 2, wn = wid & 3;
    const float* bias = B2 + e * DM;
    #pragma unroll
    for (int mt = 0; mt < 4; mt++)
        #pragma unroll
        for (int nt = 0; nt < 8; nt++) {
            int rl = wm * 64 + mt * 16 + (lane >> 2);
            int c = n0 + wn * 64 + nt * 8 + 2 * (lane & 3);
            float* d = acc[mt * 8 + nt];
            #pragma unroll
            for (int half = 0; half < 2; half++) {
                int row = rl + half * 8;
                if (row >= valid) continue;
                size_t rp = (size_t)(off + r0 + row) * DM + c;
                g_y[rp]     = d[half * 2]     + bias[c];
                g_y[rp + 1] = d[half * 2 + 1] + bias[c + 1];
            }
        }
}

__global__ void scan_kernel() {
    if (threadIdx.x == 0 && blockIdx.x == 0) {
        int o = 0;
        float aux = 0.f;
        for (int e = 0; e < NE; e++) { g_off[e] = o; o += g_cnt[e]; }
        for (int e = 0; e < NE; e++)
            aux += ((float)g_cnt[e] / (float)(NTOK * 2)) * (g_probsum[e] / (float)NTOK);
        g_aux = (float)NE * aux;
    }
}

__global__ void place_kernel() {
    int s = blockIdx.x * 256 + threadIdx.x;
    if (s >= NSLOT) return;
    int tok = s >> 1;
    int e = g_top_i[s];
    float w = g_top_w[s];
    int pos = atomicAdd(&g_cur[e], 1);
    int slot = g_off[e] + pos;
    g_perm_tok[slot] = tok;
    g_slot_gate[slot] = w;
    g_slot_of[s] = slot;
}

// ---------------- final combine ----------------
__global__ void __launch_bounds__(256) combine_kernel(float* __restrict__ out, int out_size)
{
    int tok = blockIdx.x;
    int s0 = g_slot_of[tok * 2], s1 = g_slot_of[tok * 2 + 1];
    float w0 = g_slot_gate[s0], w1 = g_slot_gate[s1];
    const float* y0 = g_y + (size_t)s0 * DM;
    const float* y1 = g_y + (size_t)s1 * DM;
    const float* xr = g_x2 + (size_t)tok * DM;
    float* orow = out + (size_t)tok * DM;
    #pragma unroll
    for (int l = 0; l < 4; l++) {
        int i = threadIdx.x + l * 256;
        orow[i] = xr[i] + w0 * y0[i] + w1 * y1[i];
    }
    if (tok == 0 && threadIdx.x == 0 && out_size > NTOK * DM)
        out[NTOK * DM] = g_aux;
}

// ===================== launch =====================
extern "C" void kernel_launch(void* const* d_in, const int* in_sizes, int n_in,
                              void* d_out, int out_size)
{
    const float* x        = (const float*)d_in[0];
    const float* ln1_g    = (const float*)d_in[2];
    const float* ln1_b    = (const float*)d_in[3];
    const float* w_qkv    = (const float*)d_in[4];
    const float* w_proj   = (const float*)d_in[5];
    const float* b_proj   = (const float*)d_in[6];
    const float* ln2_g    = (const float*)d_in[7];
    const float* ln2_b    = (const float*)d_in[8];
    const float* w_router = (const float*)d_in[9];
    const float* w1       = (const float*)d_in[10];
    const float* b1       = (const float*)d_in[11];
    const float* w2       = (const float*)d_in[12];
    const float* b2       = (const float*)d_in[13];
    float* out = (float*)d_out;

    static cudaStream_t s_side = nullptr;
    static cudaEvent_t ev_fork = nullptr, ev_join = nullptr;
    static bool attr_done = false;
    if (!attr_done) {
        cudaFuncSetAttribute(qkv_gemm,  cudaFuncAttributeMaxDynamicSharedMemorySize, GEMM_SMEM);
        cudaFuncSetAttribute(proj_gemm, cudaFuncAttributeMaxDynamicSharedMemorySize, GEMM_SMEM);
        cudaFuncSetAttribute(ffn1_gemm, cudaFuncAttributeMaxDynamicSharedMemorySize, GEMM_SMEM);
        cudaFuncSetAttribute(ffn2_gemm, cudaFuncAttributeMaxDynamicSharedMemorySize, GEMM_SMEM);
        cudaFuncSetAttribute(attn_kernel, cudaFuncAttributeMaxDynamicSharedMemorySize, ATTN_SMEM);
        cudaStreamCreateWithFlags(&s_side, cudaStreamNonBlocking);
        cudaEventCreateWithFlags(&ev_fork, cudaEventDisableTiming);
        cudaEventCreateWithFlags(&ev_join, cudaEventDisableTiming);
        attr_done = true;
    }

    float *p_qkv, *p_x2;
    h16 *p_qh, *p_kh, *p_vh;
    h16 *p_xn1_h, *p_attn_h, *p_xn2_h;
    h16 *p_wqkvt_h, *p_wprojt_h, *p_w1t, *p_w2t;
    cudaGetSymbolAddress((void**)&p_qkv,  g_qkv);
    cudaGetSymbolAddress((void**)&p_qh,   g_qh);
    cudaGetSymbolAddress((void**)&p_kh,   g_kh);
    cudaGetSymbolAddress((void**)&p_vh,   g_vh);
    cudaGetSymbolAddress((void**)&p_x2,   g_x2);
    cudaGetSymbolAddress((void**)&p_xn1_h, g_xn1_h);
    cudaGetSymbolAddress((void**)&p_attn_h, g_attn_h);
    cudaGetSymbolAddress((void**)&p_xn2_h, g_xn2_h);
    cudaGetSymbolAddress((void**)&p_wqkvt_h, g_wqkvt_h);
    cudaGetSymbolAddress((void**)&p_wprojt_h, g_wprojt_h);
    cudaGetSymbolAddress((void**)&p_w1t, g_w1t);
    cudaGetSymbolAddress((void**)&p_w2t, g_w2t);

    zero_small_kernel<<<1, 32>>>();
    rope_tab_kernel<<<TT * 32 / 256, 256>>>();

    // fork: FFN weight conversion on side stream (overlaps attention chain)
    cudaEventRecord(ev_fork, 0);
    cudaStreamWaitEvent(s_side, ev_fork, 0);
    trans_conv<<<dim3(DFF / 32, DM / 32, NE), 256, 0, s_side>>>(w1, p_w1t, DM, DFF);
    trans_conv<<<dim3(DM / 32, DFF / 32, NE), 256, 0, s_side>>>(w2, p_w2t, DFF, DM);
    cudaEventRecord(ev_join, s_side);

    // main chain
    trans_conv<<<dim3(3 * DM / 32, DM / 32, 1), 256>>>(w_qkv, p_wqkvt_h, DM, 3 * DM);
    trans_conv<<<dim3(DM / 32, DM / 32, 1), 256>>>(w_proj, p_wprojt_h, DM, DM);
    ln_kernel<<<NTOK, 256>>>(x, ln1_g, ln1_b, p_xn1_h);
    qkv_gemm<<<dim3(3 * DM / 256, NTOK / 128), 256, GEMM_SMEM>>>();
    rope_kernel<<<NTOK, 256>>>(p_qkv, p_qh, p_kh, p_vh);
    attn_kernel<<<NBH * (TT / 128), 256, ATTN_SMEM>>>(p_qh, p_kh, p_vh, p_attn_h);
    proj_gemm<<<dim3(DM / 256, NTOK / 128), 256, GEMM_SMEM>>>(b_proj, x);
    ln2_router_kernel<<<NTOK, 256>>>(p_x2, ln2_g, ln2_b, p_xn2_h, w_router);
    scan_kernel<<<1, 1>>>();
    place_kernel<<<NSLOT / 256, 256>>>();

    // join before expert GEMMs
    cudaStreamWaitEvent(0, ev_join, 0);
    ffn1_gemm<<<dim3(DFF / 256, NSLOT / 128, NE), 256, GEMM_SMEM>>>(b1);
    ffn2_gemm<<<dim3(DM / 256, NSLOT / 128, NE), 256, GEMM_SMEM>>>(b2);
    combine_kernel<<<NTOK, 256>>>(out, out_size);
}

// round 11
// speedup vs baseline: 6.4589x; 1.0094x over previous
#include <cuda_runtime.h>
#include <cuda_fp16.h>
#include <math.h>
#include <stdint.h>

#define NTOK 4096      // B*T
#define DM   1024
#define NH   16
#define HD   64
#define NE   8
#define DFF  4096
#define NSLOT 8192     // NTOK * TOP_K
#define TT   1024
#define NBH  64        // B * NH

typedef __half h16;

// ===================== scratch (static device memory) ========================
__device__ h16    g_xn1_h [NTOK * DM];
__device__ h16    g_qh    [NTOK * DM];   // [B,H,T,HD] fp16, pre-scaled 0.125
__device__ h16    g_kh    [NTOK * DM];
__device__ h16    g_vh    [NTOK * DM];
__device__ h16    g_attn_h[NTOK * DM];
__device__ h16    g_xn2_h [NTOK * DM];
__device__ h16    g_hbuf  [(size_t)NSLOT * DFF];
__device__ float2 g_rope_tab[TT * 32];

// transposed weights ([N,K] K-major per expert)
__device__ h16 g_wqkvt_h[3 * DM * DM];
__device__ h16 g_wprojt_h[DM * DM];
__device__ h16 g_w1t[(size_t)NE * DFF * DM];
__device__ h16 g_w2t[(size_t)NE * DM * DFF];

__device__ int   g_cnt[NE];
__device__ int   g_off[NE];
__device__ int   g_cur[NE];
__device__ float g_probsum[NE];
__device__ int   g_top_i[NSLOT];
__device__ float g_top_w[NSLOT];
__device__ int   g_perm_tok[NSLOT];
__device__ float g_slot_gate[NSLOT];

__device__ __forceinline__ uint32_t smem_u32(const void* p) {
    uint32_t a;
    asm("{ .reg .u64 t; cvta.to.shared.u64 t, %1; cvt.u32.u64 %0, t; }"
        : "=r"(a) : "l"(p));
    return a;
}
__device__ __forceinline__ void ldsm4(uint32_t* r, uint32_t addr) {
    asm volatile("ldmatrix.sync.aligned.m8n8.x4.shared.b16 {%0,%1,%2,%3}, [%4];"
                 : "=r"(r[0]), "=r"(r[1]), "=r"(r[2]), "=r"(r[3]) : "r"(addr));
}
__device__ __forceinline__ void ldsm4t(uint32_t* r, uint32_t addr) {
    asm volatile("ldmatrix.sync.aligned.m8n8.x4.trans.shared.b16 {%0,%1,%2,%3}, [%4];"
                 : "=r"(r[0]), "=r"(r[1]), "=r"(r[2]), "=r"(r[3]) : "r"(addr));
}
__device__ __forceinline__ void mma_f16(float* d, const uint32_t* a, const uint32_t* b) {
    asm volatile(
        "mma.sync.aligned.m16n8k16.row.col.f32.f16.f16.f32 "
        "{%0,%1,%2,%3}, {%4,%5,%6,%7}, {%8,%9}, {%0,%1,%2,%3};"
        : "+f"(d[0]), "+f"(d[1]), "+f"(d[2]), "+f"(d[3])
        : "r"(a[0]), "r"(a[1]), "r"(a[2]), "r"(a[3]), "r"(b[0]), "r"(b[1]));
}
__device__ __forceinline__ void cp_async16(uint32_t saddr, const void* g, uint32_t sz) {
    asm volatile("cp.async.cg.shared.global [%0], [%1], 16, %2;"
                 :: "r"(saddr), "l"(g), "r"(sz));
}
__device__ __forceinline__ void cp_commit() {
    asm volatile("cp.async.commit_group;");
}
template<int N> __device__ __forceinline__ void cp_wait() {
    asm volatile("cp.async.wait_group %0;" :: "n"(N));
}
__device__ __forceinline__ uint32_t sw128(uint32_t o) {
    return o ^ ((o >> 3) & 0x70u);
}
__device__ __forceinline__ uint32_t h2pack(float a, float b) {
    half2 h = __floats2half2_rn(a, b);
    return *(uint32_t*)&h;
}

// ===================== small helpers ====================
__global__ void zero_small_kernel() {
    int i = threadIdx.x;
    if (i < NE) { g_cnt[i] = 0; g_cur[i] = 0; g_probsum[i] = 0.f; }
}

// rope sincos table: tab[t*32+f] = (cos, sin)(t * 10000^(-f/32))
__global__ void __launch_bounds__(256) rope_tab_kernel() {
    int idx = blockIdx.x * 256 + threadIdx.x;
    int t = idx >> 5, f = idx & 31;
    float freq = exp2f(-(float)f * 0.41524101186092029f);
    float sv, cv;
    __sincosf((float)t * freq, &sv, &cv);
    g_rope_tab[idx] = make_float2(cv, sv);
}

// ---------------- transpose + convert: w[K,N] -> t[N,K] ----------------------
__global__ void __launch_bounds__(256) trans_conv(
    const float* __restrict__ w, h16* __restrict__ th, int K, int N)
{
    const size_t eoff = (size_t)blockIdx.z * K * N;
    const float* wp = w + eoff;
    h16* thp = th + eoff;
    __shared__ float t[32][33];
    int tx = threadIdx.x & 31, ty = threadIdx.x >> 5;
    int n0 = blockIdx.x * 32, k0 = blockIdx.y * 32;
    #pragma unroll
    for (int i = 0; i < 4; i++)
        t[ty + i * 8][tx] = wp[(size_t)(k0 + ty + i * 8) * N + n0 + tx];
    __syncthreads();
    #pragma unroll
    for (int i = 0; i < 4; i++) {
        float v = t[tx][ty + i * 8];
        int n = n0 + ty + i * 8, k = k0 + tx;
        thp[(size_t)n * K + k] = __float2half_rn(v);
    }
}

// ---------------- layernorm (256 thr/row) ----------------
__global__ void __launch_bounds__(256) ln_kernel(
    const float* __restrict__ x, const float* __restrict__ g,
    const float* __restrict__ b, h16* __restrict__ oh)
{
    int row = blockIdx.x;
    const float* xr = x + (size_t)row * DM;
    float v[4]; float s = 0.f, ss = 0.f;
    #pragma unroll
    for (int i = 0; i < 4; i++) {
        float u = xr[threadIdx.x + i * 256];
        v[i] = u; s += u; ss += u * u;
    }
    #pragma unroll
    for (int ofs = 16; ofs > 0; ofs >>= 1) {
        s  += __shfl_xor_sync(0xffffffffu, s,  ofs);
        ss += __shfl_xor_sync(0xffffffffu, ss, ofs);
    }
    __shared__ float sh[2][8];
    int warp = threadIdx.x >> 5, lane = threadIdx.x & 31;
    if (lane == 0) { sh[0][warp] = s; sh[1][warp] = ss; }
    __syncthreads();
    float S = 0.f, SS = 0.f;
    #pragma unroll
    for (int w = 0; w < 8; w++) { S += sh[0][w]; SS += sh[1][w]; }
    float mu  = S * (1.0f / DM);
    float var = SS * (1.0f / DM) - mu * mu;
    float inv = rsqrtf(var + 1e-5f);
    #pragma unroll
    for (int i = 0; i < 4; i++) {
        int idx = threadIdx.x + i * 256;
        float o = (v[i] - mu) * inv * g[idx] + b[idx];
        oh[(size_t)row * DM + idx] = __float2half_rn(o);
    }
}

// ---------------- fused ln2 + router (reads x2 from out) ---------------------
__global__ void __launch_bounds__(256) ln2_router_kernel(
    const float* __restrict__ x, const float* __restrict__ g,
    const float* __restrict__ b, h16* __restrict__ oh,
    const float* __restrict__ wr)
{
    int row = blockIdx.x, tid = threadIdx.x;
    const float* xr = x + (size_t)row * DM;
    float v[4]; float s = 0.f, ss = 0.f;
    #pragma unroll
    for (int i = 0; i < 4; i++) {
        float u = xr[tid + i * 256];
        v[i] = u; s += u; ss += u * u;
    }
    #pragma unroll
    for (int ofs = 16; ofs > 0; ofs >>= 1) {
        s  += __shfl_xor_sync(0xffffffffu, s,  ofs);
        ss += __shfl_xor_sync(0xffffffffu, ss, ofs);
    }
    __shared__ float sh[2][8];
    int warp = tid >> 5, lane = tid & 31;
    if (lane == 0) { sh[0][warp] = s; sh[1][warp] = ss; }
    __syncthreads();
    float S = 0.f, SS = 0.f;
    #pragma unroll
    for (int w = 0; w < 8; w++) { S += sh[0][w]; SS += sh[1][w]; }
    float mu  = S * (1.0f / DM);
    float var = SS * (1.0f / DM) - mu * mu;
    float inv = rsqrtf(var + 1e-5f);
    float pe[NE];
    #pragma unroll
    for (int e = 0; e < NE; e++) pe[e] = 0.f;
    #pragma unroll
    for (int i = 0; i < 4; i++) {
        int idx = tid + i * 256;
        float o = (v[i] - mu) * inv * g[idx] + b[idx];
        oh[(size_t)row * DM + idx] = __float2half_rn(o);
        const float* w = wr + idx * NE;
        #pragma unroll
        for (int e = 0; e < NE; e++) pe[e] += o * w[e];
    }
    __shared__ float red[NE][256];
    #pragma unroll
    for (int e = 0; e < NE; e++) red[e][tid] = pe[e];
    __syncthreads();
    for (int st = 128; st > 0; st >>= 1) {
        if (tid < st) {
            #pragma unroll
            for (int e = 0; e < NE; e++) red[e][tid] += red[e][tid + st];
        }
        __syncthreads();
    }
    if (tid == 0) {
        float lg[NE], mx = -1e30f;
        #pragma unroll
        for (int e = 0; e < NE; e++) { lg[e] = red[e][0]; mx = fmaxf(mx, lg[e]); }
        float se = 0.f, pr[NE];
        #pragma unroll
        for (int e = 0; e < NE; e++) { pr[e] = __expf(lg[e] - mx); se += pr[e]; }
        float invs = 1.0f / se;
        #pragma unroll
        for (int e = 0; e < NE; e++) {
            pr[e] *= invs;
            atomicAdd(&g_probsum[e], pr[e]);
        }
        int i0 = 0;
        #pragma unroll
        for (int e = 1; e < NE; e++) if (pr[e] > pr[i0]) i0 = e;
        int i1 = (i0 == 0) ? 1 : 0;
        #pragma unroll
        for (int e = 0; e < NE; e++) if (e != i0 && pr[e] > pr[i1]) i1 = e;
        float w0 = pr[i0], w1 = pr[i1], sw = 1.0f / (w0 + w1);
        g_top_i[row * 2] = i0; g_top_i[row * 2 + 1] = i1;
        g_top_w[row * 2] = w0 * sw; g_top_w[row * 2 + 1] = w1 * sw;
        atomicAdd(&g_cnt[i0], 1);
        atomicAdd(&g_cnt[i1], 1);
    }
}

// ---------------- tensor-core flash attention --------------------------------
#define ATTN_SMEM 49152
__global__ void __launch_bounds__(256, 2) attn_kernel(
    const h16* __restrict__ q, const h16* __restrict__ k,
    const h16* __restrict__ v, h16* __restrict__ oh)
{
    extern __shared__ char smem[];
    uint32_t sb = smem_u32(smem);
    const uint32_t SQ = 0, SKV = 16384, STG = 16384;

    int bh = blockIdx.x & (NBH - 1);
    int chunk = (TT / 128 - 1) - (blockIdx.x >> 6);
    int qb0 = chunk * 128;
    int tid = threadIdx.x, lane = tid & 31, w = tid >> 5;
    const h16* qb = q + (size_t)bh * TT * HD;
    const h16* kb = k + (size_t)bh * TT * HD;
    const h16* vb = v + (size_t)bh * TT * HD;

    for (int i = tid; i < 128 * 8; i += 256) {
        int r = i >> 3, ch = i & 7;
        uint32_t so = sw128((uint32_t)(r * 128 + ch * 16));
        *(uint4*)(smem + SQ + so) = *(const uint4*)(qb + (size_t)(qb0 + r) * HD + ch * 8);
    }

    auto load_kv = [&](int j0, int st) {
        uint32_t s0 = sb + SKV + (uint32_t)st * STG;
        #pragma unroll
        for (int i = 0; i < 2; i++) {
            int idx = tid + i * 256;
            int r = idx >> 3, ch = idx & 7;
            uint32_t so = sw128((uint32_t)(r * 128 + ch * 16));
            cp_async16(s0 + so, kb + (size_t)(j0 + r) * HD + ch * 8, 16);
            cp_async16(s0 + 8192 + so, vb + (size_t)(j0 + r) * HD + ch * 8, 16);
        }
        cp_commit();
    };
    load_kv(0, 0);
    __syncthreads();

    uint32_t qf[4][4];
    #pragma unroll
    for (int ks = 0; ks < 4; ks++) {
        int row = w * 16 + (lane & 15);
        uint32_t so = sw128((uint32_t)(row * 128 + ks * 32 + (lane >> 4) * 16));
        ldsm4(qf[ks], sb + SQ + so);
    }

    float oacc[8][4];
    #pragma unroll
    for (int i = 0; i < 8; i++)
        #pragma unroll
        for (int j = 0; j < 4; j++) oacc[i][j] = 0.f;
    float mrun[2] = {-1e30f, -1e30f}, lsum[2] = {0.f, 0.f};

    const int wrow = qb0 + w * 16 + (lane >> 2);
    const int wt_last = qb0 + w * 16 + 15;
    const int wt_first = qb0 + w * 16;
    const int ntiles = (qb0 + 128) / 64;

    for (int ti = 0; ti < ntiles; ti++) {
        int j0 = ti * 64;
        if (ti + 1 < ntiles) { load_kv(j0 + 64, (ti + 1) & 1); cp_wait<1>(); }
        else cp_wait<0>();
        __syncthreads();
        if (j0 <= wt_last) {
            uint32_t s0 = sb + SKV + (uint32_t)(ti & 1) * STG;
            float sacc[8][4];
            #pragma unroll
            for (int i = 0; i < 8; i++)
                #pragma unroll
                for (int j = 0; j < 4; j++) sacc[i][j] = 0.f;
            #pragma unroll
            for (int ks = 0; ks < 4; ks++) {
                #pragma unroll
                for (int n2 = 0; n2 < 4; n2++) {
                    int row = n2 * 16 + (lane & 15);
                    uint32_t so = sw128((uint32_t)(row * 128 + ks * 32 + (lane >> 4) * 16));
                    uint32_t t4[4]; ldsm4(t4, s0 + so);
                    uint32_t b0[2] = {t4[0], t4[2]}, b1[2] = {t4[1], t4[3]};
                    mma_f16(sacc[2 * n2], qf[ks], b0);
                    mma_f16(sacc[2 * n2 + 1], qf[ks], b1);
                }
            }
            if (j0 + 63 > wt_first) {
                #pragma unroll
                for (int nt = 0; nt < 8; nt++)
                    #pragma unroll
                    for (int r = 0; r < 4; r++) {
                        int col = j0 + 8 * nt + 2 * (lane & 3) + (r & 1);
                        int rowt = wrow + 8 * (r >> 1);
                        if (col > rowt) sacc[nt][r] = -1e30f;
                    }
            }
            float psc[2];
            #pragma unroll
            for (int hh = 0; hh < 2; hh++) {
                float mx = -1e30f;
                #pragma unroll
                for (int nt = 0; nt < 8; nt++) {
                    mx = fmaxf(mx, sacc[nt][2 * hh]);
                    mx = fmaxf(mx, sacc[nt][2 * hh + 1]);
                }
                mx = fmaxf(mx, __shfl_xor_sync(0xffffffffu, mx, 1));
                mx = fmaxf(mx, __shfl_xor_sync(0xffffffffu, mx, 2));
                float nm = fmaxf(mrun[hh], mx);
                float sc = __expf(mrun[hh] - nm);
                mrun[hh] = nm;
                float sum = 0.f;
                #pragma unroll
                for (int nt = 0; nt < 8; nt++) {
                    float p0 = __expf(sacc[nt][2 * hh] - nm);
                    float p1 = __expf(sacc[nt][2 * hh + 1] - nm);
                    sacc[nt][2 * hh] = p0; sacc[nt][2 * hh + 1] = p1;
                    sum += p0 + p1;
                }
                sum += __shfl_xor_sync(0xffffffffu, sum, 1);
                sum += __shfl_xor_sync(0xffffffffu, sum, 2);
                lsum[hh] = lsum[hh] * sc + sum;
                psc[hh] = sc;
            }
            #pragma unroll
            for (int nt = 0; nt < 8; nt++)
                #pragma unroll
                for (int r = 0; r < 4; r++)
                    oacc[nt][r] *= psc[r >> 1];
            uint32_t pf[4][4];
            #pragma unroll
            for (int kt = 0; kt < 4; kt++) {
                pf[kt][0] = h2pack(sacc[2 * kt][0], sacc[2 * kt][1]);
                pf[kt][1] = h2pack(sacc[2 * kt][2], sacc[2 * kt][3]);
                pf[kt][2] = h2pack(sacc[2 * kt + 1][0], sacc[2 * kt + 1][1]);
                pf[kt][3] = h2pack(sacc[2 * kt + 1][2], sacc[2 * kt + 1][3]);
            }
            uint32_t sv = s0 + 8192;
            int g = lane >> 3, rr = lane & 7;
            #pragma unroll
            for (int dp = 0; dp < 4; dp++) {
                #pragma unroll
                for (int kt = 0; kt < 4; kt++) {
                    int kvr = 16 * kt + 8 * (g & 1) + rr;
                    int dc = dp * 16 + 8 * (g >> 1);
                    uint32_t so = sw128((uint32_t)(kvr * 128 + dc * 2));
                    uint32_t t4[4]; ldsm4t(t4, sv + so);
                    uint32_t b0[2] = {t4[0], t4[1]}, b1[2] = {t4[2], t4[3]};
                    mma_f16(oacc[2 * dp], pf[kt], b0);
                    mma_f16(oacc[2 * dp + 1], pf[kt], b1);
                }
            }
        }
        __syncthreads();
    }
    int b = bh >> 4, hH = bh & 15;
    #pragma unroll
    for (int hh = 0; hh < 2; hh++) {
        float inv = 1.0f / lsum[hh];
        int t = wrow + 8 * hh;
        size_t op = ((size_t)(b * TT + t)) * DM + hH * HD;
        #pragma unroll
        for (int nt = 0; nt < 8; nt++) {
            int d = 8 * nt + 2 * (lane & 3);
            half2 hv = __floats2half2_rn(oacc[nt][2 * hh] * inv, oacc[nt][2 * hh + 1] * inv);
            *(half2*)(oh + op + d) = hv;
        }
    }
}

// ===================== 128x256 HMMA GEMM core (4-stage) ======================
#define NSTG 4
__device__ __forceinline__ void gemm256(
    uint32_t sb, float (*acc)[4],
    const h16* __restrict__ A, const h16* __restrict__ B,
    int K, const int* __restrict__ perm, int row_base, int valid, int n0)
{
    constexpr uint32_t T_B = 16384;
    constexpr uint32_t STAGE = 49152;
    const int tid = threadIdx.x, lane = tid & 31, wid = tid >> 5;
    const int wm = wid >> 2, wn = wid & 3;
    const int nkb = K >> 6;

    const int arow = tid >> 3, ach = tid & 7;
    uint32_t asz[4];
    size_t aoff[4];
    #pragma unroll
    for (int it = 0; it < 4; it++) {
        int row = arow + it * 32;
        asz[it] = (row < valid) ? 16u : 0u;
        int gra = (row < valid) ? (perm ? perm[row_base + row] : (row_base + row)) : 0;
        aoff[it] = (size_t)gra * K;
    }

    auto load_stage = [&](int kb) {
        uint32_t s0 = sb + (uint32_t)(kb & (NSTG - 1)) * STAGE;
        int koff = kb * 64 + ach * 8;
        #pragma unroll
        for (int it = 0; it < 4; it++) {
            int row = arow + it * 32;
            uint32_t so = sw128((uint32_t)(row * 128 + ach * 16));
            cp_async16(s0 + so, A + aoff[it] + koff, asz[it]);
        }
        #pragma unroll
        for (int it = 0; it < 8; it++) {
            int row = arow + it * 32;
            uint32_t so = sw128((uint32_t)(row * 128 + ach * 16));
            cp_async16(s0 + T_B + so, B + (size_t)(n0 + row) * K + koff, 16u);
        }
        cp_commit();
    };

    #pragma unroll
    for (int s = 0; s < NSTG - 1; s++)
        if (s < nkb) load_stage(s);

    for (int kb = 0; kb < nkb; kb++) {
        if (kb + NSTG - 1 < nkb) { load_stage(kb + NSTG - 1); cp_wait<NSTG - 1>(); }
        else {
            int rem = nkb - 1 - kb;
            if (rem >= 2) cp_wait<2>();
            else if (rem == 1) cp_wait<1>();
            else cp_wait<0>();
        }
        __syncthreads();
        uint32_t s0 = sb + (uint32_t)(kb & (NSTG - 1)) * STAGE;
        #pragma unroll
        for (int ks = 0; ks < 4; ks++) {
            uint32_t af[4][4];
            #pragma unroll
            for (int mt = 0; mt < 4; mt++) {
                int row = wm * 64 + mt * 16 + (lane & 15);
                uint32_t so = sw128((uint32_t)(row * 128 + ks * 32 + (lane >> 4) * 16));
                ldsm4(af[mt], s0 + so);
            }
            uint32_t bf[8][2];
            #pragma unroll
            for (int n2 = 0; n2 < 4; n2++) {
                int row = wn * 64 + n2 * 16 + (lane & 15);
                uint32_t so = sw128((uint32_t)(row * 128 + ks * 32 + (lane >> 4) * 16));
                uint32_t t4[4];
                ldsm4(t4, s0 + T_B + so);
                bf[n2 * 2][0] = t4[0]; bf[n2 * 2][1] = t4[2];
                bf[n2 * 2 + 1][0] = t4[1]; bf[n2 * 2 + 1][1] = t4[3];
            }
            #pragma unroll
            for (int mt = 0; mt < 4; mt++)
                #pragma unroll
                for (int nt = 0; nt < 8; nt++)
                    mma_f16(acc[mt * 8 + nt], af[mt], bf[nt]);
        }
        __syncthreads();
    }
}
// acc[mt*8+nt][r]: row = wm*64 + mt*16 + lane/4 + 8*(r>>1)
//                  col = wn*64 + nt*8  + 2*(lane&3) + (r&1)

#define GEMM_SMEM 196608
#define ACC_INIT float acc[32][4]; \
    _Pragma("unroll") for (int i = 0; i < 32; i++) \
    _Pragma("unroll") for (int j = 0; j < 4; j++) acc[i][j] = 0.f;

// ---------------- qkv gemm + fused rope -> fp16 q/k/v ------------------------
__global__ void __launch_bounds__(256, 1) qkv_gemm() {
    extern __shared__ char smem[];
    uint32_t sb = smem_u32(smem);
    ACC_INIT
    int m0 = blockIdx.y * 128, n0 = blockIdx.x * 256;
    gemm256(sb, acc, g_xn1_h, g_wqkvt_h, DM, nullptr, m0, 128, n0);
    int lane = threadIdx.x & 31, wid = threadIdx.x >> 5;
    int wm = wid >> 2, wn = wid & 3;
    int c_base = n0 + wn * 64;
    int sec = c_base >> 10;             // 0=q, 1=k, 2=v
    int h = (c_base & 1023) >> 6;       // head index
    h16* dstq = (sec == 0) ? g_qh : g_kh;
    #pragma unroll
    for (int mt = 0; mt < 4; mt++) {
        #pragma unroll
        for (int half = 0; half < 2; half++) {
            int rg = m0 + wm * 64 + mt * 16 + (lane >> 2) + half * 8;
            int t = rg & (TT - 1), bb = rg >> 10;
            size_t dbase = ((size_t)((bb * NH + h) * TT) + t) * HD;
            #pragma unroll
            for (int nt = 0; nt < 4; nt++) {
                int d = nt * 8 + 2 * (lane & 3);
                float a0 = acc[mt * 8 + nt][half * 2];
                float a1 = acc[mt * 8 + nt][half * 2 + 1];
                float b0 = acc[mt * 8 + nt + 4][half * 2];
                float b1 = acc[mt * 8 + nt + 4][half * 2 + 1];
                if (sec == 2) {
                    *(half2*)(g_vh + dbase + d)      = __floats2half2_rn(a0, a1);
                    *(half2*)(g_vh + dbase + d + 32) = __floats2half2_rn(b0, b1);
                } else {
                    float2 cs0 = g_rope_tab[t * 32 + d];
                    float2 cs1 = g_rope_tab[t * 32 + d + 1];
                    float lo0 = a0 * cs0.x - b0 * cs0.y;
                    float lo1 = a1 * cs1.x - b1 * cs1.y;
                    float hi0 = b0 * cs0.x + a0 * cs0.y;
                    float hi1 = b1 * cs1.x + a1 * cs1.y;
                    if (sec == 0) { lo0 *= 0.125f; lo1 *= 0.125f; hi0 *= 0.125f; hi1 *= 0.125f; }
                    *(half2*)(dstq + dbase + d)      = __floats2half2_rn(lo0, lo1);
                    *(half2*)(dstq + dbase + d + 32) = __floats2half2_rn(hi0, hi1);
                }
            }
        }
    }
}

// ---------------- x2 = attn @ w_proj + b_proj + x -> out ---------------------
__global__ void __launch_bounds__(256, 1) proj_gemm(
    const float* __restrict__ bias, const float* __restrict__ resid,
    float* __restrict__ out)
{
    extern __shared__ char smem[];
    uint32_t sb = smem_u32(smem);
    ACC_INIT
    int m0 = blockIdx.y * 128, n0 = blockIdx.x * 256;
    gemm256(sb, acc, g_attn_h, g_wprojt_h, DM, nullptr, m0, 128, n0);
    int lane = threadIdx.x & 31, wid = threadIdx.x >> 5;
    int wm = wid >> 2, wn = wid & 3;
    #pragma unroll
    for (int mt = 0; mt < 4; mt++)
        #pragma unroll
        for (int nt = 0; nt < 8; nt++) {
            int r = m0 + wm * 64 + mt * 16 + (lane >> 2);
            int c = n0 + wn * 64 + nt * 8 + 2 * (lane & 3);
            float* d = acc[mt * 8 + nt];
            size_t p0 = (size_t)r * DM + c;
            size_t p1 = (size_t)(r + 8) * DM + c;
            out[p0]     = d[0] + bias[c]     + resid[p0];
            out[p0 + 1] = d[1] + bias[c + 1] + resid[p0 + 1];
            out[p1]     = d[2] + bias[c]     + resid[p1];
            out[p1 + 1] = d[3] + bias[c + 1] + resid[p1 + 1];
        }
}

// ---------------- h = gelu(gather(xn2) @ w1[e] + b1[e]) ----------------------
__global__ void __launch_bounds__(256, 1) ffn1_gemm(const float* __restrict__ B1) {
    int e = blockIdx.z;
    int cnt = g_cnt[e];
    int r0 = blockIdx.y * 128;
    if (r0 >= cnt) return;
    extern __shared__ char smem[];
    uint32_t sb = smem_u32(smem);
    ACC_INIT
    int off = g_off[e];
    int n0 = blockIdx.x * 256;
    int valid = cnt - r0; if (valid > 128) valid = 128;
    gemm256(sb, acc, g_xn2_h, g_w1t + (size_t)e * DFF * DM,
            DM, g_perm_tok, off + r0, valid, n0);
    int lane = threadIdx.x & 31, wid = threadIdx.x >> 5;
    int wm = wid >> 2, wn = wid & 3;
    const float* bias = B1 + e * DFF;
    #pragma unroll
    for (int mt = 0; mt < 4; mt++)
        #pragma unroll
        for (int nt = 0; nt < 8; nt++) {
            int rl = wm * 64 + mt * 16 + (lane >> 2);
            int c = n0 + wn * 64 + nt * 8 + 2 * (lane & 3);
            float* d = acc[mt * 8 + nt];
            #pragma unroll
            for (int half = 0; half < 2; half++) {
                int row = rl + half * 8;
                if (row >= valid) continue;
                size_t rp = (size_t)(off + r0 + row) * DFF + c;
                #pragma unroll
                for (int u = 0; u < 2; u++) {
                    float v = d[half * 2 + u] + bias[c + u];
                    v = 0.5f * v * (1.0f + erff(v * 0.70710678118654752f));
                    g_hbuf[rp + u] = __float2half_rn(v);
                }
            }
        }
}

// ---------------- out += gate * (h @ w2[e] + b2[e]) (fused combine) ----------
__global__ void __launch_bounds__(256, 1) ffn2_gemm(
    const float* __restrict__ B2, float* __restrict__ out)
{
    int e = blockIdx.z;
    int cnt = g_cnt[e];
    int r0 = blockIdx.y * 128;
    if (r0 >= cnt) return;
    extern __shared__ char smem[];
    uint32_t sb = smem_u32(smem);
    ACC_INIT
    int off = g_off[e];
    int n0 = blockIdx.x * 256;
    int valid = cnt - r0; if (valid > 128) valid = 128;
    gemm256(sb, acc, g_hbuf, g_w2t + (size_t)e * DM * DFF,
            DFF, nullptr, off + r0, valid, n0);
    int lane = threadIdx.x & 31, wid = threadIdx.x >> 5;
    int wm = wid >> 2, wn = wid & 3;
    const float* bias = B2 + e * DM;
    #pragma unroll
    for (int mt = 0; mt < 4; mt++) {
        #pragma unroll
        for (int half = 0; half < 2; half++) {
            int row = wm * 64 + mt * 16 + (lane >> 2) + half * 8;
            if (row >= valid) continue;
            int slot = off + r0 + row;
            int tok = g_perm_tok[slot];
            float gate = g_slot_gate[slot];
            float* orow = out + (size_t)tok * DM;
            #pragma unroll
            for (int nt = 0; nt < 8; nt++) {
                int c = n0 + wn * 64 + nt * 8 + 2 * (lane & 3);
                float* d = acc[mt * 8 + nt];
                atomicAdd(orow + c,     gate * (d[half * 2]     + bias[c]));
                atomicAdd(orow + c + 1, gate * (d[half * 2 + 1] + bias[c + 1]));
            }
        }
    }
}

__global__ void scan_kernel(float* __restrict__ out, int out_size) {
    if (threadIdx.x == 0 && blockIdx.x == 0) {
        int o = 0;
        float aux = 0.f;
        for (int e = 0; e < NE; e++) { g_off[e] = o; o += g_cnt[e]; }
        for (int e = 0; e < NE; e++)
            aux += ((float)g_cnt[e] / (float)(NTOK * 2)) * (g_probsum[e] / (float)NTOK);
        if (out_size > NTOK * DM) out[NTOK * DM] = (float)NE * aux;
    }
}

__global__ void place_kernel() {
    int s = blockIdx.x * 256 + threadIdx.x;
    if (s >= NSLOT) return;
    int tok = s >> 1;
    int e = g_top_i[s];
    float w = g_top_w[s];
    int pos = atomicAdd(&g_cur[e], 1);
    int slot = g_off[e] + pos;
    g_perm_tok[slot] = tok;
    g_slot_gate[slot] = w;
}

// ===================== launch =====================
extern "C" void kernel_launch(void* const* d_in, const int* in_sizes, int n_in,
                              void* d_out, int out_size)
{
    const float* x        = (const float*)d_in[0];
    const float* ln1_g    = (const float*)d_in[2];
    const float* ln1_b    = (const float*)d_in[3];
    const float* w_qkv    = (const float*)d_in[4];
    const float* w_proj   = (const float*)d_in[5];
    const float* b_proj   = (const float*)d_in[6];
    const float* ln2_g    = (const float*)d_in[7];
    const float* ln2_b    = (const float*)d_in[8];
    const float* w_router = (const float*)d_in[9];
    const float* w1       = (const float*)d_in[10];
    const float* b1       = (const float*)d_in[11];
    const float* w2       = (const float*)d_in[12];
    const float* b2       = (const float*)d_in[13];
    float* out = (float*)d_out;

    static cudaStream_t s_side = nullptr;
    static cudaEvent_t ev_fork = nullptr, ev_join = nullptr;
    static bool attr_done = false;
    if (!attr_done) {
        cudaFuncSetAttribute(qkv_gemm,  cudaFuncAttributeMaxDynamicSharedMemorySize, GEMM_SMEM);
        cudaFuncSetAttribute(proj_gemm, cudaFuncAttributeMaxDynamicSharedMemorySize, GEMM_SMEM);
        cudaFuncSetAttribute(ffn1_gemm, cudaFuncAttributeMaxDynamicSharedMemorySize, GEMM_SMEM);
        cudaFuncSetAttribute(ffn2_gemm, cudaFuncAttributeMaxDynamicSharedMemorySize, GEMM_SMEM);
        cudaFuncSetAttribute(attn_kernel, cudaFuncAttributeMaxDynamicSharedMemorySize, ATTN_SMEM);
        cudaStreamCreateWithFlags(&s_side, cudaStreamNonBlocking);
        cudaEventCreateWithFlags(&ev_fork, cudaEventDisableTiming);
        cudaEventCreateWithFlags(&ev_join, cudaEventDisableTiming);
        attr_done = true;
    }

    h16 *p_qh, *p_kh, *p_vh;
    h16 *p_xn1_h, *p_attn_h, *p_xn2_h;
    h16 *p_wqkvt_h, *p_wprojt_h, *p_w1t, *p_w2t;
    cudaGetSymbolAddress((void**)&p_qh,   g_qh);
    cudaGetSymbolAddress((void**)&p_kh,   g_kh);
    cudaGetSymbolAddress((void**)&p_vh,   g_vh);
    cudaGetSymbolAddress((void**)&p_xn1_h, g_xn1_h);
    cudaGetSymbolAddress((void**)&p_attn_h, g_attn_h);
    cudaGetSymbolAddress((void**)&p_xn2_h, g_xn2_h);
    cudaGetSymbolAddress((void**)&p_wqkvt_h, g_wqkvt_h);
    cudaGetSymbolAddress((void**)&p_wprojt_h, g_wprojt_h);
    cudaGetSymbolAddress((void**)&p_w1t, g_w1t);
    cudaGetSymbolAddress((void**)&p_w2t, g_w2t);

    zero_small_kernel<<<1, 32>>>();
    rope_tab_kernel<<<TT * 32 / 256, 256>>>();

    // fork: FFN weight conversion on side stream (overlaps attention chain)
    cudaEventRecord(ev_fork, 0);
    cudaStreamWaitEvent(s_side, ev_fork, 0);
    trans_conv<<<dim3(DFF / 32, DM / 32, NE), 256, 0, s_side>>>(w1, p_w1t, DM, DFF);
    trans_conv<<<dim3(DM / 32, DFF / 32, NE), 256, 0, s_side>>>(w2, p_w2t, DFF, DM);
    cudaEventRecord(ev_join, s_side);

    // main chain
    trans_conv<<<dim3(3 * DM / 32, DM / 32, 1), 256>>>(w_qkv, p_wqkvt_h, DM, 3 * DM);
    trans_conv<<<dim3(DM / 32, DM / 32, 1), 256>>>(w_proj, p_wprojt_h, DM, DM);
    ln_kernel<<<NTOK, 256>>>(x, ln1_g, ln1_b, p_xn1_h);
    qkv_gemm<<<dim3(3 * DM / 256, NTOK / 128), 256, GEMM_SMEM>>>();   // + fused rope
    attn_kernel<<<NBH * (TT / 128), 256, ATTN_SMEM>>>(p_qh, p_kh, p_vh, p_attn_h);
    proj_gemm<<<dim3(DM / 256, NTOK / 128), 256, GEMM_SMEM>>>(b_proj, x, out);
    ln2_router_kernel<<<NTOK, 256>>>(out, ln2_g, ln2_b, p_xn2_h, w_router);
    scan_kernel<<<1, 1>>>(out, out_size);
    place_kernel<<<NSLOT / 256, 256>>>();

    // join before expert GEMMs
    cudaStreamWaitEvent(0, ev_join, 0);
    ffn1_gemm<<<dim3(DFF / 256, NSLOT / 128, NE), 256, GEMM_SMEM>>>(b1);
    ffn2_gemm<<<dim3(DM / 256, NSLOT / 128, NE), 256, GEMM_SMEM>>>(b2, out);
}